// round 7
// baseline (speedup 1.0000x reference)
#include <cuda_runtime.h>
#include <math.h>

#define NTH 256
#define TB  64
#define SWS 132   // weight smem stride (floats)
#define HS  132   // activation smem stride (floats)

// ---- smem layout (float offsets) ----
#define OFF_W    0
#define OFF_H1   (OFF_W   + 128*SWS)
#define OFF_H2   (OFF_H1  + TB*HS)
#define OFF_U    (OFF_H2  + TB*HS)
#define OFF_W1L  (OFF_U   + TB*HS)
#define OFF_W1V  (OFF_W1L + 12*SWS)
#define OFF_W3L  (OFF_W1V + 12*SWS)
#define OFF_W3V  (OFF_W3L + 128*21)
#define OFF_B1L  (OFF_W3V + 128)
#define OFF_B2L  (OFF_B1L + 128)
#define OFF_B3L  (OFF_B2L + 128)
#define OFF_B1V  (OFF_B3L + 24)
#define OFF_B2V  (OFF_B1V + 128)
#define OFF_X    (OFF_B2V + 128)
#define OFF_Q    (OFF_X   + TB*12)
#define OFF_QD   (OFF_Q   + TB*6)
#define OFF_A    (OFF_QD  + TB*6)
#define OFF_K1   (OFF_A   + TB*6)
#define OFF_M    (OFF_K1  + TB*6)
#define OFF_L    (OFF_M   + TB*36)
#define OFF_DY   (OFF_L   + TB*21)
#define OFF_QDD  (OFF_DY  + TB*21)
#define SMEM_FLOATS (OFF_QDD + TB*6)

static __device__ __forceinline__ float softplusf(float z) {
    return fmaxf(z, 0.0f) + __logf(1.0f + __expf(-fabsf(z)));
}
// sigmoid(z) given h = softplus(z):  sigma = 1 - exp(-h)   (h >= 0)
static __device__ __forceinline__ float sig_from_h(float h) {
    return 1.0f - __expf(-h);
}
static __device__ __forceinline__ float f4c(const float4& v, int k) {
    return k == 0 ? v.x : k == 1 ? v.y : k == 2 ? v.z : v.w;
}

extern "C" __global__ void __launch_bounds__(NTH, 1)
lnn6dof_kernel(const float* __restrict__ o,    const float* __restrict__ ain,
               const float* __restrict__ gW1L, const float* __restrict__ gb1L,
               const float* __restrict__ gW2L, const float* __restrict__ gb2L,
               const float* __restrict__ gW3L, const float* __restrict__ gb3L,
               const float* __restrict__ gW1V, const float* __restrict__ gb1V,
               const float* __restrict__ gW2V, const float* __restrict__ gb2V,
               const float* __restrict__ gW3V,
               float* __restrict__ outp, int B)
{
    extern __shared__ float sm[];
    float* sW   = sm + OFF_W;
    float* sH1  = sm + OFF_H1;
    float* sH2  = sm + OFF_H2;
    float* sU   = sm + OFF_U;
    float* sW1L = sm + OFF_W1L;
    float* sW1V = sm + OFF_W1V;
    float* sW3L = sm + OFF_W3L;
    float* sW3V = sm + OFF_W3V;
    float* sB1L = sm + OFF_B1L;
    float* sB2L = sm + OFF_B2L;
    float* sB3L = sm + OFF_B3L;
    float* sB1V = sm + OFF_B1V;
    float* sB2V = sm + OFF_B2V;
    float* sX   = sm + OFF_X;
    float* sQ   = sm + OFF_Q;
    float* sQd  = sm + OFF_QD;
    float* sA   = sm + OFF_A;
    float* sK1  = sm + OFF_K1;
    float* sM   = sm + OFF_M;
    float* sL   = sm + OFF_L;
    float* sDY  = sm + OFF_DY;
    float* sQdd = sm + OFF_QDD;

    const int tid  = threadIdx.x;
    const int lane = tid & 31;
    const int r0   = (tid >> 5) * 8;   // warp's first local row
    const int c0   = lane * 4;         // lane's first output col

    // ---- persistent small weights ----
    for (int i = tid; i < 12 * 128; i += NTH) {
        int r = i >> 7, c = i & 127;
        sW1L[r * SWS + c] = gW1L[i];
        sW1V[r * SWS + c] = gW1V[i];
    }
    for (int i = tid; i < 128 * 21; i += NTH) sW3L[i] = gW3L[i];
    for (int i = tid; i < 128; i += NTH) {
        sW3V[i] = gW3V[i];
        sB1L[i] = gb1L[i]; sB2L[i] = gb2L[i];
        sB1V[i] = gb1V[i]; sB2V[i] = gb2V[i];
    }
    if (tid < 21) sB3L[tid] = gb3L[tid];

    const int base = blockIdx.x * TB;
    for (int i = tid; i < TB * 6; i += NTH) {
        int r = i / 6, c = i - 6 * r;
        int g = base + r; if (g > B - 1) g = B - 1;
        sQ[i]  = o[g * 18 + c];
        sQd[i] = o[g * 18 + 6 + c];
        sA[i]  = ain[g * 6 + c];
    }
    __syncthreads();

    // ---------- helpers (NO trailing sync inside; caller syncs) ----------
    // big GEMM: Out[r][c] = post( Ain[r][:] @ sW[:, c] (+ bias) )
    // post: mulSrc ? mulSrc[idx]*acc : softplus(acc)     (mulSrc already sigma!)
    auto bigGemm = [&](const float* Ain, const float* bias, float* Out,
                       const float* mulSrc, bool inplace) {
        float acc[8][4];
        if (bias) {
            float4 bv = *(const float4*)&bias[c0];
            #pragma unroll
            for (int rr = 0; rr < 8; rr++) {
                acc[rr][0] = bv.x; acc[rr][1] = bv.y;
                acc[rr][2] = bv.z; acc[rr][3] = bv.w;
            }
        } else {
            #pragma unroll
            for (int rr = 0; rr < 8; rr++)
                acc[rr][0] = acc[rr][1] = acc[rr][2] = acc[rr][3] = 0.f;
        }
        #pragma unroll 2
        for (int k = 0; k < 128; k += 4) {
            float4 av[8];
            #pragma unroll
            for (int rr = 0; rr < 8; rr++)
                av[rr] = *(const float4*)&Ain[(r0 + rr) * HS + k];
            #pragma unroll
            for (int kk = 0; kk < 4; kk++) {
                float4 wv = *(const float4*)&sW[(k + kk) * SWS + c0];
                #pragma unroll
                for (int rr = 0; rr < 8; rr++) {
                    float a = f4c(av[rr], kk);
                    acc[rr][0] += a * wv.x;
                    acc[rr][1] += a * wv.y;
                    acc[rr][2] += a * wv.z;
                    acc[rr][3] += a * wv.w;
                }
            }
        }
        if (inplace) __syncthreads();   // everyone done reading before overwrite
        #pragma unroll
        for (int rr = 0; rr < 8; rr++) {
            int rb = (r0 + rr) * HS + c0;
            float4 ov;
            if (mulSrc) {
                float4 mv = *(const float4*)&mulSrc[rb];
                ov.x = acc[rr][0] * mv.x; ov.y = acc[rr][1] * mv.y;
                ov.z = acc[rr][2] * mv.z; ov.w = acc[rr][3] * mv.w;
            } else {
                ov.x = softplusf(acc[rr][0]); ov.y = softplusf(acc[rr][1]);
                ov.z = softplusf(acc[rr][2]); ov.w = softplusf(acc[rr][3]);
            }
            *(float4*)&Out[rb] = ov;
        }
    };

    // K=12 GEMM from sX: Out = softplus(sX @ Wsm + bias)
    auto smallGemm = [&](const float* Wsm, const float* bias, float* Out) {
        float acc[8][4];
        float4 bv = *(const float4*)&bias[c0];
        #pragma unroll
        for (int rr = 0; rr < 8; rr++) {
            acc[rr][0] = bv.x; acc[rr][1] = bv.y;
            acc[rr][2] = bv.z; acc[rr][3] = bv.w;
        }
        #pragma unroll
        for (int k = 0; k < 12; k += 4) {
            float4 av[8];
            #pragma unroll
            for (int rr = 0; rr < 8; rr++)
                av[rr] = *(const float4*)&sX[(r0 + rr) * 12 + k];
            #pragma unroll
            for (int kk = 0; kk < 4; kk++) {
                float4 wv = *(const float4*)&Wsm[(k + kk) * SWS + c0];
                #pragma unroll
                for (int rr = 0; rr < 8; rr++) {
                    float a = f4c(av[rr], kk);
                    acc[rr][0] += a * wv.x; acc[rr][1] += a * wv.y;
                    acc[rr][2] += a * wv.z; acc[rr][3] += a * wv.w;
                }
            }
        }
        #pragma unroll
        for (int rr = 0; rr < 8; rr++) {
            int rb = (r0 + rr) * HS + c0;
            float4 ov;
            ov.x = softplusf(acc[rr][0]); ov.y = softplusf(acc[rr][1]);
            ov.z = softplusf(acc[rr][2]); ov.w = softplusf(acc[rr][3]);
            *(float4*)&Out[rb] = ov;
        }
    };

    // 128->21 GEMM with W3L : sDY[r*21+l] (lanes 0..20)
    auto mini21 = [&](const float* Ain, const float* bias) {
        if (lane < 21) {
            float acc[8];
            float b = bias ? bias[lane] : 0.f;
            #pragma unroll
            for (int rr = 0; rr < 8; rr++) acc[rr] = b;
            #pragma unroll 2
            for (int k = 0; k < 128; k += 4) {
                float4 av[8];
                #pragma unroll
                for (int rr = 0; rr < 8; rr++)
                    av[rr] = *(const float4*)&Ain[(r0 + rr) * HS + k];
                #pragma unroll
                for (int kk = 0; kk < 4; kk++) {
                    float wv = sW3L[(k + kk) * 21 + lane];
                    #pragma unroll
                    for (int rr = 0; rr < 8; rr++)
                        acc[rr] += f4c(av[rr], kk) * wv;
                }
            }
            #pragma unroll
            for (int rr = 0; rr < 8; rr++) sDY[(r0 + rr) * 21 + lane] = acc[rr];
        }
    };

    // tangent layer-1 input: sU = sig1 * (cq*W1L[2d+1] - sq*W1L[2d])
    auto buildU1 = [&](int d, int t, int nt) {
        for (int i = t; i < TB * 32; i += nt) {
            int r = i >> 5, c4 = (i & 31) << 2;
            float cq = sX[r * 12 + 2 * d];
            float sq = sX[r * 12 + 2 * d + 1];
            float4 w0 = *(const float4*)&sW1L[(2 * d) * SWS + c4];
            float4 w1 = *(const float4*)&sW1L[(2 * d + 1) * SWS + c4];
            float4 s1 = *(const float4*)&sH1[r * HS + c4];
            float4 ov;
            ov.x = s1.x * (cq * w1.x - sq * w0.x);
            ov.y = s1.y * (cq * w1.y - sq * w0.y);
            ov.z = s1.z * (cq * w1.z - sq * w0.z);
            ov.w = s1.w * (cq * w1.w - sq * w0.w);
            *(float4*)&sU[r * HS + c4] = ov;
        }
    };

    // convert h -> sigma(h) in place
    auto sigConvert = [&](float* P) {
        for (int i = tid; i < TB * 32; i += NTH) {
            float4* p = (float4*)&P[(i >> 5) * HS + ((i & 31) << 2)];
            float4 v = *p;
            v.x = 1.f - __expf(-v.x); v.y = 1.f - __expf(-v.y);
            v.z = 1.f - __expf(-v.z); v.w = 1.f - __expf(-v.w);
            *p = v;
        }
    };

    auto streamW = [&](const float* g) {     // row-major 128x128 -> sW
        for (int i = tid; i < 4096; i += NTH) {
            int r = i >> 5, c4 = (i & 31) << 2;
            *(float4*)&sW[r * SWS + c4] = *(const float4*)&g[i << 2];
        }
    };
    auto streamWT = [&](const float* g) {    // transposed -> sW
        for (int i = tid; i < 16384; i += NTH) {
            int r = i >> 7, c = i & 127;
            sW[c * SWS + r] = g[i];
        }
    };

    const float ADT = (2.0f / 3.0f) * 0.02f;
    const int RO[6] = {0, 1, 3, 6, 10, 15};

    for (int stage = 0; stage < 2; ++stage) {
        float wv6[6], Aacc[6], svec[6], Cacc[6], cvec[6];

        // R1: trig features + stream W2L
        for (int i = tid; i < TB * 6; i += NTH) {
            int r = i / 6, j = i - 6 * r;
            float sv, cv; __sincosf(sQ[i], &sv, &cv);
            sX[r * 12 + 2 * j]     = cv;
            sX[r * 12 + 2 * j + 1] = sv;
        }
        streamW(gW2L);
        __syncthreads();

        // R2: h1 = softplus(x @ W1L + b1L)
        smallGemm(sW1L, sB1L, sH1);
        __syncthreads();

        // R3: h2 = softplus(h1 @ W2L + b2L)
        bigGemm(sH1, sB2L, sH2, nullptr, false);
        __syncthreads();

        // R4: y = h2 @ W3L + b3L  ;  sH1 := sigma(h1)
        mini21(sH2, sB3L);
        sigConvert(sH1);
        __syncthreads();

        // R5: per-row L, M, w  ||  sH2 := sigma(h2)  ||  u1(dir 0)
        if (tid < TB) {
            const int r = tid;
            const float* y = sDY + r * 21;
            float* Lp = sL + r * 21;
            #pragma unroll
            for (int t = 0; t < 21; t++) Lp[t] = y[t];
            float* Mp = sM + r * 36;
            #pragma unroll
            for (int i = 0; i < 6; i++) {
                #pragma unroll
                for (int j = 0; j <= i; j++) {
                    float s2 = 0.f;
                    #pragma unroll
                    for (int k = 0; k <= j; k++)
                        s2 += Lp[RO[i] + k] * Lp[RO[j] + k];
                    if (i == j) s2 += 1e-6f;
                    Mp[i * 6 + j] = s2; Mp[j * 6 + i] = s2;
                }
            }
            #pragma unroll
            for (int i = 0; i < 6; i++) {
                float s2 = 0.f;
                #pragma unroll
                for (int j = 0; j < 6; j++) s2 += Mp[i * 6 + j] * sQd[r * 6 + j];
                wv6[i] = s2; Aacc[i] = 0.f; svec[i] = 0.f;
            }
        }
        sigConvert(sH2);
        if (tid >= 64) buildU1(0, tid - 64, NTH - 64);
        __syncthreads();

        // ---- 6 tangent directions ----
        for (int dir = 0; dir < 6; ++dir) {
            bigGemm(sU, nullptr, sU, sH2, true);   // u2 = sig2*(u1@W2L), in place
            __syncthreads();
            mini21(sU, nullptr);                   // dy
            if (dir == 5) streamW(gW2V);           // sW := W2V (W2L done)
            __syncthreads();

            if (tid < TB) {                        // epilogue(dir)
                const int r = tid;
                const float* dy  = sDY + r * 21;
                const float* Lp  = sL  + r * 21;
                const float* qdr = sQd + r * 6;
                float D[6][6];
                #pragma unroll
                for (int i = 0; i < 6; i++) {
                    #pragma unroll
                    for (int j = 0; j <= i; j++) {
                        float s2 = 0.f;
                        #pragma unroll
                        for (int k = 0; k <= j; k++)
                            s2 += dy[RO[i] + k] * Lp[RO[j] + k]
                                + Lp[RO[i] + k] * dy[RO[j] + k];
                        D[i][j] = s2; D[j][i] = s2;
                    }
                }
                float qdd = qdr[dir];
                float cdot = 0.f;
                #pragma unroll
                for (int i = 0; i < 6; i++) {
                    float v1 = 0.f, v2 = 0.f;
                    #pragma unroll
                    for (int j = 0; j < 6; j++) {
                        v1 += D[i][j] * wv6[j];
                        v2 += D[i][j] * qdr[j];
                    }
                    Aacc[i] += qdd * v1;
                    svec[i] += qdd * v2;
                    cdot    += qdr[i] * v1;
                }
                Cacc[dir] = cdot;
            }
            if (dir < 5) {
                if (tid >= 64) buildU1(dir + 1, tid - 64, NTH - 64);
            } else {
                smallGemm(sW1V, sB1V, sH1);        // h1V (all threads)
            }
            __syncthreads();
        }

        // h2V
        bigGemm(sH1, sB2V, sH2, nullptr, false);
        __syncthreads();

        // R9: u2g = sig(h2V)*W3V  ||  sW := W2V^T  ||  sH1 := sig(h1V)  ||  cvec
        for (int i = tid; i < TB * 32; i += NTH) {
            int r = i >> 5, c4 = (i & 31) << 2;
            float4 h = *(const float4*)&sH2[r * HS + c4];
            float4 w = *(const float4*)&sW3V[c4];
            float4 ov;
            ov.x = (1.f - __expf(-h.x)) * w.x;
            ov.y = (1.f - __expf(-h.y)) * w.y;
            ov.z = (1.f - __expf(-h.z)) * w.z;
            ov.w = (1.f - __expf(-h.w)) * w.w;
            *(float4*)&sU[r * HS + c4] = ov;
        }
        streamWT(gW2V);
        sigConvert(sH1);
        if (tid < TB) {
            const int r = tid;
            #pragma unroll
            for (int i = 0; i < 6; i++) {
                float ms = 0.f;
                #pragma unroll
                for (int j = 0; j < 6; j++) ms += sM[r * 36 + i * 6 + j] * svec[j];
                cvec[i] = Aacc[i] + ms - Cacc[i];
            }
        }
        __syncthreads();

        // R10: u1g = sig1V * (u2g @ W2V^T)  -> sH2 (no alias)
        bigGemm(sU, nullptr, sH2, sH1, false);
        __syncthreads();

        // R11: gx[d] = sum_k u1g[k] * W1V[d][k]  (lanes 0..11)
        if (lane < 12) {
            float acc[8];
            #pragma unroll
            for (int rr = 0; rr < 8; rr++) acc[rr] = 0.f;
            #pragma unroll 2
            for (int k = 0; k < 128; k += 4) {
                float4 wv = *(const float4*)&sW1V[lane * SWS + k];
                #pragma unroll
                for (int rr = 0; rr < 8; rr++) {
                    float4 av = *(const float4*)&sH2[(r0 + rr) * HS + k];
                    acc[rr] += av.x * wv.x + av.y * wv.y
                             + av.z * wv.z + av.w * wv.w;
                }
            }
            #pragma unroll
            for (int rr = 0; rr < 8; rr++) sDY[(r0 + rr) * 21 + lane] = acc[rr];
        }
        __syncthreads();

        // R12: rhs, triangular solves -> qddot ; stage-0 state update
        if (tid < TB) {
            const int r = tid;
            const float* Mp = sM + r * 36;
            float rhs[6];
            #pragma unroll
            for (int i = 0; i < 6; i++) {
                float gx0 = sDY[r * 21 + 2 * i];
                float gx1 = sDY[r * 21 + 2 * i + 1];
                float dv = -sX[r * 12 + 2 * i + 1] * gx0
                         +  sX[r * 12 + 2 * i]     * gx1;
                rhs[i] = sA[r * 6 + i] - cvec[i] - dv;
            }
            float yv[6];
            #pragma unroll
            for (int i = 0; i < 6; i++) {
                float s2 = rhs[i];
                #pragma unroll
                for (int j = 0; j < 6; j++) if (j < i) s2 -= Mp[i * 6 + j] * yv[j];
                yv[i] = s2 / Mp[i * 6 + i];
            }
            float zv[6];
            #pragma unroll
            for (int ii = 5; ii >= 0; ii--) {
                float s2 = yv[ii];
                #pragma unroll
                for (int j = 0; j < 6; j++) if (j > ii) s2 -= Mp[j * 6 + ii] * zv[j];
                zv[ii] = s2 / Mp[ii * 6 + ii];
            }
            if (stage == 0) {
                #pragma unroll
                for (int i = 0; i < 6; i++) {
                    sK1[r * 6 + i] = zv[i];
                    float q0  = sQ[r * 6 + i];
                    float qd0 = sQd[r * 6 + i];
                    sQ[r * 6 + i]  = q0  + ADT * qd0;
                    sQd[r * 6 + i] = qd0 + ADT * zv[i];
                }
            } else {
                #pragma unroll
                for (int i = 0; i < 6; i++) sQdd[r * 6 + i] = zv[i];
            }
        }
        __syncthreads();
    }

    // ---- RK2 combine + passthrough tail ----
    for (int i = tid; i < TB * 18; i += NTH) {
        int r = i / 18, c = i - 18 * r;
        int g = base + r;
        if (g < B) {
            float v;
            if (c < 6) {
                v = o[g * 18 + c] + 0.02f * (0.25f * o[g * 18 + 6 + c] + 0.75f * sQd[r * 6 + c]);
            } else if (c < 12) {
                int j = c - 6;
                v = o[g * 18 + c] + 0.02f * (0.25f * sK1[r * 6 + j] + 0.75f * sQdd[r * 6 + j]);
            } else {
                v = o[g * 18 + c];
            }
            outp[g * 18 + c] = v;
        }
    }
}

extern "C" void kernel_launch(void* const* d_in, const int* in_sizes, int n_in,
                              void* d_out, int out_size) {
    const float* o    = (const float*)d_in[0];
    const float* a    = (const float*)d_in[1];
    const float* W1L  = (const float*)d_in[2];
    const float* b1L  = (const float*)d_in[3];
    const float* W2L  = (const float*)d_in[4];
    const float* b2L  = (const float*)d_in[5];
    const float* W3L  = (const float*)d_in[6];
    const float* b3L  = (const float*)d_in[7];
    const float* W1V  = (const float*)d_in[8];
    const float* b1V  = (const float*)d_in[9];
    const float* W2V  = (const float*)d_in[10];
    const float* b2V  = (const float*)d_in[11];
    const float* W3V  = (const float*)d_in[12];
    float* outp = (float*)d_out;

    int B = in_sizes[0] / 18;
    int grid = (B + TB - 1) / TB;
    size_t smem = (size_t)SMEM_FLOATS * sizeof(float);
    cudaFuncSetAttribute(lnn6dof_kernel,
                         cudaFuncAttributeMaxDynamicSharedMemorySize, (int)smem);
    lnn6dof_kernel<<<grid, NTH, smem>>>(o, a, W1L, b1L, W2L, b2L, W3L, b3L,
                                        W1V, b1V, W2V, b2V, W3V, outp, B);
}

// round 8
// speedup vs baseline: 1.0019x; 1.0019x over previous
#include <cuda_runtime.h>
#include <math.h>

#define NTH 256
#define TB  64
#define SWS 132   // weight smem stride (floats)
#define HS  132   // activation smem stride (floats)

// ---- smem layout (float offsets) ----
#define OFF_W    0
#define OFF_H1   (OFF_W   + 128*SWS)
#define OFF_H2   (OFF_H1  + TB*HS)
#define OFF_U    (OFF_H2  + TB*HS)
#define OFF_W1L  (OFF_U   + TB*HS)
#define OFF_W1V  (OFF_W1L + 12*SWS)
#define OFF_W3L  (OFF_W1V + 12*SWS)
#define OFF_W3V  (OFF_W3L + 128*21)
#define OFF_B1L  (OFF_W3V + 128)
#define OFF_B2L  (OFF_B1L + 128)
#define OFF_B3L  (OFF_B2L + 128)
#define OFF_B1V  (OFF_B3L + 24)
#define OFF_B2V  (OFF_B1V + 128)
#define OFF_X    (OFF_B2V + 128)
#define OFF_Q    (OFF_X   + TB*12)
#define OFF_QD   (OFF_Q   + TB*6)
#define OFF_A    (OFF_QD  + TB*6)
#define OFF_K1   (OFF_A   + TB*6)
#define OFF_M    (OFF_K1  + TB*6)
#define OFF_L    (OFF_M   + TB*36)
#define OFF_DY   (OFF_L   + TB*21)
#define OFF_QDD  (OFF_DY  + TB*21)
#define SMEM_FLOATS (OFF_QDD + TB*6)

static __device__ __forceinline__ float softplusf(float z) {
    return fmaxf(z, 0.0f) + __logf(1.0f + __expf(-fabsf(z)));
}
// sigmoid(z) given h = softplus(z):  sigma = 1 - exp(-h)   (h >= 0)
static __device__ __forceinline__ float sig_from_h(float h) {
    return 1.0f - __expf(-h);
}
static __device__ __forceinline__ float f4c(const float4& v, int k) {
    return k == 0 ? v.x : k == 1 ? v.y : k == 2 ? v.z : v.w;
}

extern "C" __global__ void __launch_bounds__(NTH, 1)
lnn6dof_kernel(const float* __restrict__ o,    const float* __restrict__ ain,
               const float* __restrict__ gW1L, const float* __restrict__ gb1L,
               const float* __restrict__ gW2L, const float* __restrict__ gb2L,
               const float* __restrict__ gW3L, const float* __restrict__ gb3L,
               const float* __restrict__ gW1V, const float* __restrict__ gb1V,
               const float* __restrict__ gW2V, const float* __restrict__ gb2V,
               const float* __restrict__ gW3V,
               float* __restrict__ outp, int B)
{
    extern __shared__ float sm[];
    float* sW   = sm + OFF_W;
    float* sH1  = sm + OFF_H1;
    float* sH2  = sm + OFF_H2;
    float* sU   = sm + OFF_U;
    float* sW1L = sm + OFF_W1L;
    float* sW1V = sm + OFF_W1V;
    float* sW3L = sm + OFF_W3L;
    float* sW3V = sm + OFF_W3V;
    float* sB1L = sm + OFF_B1L;
    float* sB2L = sm + OFF_B2L;
    float* sB3L = sm + OFF_B3L;
    float* sB1V = sm + OFF_B1V;
    float* sB2V = sm + OFF_B2V;
    float* sX   = sm + OFF_X;
    float* sQ   = sm + OFF_Q;
    float* sQd  = sm + OFF_QD;
    float* sA   = sm + OFF_A;
    float* sK1  = sm + OFF_K1;
    float* sM   = sm + OFF_M;
    float* sL   = sm + OFF_L;
    float* sDY  = sm + OFF_DY;
    float* sQdd = sm + OFF_QDD;

    const int tid  = threadIdx.x;
    const int lane = tid & 31;
    const int r0   = (tid >> 5) * 8;   // warp's first local row
    const int c0   = lane * 4;         // lane's first output col

    // ---- persistent small weights ----
    for (int i = tid; i < 12 * 128; i += NTH) {
        int r = i >> 7, c = i & 127;
        sW1L[r * SWS + c] = gW1L[i];
        sW1V[r * SWS + c] = gW1V[i];
    }
    for (int i = tid; i < 128 * 21; i += NTH) sW3L[i] = gW3L[i];
    for (int i = tid; i < 128; i += NTH) {
        sW3V[i] = gW3V[i];
        sB1L[i] = gb1L[i]; sB2L[i] = gb2L[i];
        sB1V[i] = gb1V[i]; sB2V[i] = gb2V[i];
    }
    if (tid < 21) sB3L[tid] = gb3L[tid];

    const int base = blockIdx.x * TB;
    for (int i = tid; i < TB * 6; i += NTH) {
        int r = i / 6, c = i - 6 * r;
        int g = base + r; if (g > B - 1) g = B - 1;
        sQ[i]  = o[g * 18 + c];
        sQd[i] = o[g * 18 + 6 + c];
        sA[i]  = ain[g * 6 + c];
    }
    __syncthreads();

    // ---------- helpers (NO trailing sync inside; caller syncs) ----------
    // big GEMM: Out[r][c] = post( Ain[r][:] @ sW[:, c] (+ bias) )
    // post: mulSrc ? mulSrc[idx]*acc : softplus(acc)     (mulSrc already sigma!)
    auto bigGemm = [&](const float* Ain, const float* bias, float* Out,
                       const float* mulSrc, bool inplace) {
        float acc[8][4];
        if (bias) {
            float4 bv = *(const float4*)&bias[c0];
            #pragma unroll
            for (int rr = 0; rr < 8; rr++) {
                acc[rr][0] = bv.x; acc[rr][1] = bv.y;
                acc[rr][2] = bv.z; acc[rr][3] = bv.w;
            }
        } else {
            #pragma unroll
            for (int rr = 0; rr < 8; rr++)
                acc[rr][0] = acc[rr][1] = acc[rr][2] = acc[rr][3] = 0.f;
        }
        #pragma unroll 2
        for (int k = 0; k < 128; k += 4) {
            float4 av[8];
            #pragma unroll
            for (int rr = 0; rr < 8; rr++)
                av[rr] = *(const float4*)&Ain[(r0 + rr) * HS + k];
            #pragma unroll
            for (int kk = 0; kk < 4; kk++) {
                float4 wv = *(const float4*)&sW[(k + kk) * SWS + c0];
                #pragma unroll
                for (int rr = 0; rr < 8; rr++) {
                    float a = f4c(av[rr], kk);
                    acc[rr][0] += a * wv.x;
                    acc[rr][1] += a * wv.y;
                    acc[rr][2] += a * wv.z;
                    acc[rr][3] += a * wv.w;
                }
            }
        }
        if (inplace) __syncthreads();   // everyone done reading before overwrite
        #pragma unroll
        for (int rr = 0; rr < 8; rr++) {
            int rb = (r0 + rr) * HS + c0;
            float4 ov;
            if (mulSrc) {
                float4 mv = *(const float4*)&mulSrc[rb];
                ov.x = acc[rr][0] * mv.x; ov.y = acc[rr][1] * mv.y;
                ov.z = acc[rr][2] * mv.z; ov.w = acc[rr][3] * mv.w;
            } else {
                ov.x = softplusf(acc[rr][0]); ov.y = softplusf(acc[rr][1]);
                ov.z = softplusf(acc[rr][2]); ov.w = softplusf(acc[rr][3]);
            }
            *(float4*)&Out[rb] = ov;
        }
    };

    // K=12 GEMM from sX: Out = softplus(sX @ Wsm + bias)
    auto smallGemm = [&](const float* Wsm, const float* bias, float* Out) {
        float acc[8][4];
        float4 bv = *(const float4*)&bias[c0];
        #pragma unroll
        for (int rr = 0; rr < 8; rr++) {
            acc[rr][0] = bv.x; acc[rr][1] = bv.y;
            acc[rr][2] = bv.z; acc[rr][3] = bv.w;
        }
        #pragma unroll
        for (int k = 0; k < 12; k += 4) {
            float4 av[8];
            #pragma unroll
            for (int rr = 0; rr < 8; rr++)
                av[rr] = *(const float4*)&sX[(r0 + rr) * 12 + k];
            #pragma unroll
            for (int kk = 0; kk < 4; kk++) {
                float4 wv = *(const float4*)&Wsm[(k + kk) * SWS + c0];
                #pragma unroll
                for (int rr = 0; rr < 8; rr++) {
                    float a = f4c(av[rr], kk);
                    acc[rr][0] += a * wv.x; acc[rr][1] += a * wv.y;
                    acc[rr][2] += a * wv.z; acc[rr][3] += a * wv.w;
                }
            }
        }
        #pragma unroll
        for (int rr = 0; rr < 8; rr++) {
            int rb = (r0 + rr) * HS + c0;
            float4 ov;
            ov.x = softplusf(acc[rr][0]); ov.y = softplusf(acc[rr][1]);
            ov.z = softplusf(acc[rr][2]); ov.w = softplusf(acc[rr][3]);
            *(float4*)&Out[rb] = ov;
        }
    };

    // 128->21 GEMM with W3L : sDY[r*21+l] (lanes 0..20)
    auto mini21 = [&](const float* Ain, const float* bias) {
        if (lane < 21) {
            float acc[8];
            float b = bias ? bias[lane] : 0.f;
            #pragma unroll
            for (int rr = 0; rr < 8; rr++) acc[rr] = b;
            #pragma unroll 2
            for (int k = 0; k < 128; k += 4) {
                float4 av[8];
                #pragma unroll
                for (int rr = 0; rr < 8; rr++)
                    av[rr] = *(const float4*)&Ain[(r0 + rr) * HS + k];
                #pragma unroll
                for (int kk = 0; kk < 4; kk++) {
                    float wv = sW3L[(k + kk) * 21 + lane];
                    #pragma unroll
                    for (int rr = 0; rr < 8; rr++)
                        acc[rr] += f4c(av[rr], kk) * wv;
                }
            }
            #pragma unroll
            for (int rr = 0; rr < 8; rr++) sDY[(r0 + rr) * 21 + lane] = acc[rr];
        }
    };

    // tangent layer-1 input: sU = sig1 * (cq*W1L[2d+1] - sq*W1L[2d])
    auto buildU1 = [&](int d, int t, int nt) {
        for (int i = t; i < TB * 32; i += nt) {
            int r = i >> 5, c4 = (i & 31) << 2;
            float cq = sX[r * 12 + 2 * d];
            float sq = sX[r * 12 + 2 * d + 1];
            float4 w0 = *(const float4*)&sW1L[(2 * d) * SWS + c4];
            float4 w1 = *(const float4*)&sW1L[(2 * d + 1) * SWS + c4];
            float4 s1 = *(const float4*)&sH1[r * HS + c4];
            float4 ov;
            ov.x = s1.x * (cq * w1.x - sq * w0.x);
            ov.y = s1.y * (cq * w1.y - sq * w0.y);
            ov.z = s1.z * (cq * w1.z - sq * w0.z);
            ov.w = s1.w * (cq * w1.w - sq * w0.w);
            *(float4*)&sU[r * HS + c4] = ov;
        }
    };

    // convert h -> sigma(h) in place
    auto sigConvert = [&](float* P) {
        for (int i = tid; i < TB * 32; i += NTH) {
            float4* p = (float4*)&P[(i >> 5) * HS + ((i & 31) << 2)];
            float4 v = *p;
            v.x = 1.f - __expf(-v.x); v.y = 1.f - __expf(-v.y);
            v.z = 1.f - __expf(-v.z); v.w = 1.f - __expf(-v.w);
            *p = v;
        }
    };

    auto streamW = [&](const float* g) {     // row-major 128x128 -> sW
        for (int i = tid; i < 4096; i += NTH) {
            int r = i >> 5, c4 = (i & 31) << 2;
            *(float4*)&sW[r * SWS + c4] = *(const float4*)&g[i << 2];
        }
    };
    auto streamWT = [&](const float* g) {    // transposed -> sW
        for (int i = tid; i < 16384; i += NTH) {
            int r = i >> 7, c = i & 127;
            sW[c * SWS + r] = g[i];
        }
    };

    const float ADT = (2.0f / 3.0f) * 0.02f;
    const int RO[6] = {0, 1, 3, 6, 10, 15};

    for (int stage = 0; stage < 2; ++stage) {
        float wv6[6], Aacc[6], svec[6], Cacc[6], cvec[6];

        // R1: trig features + stream W2L
        for (int i = tid; i < TB * 6; i += NTH) {
            int r = i / 6, j = i - 6 * r;
            float sv, cv; __sincosf(sQ[i], &sv, &cv);
            sX[r * 12 + 2 * j]     = cv;
            sX[r * 12 + 2 * j + 1] = sv;
        }
        streamW(gW2L);
        __syncthreads();

        // R2: h1 = softplus(x @ W1L + b1L)
        smallGemm(sW1L, sB1L, sH1);
        __syncthreads();

        // R3: h2 = softplus(h1 @ W2L + b2L)
        bigGemm(sH1, sB2L, sH2, nullptr, false);
        __syncthreads();

        // R4: y = h2 @ W3L + b3L  ;  sH1 := sigma(h1)
        mini21(sH2, sB3L);
        sigConvert(sH1);
        __syncthreads();

        // R5: per-row L, M, w  ||  sH2 := sigma(h2)  ||  u1(dir 0)
        if (tid < TB) {
            const int r = tid;
            const float* y = sDY + r * 21;
            float* Lp = sL + r * 21;
            #pragma unroll
            for (int t = 0; t < 21; t++) Lp[t] = y[t];
            float* Mp = sM + r * 36;
            #pragma unroll
            for (int i = 0; i < 6; i++) {
                #pragma unroll
                for (int j = 0; j <= i; j++) {
                    float s2 = 0.f;
                    #pragma unroll
                    for (int k = 0; k <= j; k++)
                        s2 += Lp[RO[i] + k] * Lp[RO[j] + k];
                    if (i == j) s2 += 1e-6f;
                    Mp[i * 6 + j] = s2; Mp[j * 6 + i] = s2;
                }
            }
            #pragma unroll
            for (int i = 0; i < 6; i++) {
                float s2 = 0.f;
                #pragma unroll
                for (int j = 0; j < 6; j++) s2 += Mp[i * 6 + j] * sQd[r * 6 + j];
                wv6[i] = s2; Aacc[i] = 0.f; svec[i] = 0.f;
            }
        }
        sigConvert(sH2);
        if (tid >= 64) buildU1(0, tid - 64, NTH - 64);
        __syncthreads();

        // ---- 6 tangent directions ----
        for (int dir = 0; dir < 6; ++dir) {
            bigGemm(sU, nullptr, sU, sH2, true);   // u2 = sig2*(u1@W2L), in place
            __syncthreads();
            mini21(sU, nullptr);                   // dy
            if (dir == 5) streamW(gW2V);           // sW := W2V (W2L done)
            __syncthreads();

            if (tid < TB) {                        // epilogue(dir)
                const int r = tid;
                const float* dy  = sDY + r * 21;
                const float* Lp  = sL  + r * 21;
                const float* qdr = sQd + r * 6;
                float D[6][6];
                #pragma unroll
                for (int i = 0; i < 6; i++) {
                    #pragma unroll
                    for (int j = 0; j <= i; j++) {
                        float s2 = 0.f;
                        #pragma unroll
                        for (int k = 0; k <= j; k++)
                            s2 += dy[RO[i] + k] * Lp[RO[j] + k]
                                + Lp[RO[i] + k] * dy[RO[j] + k];
                        D[i][j] = s2; D[j][i] = s2;
                    }
                }
                float qdd = qdr[dir];
                float cdot = 0.f;
                #pragma unroll
                for (int i = 0; i < 6; i++) {
                    float v1 = 0.f, v2 = 0.f;
                    #pragma unroll
                    for (int j = 0; j < 6; j++) {
                        v1 += D[i][j] * wv6[j];
                        v2 += D[i][j] * qdr[j];
                    }
                    Aacc[i] += qdd * v1;
                    svec[i] += qdd * v2;
                    cdot    += qdr[i] * v1;
                }
                Cacc[dir] = cdot;
            }
            if (dir < 5) {
                if (tid >= 64) buildU1(dir + 1, tid - 64, NTH - 64);
            } else {
                smallGemm(sW1V, sB1V, sH1);        // h1V (all threads)
            }
            __syncthreads();
        }

        // h2V
        bigGemm(sH1, sB2V, sH2, nullptr, false);
        __syncthreads();

        // R9: u2g = sig(h2V)*W3V  ||  sW := W2V^T  ||  sH1 := sig(h1V)  ||  cvec
        for (int i = tid; i < TB * 32; i += NTH) {
            int r = i >> 5, c4 = (i & 31) << 2;
            float4 h = *(const float4*)&sH2[r * HS + c4];
            float4 w = *(const float4*)&sW3V[c4];
            float4 ov;
            ov.x = (1.f - __expf(-h.x)) * w.x;
            ov.y = (1.f - __expf(-h.y)) * w.y;
            ov.z = (1.f - __expf(-h.z)) * w.z;
            ov.w = (1.f - __expf(-h.w)) * w.w;
            *(float4*)&sU[r * HS + c4] = ov;
        }
        streamWT(gW2V);
        sigConvert(sH1);
        if (tid < TB) {
            const int r = tid;
            #pragma unroll
            for (int i = 0; i < 6; i++) {
                float ms = 0.f;
                #pragma unroll
                for (int j = 0; j < 6; j++) ms += sM[r * 36 + i * 6 + j] * svec[j];
                cvec[i] = Aacc[i] + ms - Cacc[i];
            }
        }
        __syncthreads();

        // R10: u1g = sig1V * (u2g @ W2V^T)  -> sH2 (no alias)
        bigGemm(sU, nullptr, sH2, sH1, false);
        __syncthreads();

        // R11: gx[d] = sum_k u1g[k] * W1V[d][k]  (lanes 0..11)
        if (lane < 12) {
            float acc[8];
            #pragma unroll
            for (int rr = 0; rr < 8; rr++) acc[rr] = 0.f;
            #pragma unroll 2
            for (int k = 0; k < 128; k += 4) {
                float4 wv = *(const float4*)&sW1V[lane * SWS + k];
                #pragma unroll
                for (int rr = 0; rr < 8; rr++) {
                    float4 av = *(const float4*)&sH2[(r0 + rr) * HS + k];
                    acc[rr] += av.x * wv.x + av.y * wv.y
                             + av.z * wv.z + av.w * wv.w;
                }
            }
            #pragma unroll
            for (int rr = 0; rr < 8; rr++) sDY[(r0 + rr) * 21 + lane] = acc[rr];
        }
        __syncthreads();

        // R12: rhs, triangular solves -> qddot ; stage-0 state update
        if (tid < TB) {
            const int r = tid;
            const float* Mp = sM + r * 36;
            float rhs[6];
            #pragma unroll
            for (int i = 0; i < 6; i++) {
                float gx0 = sDY[r * 21 + 2 * i];
                float gx1 = sDY[r * 21 + 2 * i + 1];
                float dv = -sX[r * 12 + 2 * i + 1] * gx0
                         +  sX[r * 12 + 2 * i]     * gx1;
                rhs[i] = sA[r * 6 + i] - cvec[i] - dv;
            }
            float yv[6];
            #pragma unroll
            for (int i = 0; i < 6; i++) {
                float s2 = rhs[i];
                #pragma unroll
                for (int j = 0; j < 6; j++) if (j < i) s2 -= Mp[i * 6 + j] * yv[j];
                yv[i] = s2 / Mp[i * 6 + i];
            }
            float zv[6];
            #pragma unroll
            for (int ii = 5; ii >= 0; ii--) {
                float s2 = yv[ii];
                #pragma unroll
                for (int j = 0; j < 6; j++) if (j > ii) s2 -= Mp[j * 6 + ii] * zv[j];
                zv[ii] = s2 / Mp[ii * 6 + ii];
            }
            if (stage == 0) {
                #pragma unroll
                for (int i = 0; i < 6; i++) {
                    sK1[r * 6 + i] = zv[i];
                    float q0  = sQ[r * 6 + i];
                    float qd0 = sQd[r * 6 + i];
                    sQ[r * 6 + i]  = q0  + ADT * qd0;
                    sQd[r * 6 + i] = qd0 + ADT * zv[i];
                }
            } else {
                #pragma unroll
                for (int i = 0; i < 6; i++) sQdd[r * 6 + i] = zv[i];
            }
        }
        __syncthreads();
    }

    // ---- RK2 combine + passthrough tail ----
    for (int i = tid; i < TB * 18; i += NTH) {
        int r = i / 18, c = i - 18 * r;
        int g = base + r;
        if (g < B) {
            float v;
            if (c < 6) {
                v = o[g * 18 + c] + 0.02f * (0.25f * o[g * 18 + 6 + c] + 0.75f * sQd[r * 6 + c]);
            } else if (c < 12) {
                int j = c - 6;
                v = o[g * 18 + c] + 0.02f * (0.25f * sK1[r * 6 + j] + 0.75f * sQdd[r * 6 + j]);
            } else {
                v = o[g * 18 + c];
            }
            outp[g * 18 + c] = v;
        }
    }
}

extern "C" void kernel_launch(void* const* d_in, const int* in_sizes, int n_in,
                              void* d_out, int out_size) {
    const float* o    = (const float*)d_in[0];
    const float* a    = (const float*)d_in[1];
    const float* W1L  = (const float*)d_in[2];
    const float* b1L  = (const float*)d_in[3];
    const float* W2L  = (const float*)d_in[4];
    const float* b2L  = (const float*)d_in[5];
    const float* W3L  = (const float*)d_in[6];
    const float* b3L  = (const float*)d_in[7];
    const float* W1V  = (const float*)d_in[8];
    const float* b1V  = (const float*)d_in[9];
    const float* W2V  = (const float*)d_in[10];
    const float* b2V  = (const float*)d_in[11];
    const float* W3V  = (const float*)d_in[12];
    float* outp = (float*)d_out;

    int B = in_sizes[0] / 18;
    int grid = (B + TB - 1) / TB;
    size_t smem = (size_t)SMEM_FLOATS * sizeof(float);
    cudaFuncSetAttribute(lnn6dof_kernel,
                         cudaFuncAttributeMaxDynamicSharedMemorySize, (int)smem);
    lnn6dof_kernel<<<grid, NTH, smem>>>(o, a, W1L, b1L, W2L, b2L, W3L, b3L,
                                        W1V, b1V, W2V, b2V, W3V, outp, B);
}

// round 11
// speedup vs baseline: 1.9952x; 1.9913x over previous
#include <cuda_runtime.h>
#include <cuda_bf16.h>
#include <cstdint>
#include <math.h>

#define NTH 256
#define TB  64

// ---- smem byte offsets ----
#define SB_AH  0                      // A hi: 64 x 272B
#define SB_AL  17408
#define SB_WH  34816                  // W hi: 128 x 272B
#define SB_WL  69632
#define SB_W3H 104448                 // W3 hi: 24 x 272B
#define SB_W3L 110976
#define SB_W1R 117504                 // 12288: W1 split (hi+lo) OR W1 fp32 (first 6144)
#define SB_XH  129792                 // X hi: 64 x 48B
#define SB_XL  132864
#define SB_DY  135936                 // 64 x 24 f32
#define SB_GX  142080                 // 64 x 24 f32
#define SB_XF  148224                 // 64 x 12 f32
#define SB_Q   151296
#define SB_QD  152832
#define SB_AA  154368
#define SB_LR  155904                 // 64 x 21 f32
#define SB_MS  161280
#define SB_B   166656                 // 664 f32
#define SB_END 169312

#define MMA(acc,a0,a1,a2,a3,b0,b1) \
  asm volatile("mma.sync.aligned.m16n8k16.row.col.f32.bf16.bf16.f32 " \
    "{%0,%1,%2,%3},{%4,%5,%6,%7},{%8,%9},{%0,%1,%2,%3};" \
    : "+f"(acc[0]),"+f"(acc[1]),"+f"(acc[2]),"+f"(acc[3]) \
    : "r"(a0),"r"(a1),"r"(a2),"r"(a3),"r"(b0),"r"(b1))

static __device__ __forceinline__ float softplusf(float z) {
    return fmaxf(z, 0.0f) + __logf(1.0f + __expf(-fabsf(z)));
}
static __device__ __forceinline__ uint32_t pack2(float a, float b) {
    __nv_bfloat162 t = __floats2bfloat162_rn(a, b);
    return *reinterpret_cast<uint32_t*>(&t);
}
static __device__ __forceinline__ void wsplit2(float v, char* hi, char* lo, uint32_t off) {
    __nv_bfloat16 h = __float2bfloat16(v);
    *(__nv_bfloat16*)(hi + off) = h;
    *(__nv_bfloat16*)(lo + off) = __float2bfloat16(v - __bfloat162float(h));
}

extern "C" __global__ void __launch_bounds__(NTH, 1)
lnn_mma(const float* __restrict__ o,    const float* __restrict__ ain,
        const float* __restrict__ gW1L, const float* __restrict__ gb1L,
        const float* __restrict__ gW2L, const float* __restrict__ gb2L,
        const float* __restrict__ gW3L, const float* __restrict__ gb3L,
        const float* __restrict__ gW1V, const float* __restrict__ gb1V,
        const float* __restrict__ gW2V, const float* __restrict__ gb2V,
        const float* __restrict__ gW3V,
        float* __restrict__ outp, int B)
{
    extern __shared__ char smc[];
    uint32_t* AH32  = (uint32_t*)(smc + SB_AH);
    uint32_t* AL32  = (uint32_t*)(smc + SB_AL);
    uint32_t* WH32  = (uint32_t*)(smc + SB_WH);
    uint32_t* WL32  = (uint32_t*)(smc + SB_WL);
    uint32_t* W3H32 = (uint32_t*)(smc + SB_W3H);
    uint32_t* W3L32 = (uint32_t*)(smc + SB_W3L);
    uint32_t* U1H32 = (uint32_t*)(smc + SB_W1R);
    uint32_t* U1L32 = (uint32_t*)(smc + SB_W1R + 6144);
    uint32_t* XH32  = (uint32_t*)(smc + SB_XH);
    uint32_t* XL32  = (uint32_t*)(smc + SB_XL);
    float* W1f  = (float*)(smc + SB_W1R);
    float* sDYf = (float*)(smc + SB_DY);
    float* sGX  = (float*)(smc + SB_GX);
    float* sXF  = (float*)(smc + SB_XF);
    float* sQ   = (float*)(smc + SB_Q);
    float* sQD  = (float*)(smc + SB_QD);
    float* sAA  = (float*)(smc + SB_AA);
    float* sLr  = (float*)(smc + SB_LR);
    float* sMs  = (float*)(smc + SB_MS);
    float* sB   = (float*)(smc + SB_B);

    const int tid = threadIdx.x, w = tid >> 5, lane = tid & 31;
    const int gid = lane >> 2, tig = lane & 3;
    const int mt = w & 3, nh = w >> 2;
    const int r0 = mt * 16 + gid, r1 = r0 + 8;
    const int base = blockIdx.x * TB;
    const int RO[6] = {0, 1, 3, 6, 10, 15};
    #define MML(i,j) ((i)>=(j) ? Msl[RO[i]+(j)] : Msl[RO[j]+(i)])

    // persistent loads
    for (int i = tid; i < 128; i += NTH) {
        sB[i] = gb1L[i]; sB[128 + i] = gb2L[i];
        sB[256 + i] = gb1V[i]; sB[384 + i] = gb2V[i]; sB[512 + i] = gW3V[i];
    }
    if (tid < 24) sB[640 + tid] = tid < 21 ? gb3L[tid] : 0.f;
    for (int i = tid; i < 3072; i += NTH) {     // W3^T tile (24 x 128)
        int j = i >> 7, k = i & 127;
        float v = (j < 21) ? gW3L[k * 21 + j] : 0.f;
        wsplit2(v, smc + SB_W3H, smc + SB_W3L, (uint32_t)(j * 272 + k * 2));
    }
    for (int i = tid; i < TB * 6; i += NTH) {
        int r = i / 6, c = i - 6 * r;
        int g = base + r; if (g > B - 1) g = B - 1;
        sQ[i] = o[g * 18 + c]; sQD[i] = o[g * 18 + 6 + c]; sAA[i] = ain[g * 6 + c];
    }

    float sg1[8][4], sg2[8][4], k1v[6], k2v[6];

    // ---- helpers ----
    auto storeA = [&](int nt, float v0, float v1, float v2, float v3) {
        int ci = nh * 32 + nt * 4 + tig;
        uint32_t h01 = pack2(v0, v1);
        __nv_bfloat162 hh = *reinterpret_cast<__nv_bfloat162*>(&h01);
        AH32[r0 * 68 + ci] = h01;
        AL32[r0 * 68 + ci] = pack2(v0 - __bfloat162float(hh.x), v1 - __bfloat162float(hh.y));
        uint32_t h23 = pack2(v2, v3);
        __nv_bfloat162 hh2 = *reinterpret_cast<__nv_bfloat162*>(&h23);
        AH32[r1 * 68 + ci] = h23;
        AL32[r1 * 68 + ci] = pack2(v2 - __bfloat162float(hh2.x), v3 - __bfloat162float(hh2.y));
    };
    auto bigGemm = [&](float (&acc)[8][4]) {
        #pragma unroll
        for (int nt = 0; nt < 8; nt++)
            acc[nt][0] = acc[nt][1] = acc[nt][2] = acc[nt][3] = 0.f;
        #pragma unroll
        for (int kt = 0; kt < 8; kt++) {
            int ab = r0 * 68 + kt * 8 + tig;
            uint32_t ah0 = AH32[ab], ah1 = AH32[ab + 544], ah2 = AH32[ab + 4], ah3 = AH32[ab + 548];
            uint32_t al0 = AL32[ab], al1 = AL32[ab + 544], al2 = AL32[ab + 4], al3 = AL32[ab + 548];
            #pragma unroll
            for (int nt = 0; nt < 8; nt++) {
                int nb = (nh * 64 + nt * 8 + gid) * 68 + kt * 8 + tig;
                uint32_t bh0 = WH32[nb], bh1 = WH32[nb + 4];
                uint32_t bl0 = WL32[nb], bl1 = WL32[nb + 4];
                MMA(acc[nt], ah0, ah1, ah2, ah3, bh0, bh1);
                MMA(acc[nt], ah0, ah1, ah2, ah3, bl0, bl1);
                MMA(acc[nt], al0, al1, al2, al3, bh0, bh1);
            }
        }
    };
    auto l1Gemm = [&](float (&acc)[8][4]) {
        int ab = r0 * 12 + tig;
        uint32_t ah0 = XH32[ab], ah1 = XH32[ab + 96], ah2 = XH32[ab + 4], ah3 = XH32[ab + 100];
        uint32_t al0 = XL32[ab], al1 = XL32[ab + 96], al2 = XL32[ab + 4], al3 = XL32[ab + 100];
        #pragma unroll
        for (int nt = 0; nt < 8; nt++) {
            acc[nt][0] = acc[nt][1] = acc[nt][2] = acc[nt][3] = 0.f;
            int nb = (nh * 64 + nt * 8 + gid) * 12 + tig;
            uint32_t bh0 = U1H32[nb], bh1 = U1H32[nb + 4];
            uint32_t bl0 = U1L32[nb], bl1 = U1L32[nb + 4];
            MMA(acc[nt], ah0, ah1, ah2, ah3, bh0, bh1);
            MMA(acc[nt], ah0, ah1, ah2, ah3, bl0, bl1);
            MMA(acc[nt], al0, al1, al2, al3, bh0, bh1);
        }
    };
    auto miniGemm = [&]() {           // nh==0 warps only; writes sDYf (raw, no bias)
        float acc[3][4];
        #pragma unroll
        for (int nt = 0; nt < 3; nt++)
            acc[nt][0] = acc[nt][1] = acc[nt][2] = acc[nt][3] = 0.f;
        #pragma unroll
        for (int kt = 0; kt < 8; kt++) {
            int ab = r0 * 68 + kt * 8 + tig;
            uint32_t ah0 = AH32[ab], ah1 = AH32[ab + 544], ah2 = AH32[ab + 4], ah3 = AH32[ab + 548];
            uint32_t al0 = AL32[ab], al1 = AL32[ab + 544], al2 = AL32[ab + 4], al3 = AL32[ab + 548];
            #pragma unroll
            for (int nt = 0; nt < 3; nt++) {
                int nb = (nt * 8 + gid) * 68 + kt * 8 + tig;
                uint32_t bh0 = W3H32[nb], bh1 = W3H32[nb + 4];
                uint32_t bl0 = W3L32[nb], bl1 = W3L32[nb + 4];
                MMA(acc[nt], ah0, ah1, ah2, ah3, bh0, bh1);
                MMA(acc[nt], ah0, ah1, ah2, ah3, bl0, bl1);
                MMA(acc[nt], al0, al1, al2, al3, bh0, bh1);
            }
        }
        #pragma unroll
        for (int nt = 0; nt < 3; nt++) {
            int c = nt * 8 + tig * 2;
            sDYf[r0 * 24 + c] = acc[nt][0]; sDYf[r0 * 24 + c + 1] = acc[nt][1];
            sDYf[r1 * 24 + c] = acc[nt][2]; sDYf[r1 * 24 + c + 1] = acc[nt][3];
        }
    };
    auto buildU1 = [&](int d) {       // tangent input u1(d) -> A (needs W1f = W1L fp32)
        float cq0 = sXF[r0 * 12 + 2 * d], sq0 = sXF[r0 * 12 + 2 * d + 1];
        float cq1 = sXF[r1 * 12 + 2 * d], sq1 = sXF[r1 * 12 + 2 * d + 1];
        #pragma unroll
        for (int nt = 0; nt < 8; nt++) {
            int c = nh * 64 + nt * 8 + tig * 2;
            float2 wa = *(const float2*)&W1f[2 * d * 128 + c];
            float2 wb = *(const float2*)&W1f[(2 * d + 1) * 128 + c];
            storeA(nt,
                sg1[nt][0] * (cq0 * wb.x - sq0 * wa.x),
                sg1[nt][1] * (cq0 * wb.y - sq0 * wa.y),
                sg1[nt][2] * (cq1 * wb.x - sq1 * wa.x),
                sg1[nt][3] * (cq1 * wb.y - sq1 * wa.y));
        }
    };
    auto streamW2T = [&](const float* g) {   // Wt[n][k] = g[k*128+n]
        for (int i = tid; i < 16384; i += NTH) {
            int k = i >> 7, n = i & 127;
            wsplit2(g[i], smc + SB_WH, smc + SB_WL, (uint32_t)(n * 272 + k * 2));
        }
    };
    auto streamW2D = [&](const float* g) {   // Wt[t][n] = g[t*128+n]  (VJP)
        for (int i = tid; i < 16384; i += NTH) {
            int t = i >> 7, n = i & 127;
            wsplit2(g[i], smc + SB_WH, smc + SB_WL, (uint32_t)(t * 272 + n * 2));
        }
    };
    auto streamW1S = [&](const float* g) {   // layer1 B: [c][t], t padded to 16
        for (int i = tid; i < 2048; i += NTH) {
            int c = i >> 4, t = i & 15;
            float v = (t < 12) ? g[t * 128 + c] : 0.f;
            wsplit2(v, smc + SB_W1R, smc + SB_W1R + 6144, (uint32_t)(c * 48 + t * 2));
        }
    };
    auto streamW1F = [&](const float* g) {
        for (int i = tid; i < 1536; i += NTH) W1f[i] = g[i];
    };

    __syncthreads();
    const float ADT = (2.0f / 3.0f) * 0.02f;

    for (int stage = 0; stage < 2; ++stage) {
        // trig features + X tile
        if (tid < TB) {
            int r = tid;
            #pragma unroll
            for (int i = 0; i < 6; i++) {
                float sv, cv; __sincosf(sQ[r * 6 + i], &sv, &cv);
                sXF[r * 12 + 2 * i] = cv; sXF[r * 12 + 2 * i + 1] = sv;
            }
            #pragma unroll
            for (int t = 0; t < 12; t++)
                wsplit2(sXF[r * 12 + t], smc + SB_XH, smc + SB_XL, (uint32_t)(r * 48 + t * 2));
            XH32[r * 12 + 6] = 0; XH32[r * 12 + 7] = 0;
            XL32[r * 12 + 6] = 0; XL32[r * 12 + 7] = 0;
        }
        streamW2T(gW2L);
        streamW1S(gW1L);
        __syncthreads();

        // layer1 L -> h1 (A), sigma1 (regs)
        {
            float acc[8][4]; l1Gemm(acc);
            #pragma unroll
            for (int nt = 0; nt < 8; nt++) {
                int c = nh * 64 + nt * 8 + tig * 2;
                float h0 = softplusf(acc[nt][0] + sB[c]);
                float h1 = softplusf(acc[nt][1] + sB[c + 1]);
                float h2 = softplusf(acc[nt][2] + sB[c]);
                float h3 = softplusf(acc[nt][3] + sB[c + 1]);
                sg1[nt][0] = 1.f - __expf(-h0); sg1[nt][1] = 1.f - __expf(-h1);
                sg1[nt][2] = 1.f - __expf(-h2); sg1[nt][3] = 1.f - __expf(-h3);
                storeA(nt, h0, h1, h2, h3);
            }
        }
        __syncthreads();
        streamW1F(gW1L);                       // W1f := W1L fp32 (split tile done)
        // h2 = softplus(h1 @ W2L^T + b2L)
        {
            float acc[8][4]; bigGemm(acc);
            __syncthreads();
            #pragma unroll
            for (int nt = 0; nt < 8; nt++) {
                int c = nh * 64 + nt * 8 + tig * 2;
                float h0 = softplusf(acc[nt][0] + sB[128 + c]);
                float h1 = softplusf(acc[nt][1] + sB[128 + c + 1]);
                float h2 = softplusf(acc[nt][2] + sB[128 + c]);
                float h3 = softplusf(acc[nt][3] + sB[128 + c + 1]);
                sg2[nt][0] = 1.f - __expf(-h0); sg2[nt][1] = 1.f - __expf(-h1);
                sg2[nt][2] = 1.f - __expf(-h2); sg2[nt][3] = 1.f - __expf(-h3);
                storeA(nt, h0, h1, h2, h3);
            }
        }
        __syncthreads();
        if (nh == 0) miniGemm();               // y -> sDY
        __syncthreads();

        float wv[6], Aacc[6], svec[6], Cacc[6];
        if (tid < TB) {                        // physics init
            int r = tid;
            const float* dy = sDYf + r * 24;
            float Lrl[21], Msl[21];
            #pragma unroll
            for (int t = 0; t < 21; t++) { Lrl[t] = dy[t] + sB[640 + t]; sLr[r * 21 + t] = Lrl[t]; }
            #pragma unroll
            for (int i = 0; i < 6; i++)
                #pragma unroll
                for (int j = 0; j < 6; j++) if (j <= i) {
                    float s2 = 0.f;
                    #pragma unroll
                    for (int k = 0; k < 6; k++) if (k <= j) s2 += Lrl[RO[i] + k] * Lrl[RO[j] + k];
                    if (i == j) s2 += 1e-6f;
                    Msl[RO[i] + j] = s2; sMs[r * 21 + RO[i] + j] = s2;
                }
            #pragma unroll
            for (int i = 0; i < 6; i++) {
                float s2 = 0.f;
                #pragma unroll
                for (int j = 0; j < 6; j++) s2 += MML(i, j) * sQD[r * 6 + j];
                wv[i] = s2; Aacc[i] = 0.f; svec[i] = 0.f;
            }
        }
        buildU1(0);
        __syncthreads();

        // ---- 6 tangent directions ----
        for (int d = 0; d < 6; ++d) {
            {
                float acc[8][4]; bigGemm(acc);  // u1 @ W2L^T
                __syncthreads();
                #pragma unroll
                for (int nt = 0; nt < 8; nt++)  // u2 = sigma2 * acc
                    storeA(nt, acc[nt][0] * sg2[nt][0], acc[nt][1] * sg2[nt][1],
                               acc[nt][2] * sg2[nt][2], acc[nt][3] * sg2[nt][3]);
            }
            __syncthreads();
            if (nh == 0) miniGemm();            // dy(d) -> sDY
            if (d == 5) streamW1S(gW1V);        // W1R := W1V split (W1Lf dead)
            __syncthreads();
            if (tid < TB) {                     // physics(d)
                int r = tid;
                const float* dy = sDYf + r * 24;
                const float* Lp = sLr + r * 21;
                float qdr[6];
                #pragma unroll
                for (int j = 0; j < 6; j++) qdr[j] = sQD[r * 6 + j];
                float D6[6][6];
                #pragma unroll
                for (int i = 0; i < 6; i++)
                    #pragma unroll
                    for (int j = 0; j < 6; j++) if (j <= i) {
                        float s2 = 0.f;
                        #pragma unroll
                        for (int k = 0; k < 6; k++) if (k <= j)
                            s2 += dy[RO[i] + k] * Lp[RO[j] + k] + Lp[RO[i] + k] * dy[RO[j] + k];
                        D6[i][j] = s2; D6[j][i] = s2;
                    }
                float qdd = qdr[d], cdot = 0.f;
                #pragma unroll
                for (int i = 0; i < 6; i++) {
                    float v1 = 0.f, v2 = 0.f;
                    #pragma unroll
                    for (int j = 0; j < 6; j++) { v1 += D6[i][j] * wv[j]; v2 += D6[i][j] * qdr[j]; }
                    Aacc[i] += qdd * v1; svec[i] += qdd * v2; cdot += qdr[i] * v1;
                }
                Cacc[d] = cdot;
            }
            if (d < 5) {
                buildU1(d + 1);
            } else {                            // layer1 V -> h1V (A), sigma1V (regs)
                float acc[8][4]; l1Gemm(acc);
                #pragma unroll
                for (int nt = 0; nt < 8; nt++) {
                    int c = nh * 64 + nt * 8 + tig * 2;
                    float h0 = softplusf(acc[nt][0] + sB[256 + c]);
                    float h1 = softplusf(acc[nt][1] + sB[256 + c + 1]);
                    float h2 = softplusf(acc[nt][2] + sB[256 + c]);
                    float h3 = softplusf(acc[nt][3] + sB[256 + c + 1]);
                    sg1[nt][0] = 1.f - __expf(-h0); sg1[nt][1] = 1.f - __expf(-h1);
                    sg1[nt][2] = 1.f - __expf(-h2); sg1[nt][3] = 1.f - __expf(-h3);
                    storeA(nt, h0, h1, h2, h3);
                }
            }
            __syncthreads();
        }

        streamW2T(gW2V);                        // W := W2V^T
        streamW1F(gW1V);                        // W1f := W1V fp32
        __syncthreads();
        // h2V ; u2g = sig(h2V)*W3V
        {
            float acc[8][4]; bigGemm(acc);
            __syncthreads();
            #pragma unroll
            for (int nt = 0; nt < 8; nt++) {
                int c = nh * 64 + nt * 8 + tig * 2;
                float h0 = softplusf(acc[nt][0] + sB[384 + c]);
                float h1 = softplusf(acc[nt][1] + sB[384 + c + 1]);
                float h2 = softplusf(acc[nt][2] + sB[384 + c]);
                float h3 = softplusf(acc[nt][3] + sB[384 + c + 1]);
                storeA(nt, (1.f - __expf(-h0)) * sB[512 + c],
                           (1.f - __expf(-h1)) * sB[512 + c + 1],
                           (1.f - __expf(-h2)) * sB[512 + c],
                           (1.f - __expf(-h3)) * sB[512 + c + 1]);
            }
        }
        __syncthreads();
        streamW2D(gW2V);                        // W := W2V direct (VJP)
        __syncthreads();
        // VJP GEMM + gx projection
        {
            float acc[8][4]; bigGemm(acc);
            float gx0[12], gx1[12];
            #pragma unroll
            for (int t = 0; t < 12; t++) { gx0[t] = 0.f; gx1[t] = 0.f; }
            #pragma unroll
            for (int nt = 0; nt < 8; nt++) {
                int c = nh * 64 + nt * 8 + tig * 2;
                float u0 = acc[nt][0] * sg1[nt][0], u1 = acc[nt][1] * sg1[nt][1];
                float u2 = acc[nt][2] * sg1[nt][2], u3 = acc[nt][3] * sg1[nt][3];
                #pragma unroll
                for (int t = 0; t < 12; t++) {
                    float2 wv2 = *(const float2*)&W1f[t * 128 + c];
                    gx0[t] += u0 * wv2.x + u1 * wv2.y;
                    gx1[t] += u2 * wv2.x + u3 * wv2.y;
                }
            }
            #pragma unroll
            for (int t = 0; t < 12; t++) {
                gx0[t] += __shfl_xor_sync(0xFFFFFFFF, gx0[t], 1);
                gx0[t] += __shfl_xor_sync(0xFFFFFFFF, gx0[t], 2);
                gx1[t] += __shfl_xor_sync(0xFFFFFFFF, gx1[t], 1);
                gx1[t] += __shfl_xor_sync(0xFFFFFFFF, gx1[t], 2);
            }
            if (tig == 0) {
                #pragma unroll
                for (int t = 0; t < 12; t++) {
                    sGX[r0 * 24 + nh * 12 + t] = gx0[t];
                    sGX[r1 * 24 + nh * 12 + t] = gx1[t];
                }
            }
        }
        __syncthreads();
        // final per-row: cvec, rhs, solves, state update
        if (tid < TB) {
            int r = tid;
            float Msl[21];
            #pragma unroll
            for (int t = 0; t < 21; t++) Msl[t] = sMs[r * 21 + t];
            float cv[6];
            #pragma unroll
            for (int i = 0; i < 6; i++) {
                float ms = 0.f;
                #pragma unroll
                for (int j = 0; j < 6; j++) ms += MML(i, j) * svec[j];
                cv[i] = Aacc[i] + ms - Cacc[i];
            }
            float rhs[6];
            #pragma unroll
            for (int i = 0; i < 6; i++) {
                float g0 = sGX[r * 24 + 2 * i]     + sGX[r * 24 + 12 + 2 * i];
                float g1 = sGX[r * 24 + 2 * i + 1] + sGX[r * 24 + 12 + 2 * i + 1];
                float dv = -sXF[r * 12 + 2 * i + 1] * g0 + sXF[r * 12 + 2 * i] * g1;
                rhs[i] = sAA[r * 6 + i] - cv[i] - dv;
            }
            float yv[6], zv[6];
            #pragma unroll
            for (int i = 0; i < 6; i++) {
                float s2 = rhs[i];
                #pragma unroll
                for (int j = 0; j < 6; j++) if (j < i) s2 -= Msl[RO[i] + j] * yv[j];
                yv[i] = s2 / Msl[RO[i] + i];
            }
            #pragma unroll
            for (int ii = 5; ii >= 0; ii--) {
                float s2 = yv[ii];
                #pragma unroll
                for (int j = 0; j < 6; j++) if (j > ii) s2 -= Msl[RO[j] + ii] * zv[j];
                zv[ii] = s2 / Msl[RO[ii] + ii];
            }
            if (stage == 0) {
                #pragma unroll
                for (int i = 0; i < 6; i++) {
                    k1v[i] = zv[i];
                    float qdi = sQD[r * 6 + i];
                    sQ[r * 6 + i] += ADT * qdi;
                    sQD[r * 6 + i] = qdi + ADT * zv[i];
                }
            } else {
                #pragma unroll
                for (int i = 0; i < 6; i++) k2v[i] = zv[i];
            }
        }
        __syncthreads();
    }

    // ---- output ----
    if (tid < TB && base + tid < B) {
        int g = base + tid, r = tid;
        #pragma unroll
        for (int i = 0; i < 6; i++)
            outp[g * 18 + i] = o[g * 18 + i]
                + 0.02f * (0.25f * o[g * 18 + 6 + i] + 0.75f * sQD[r * 6 + i]);
        #pragma unroll
        for (int i = 0; i < 6; i++)
            outp[g * 18 + 6 + i] = o[g * 18 + 6 + i]
                + 0.02f * (0.25f * k1v[i] + 0.75f * k2v[i]);
        #pragma unroll
        for (int i = 0; i < 6; i++)
            outp[g * 18 + 12 + i] = o[g * 18 + 12 + i];
    }
}

extern "C" void kernel_launch(void* const* d_in, const int* in_sizes, int n_in,
                              void* d_out, int out_size) {
    const float* o   = (const float*)d_in[0];
    const float* a   = (const float*)d_in[1];
    const float* W1L = (const float*)d_in[2];
    const float* b1L = (const float*)d_in[3];
    const float* W2L = (const float*)d_in[4];
    const float* b2L = (const float*)d_in[5];
    const float* W3L = (const float*)d_in[6];
    const float* b3L = (const float*)d_in[7];
    const float* W1V = (const float*)d_in[8];
    const float* b1V = (const float*)d_in[9];
    const float* W2V = (const float*)d_in[10];
    const float* b2V = (const float*)d_in[11];
    const float* W3V = (const float*)d_in[12];
    float* outp = (float*)d_out;

    int B = in_sizes[0] / 18;
    int grid = (B + TB - 1) / TB;
    cudaFuncSetAttribute(lnn_mma,
                         cudaFuncAttributeMaxDynamicSharedMemorySize, SB_END);
    lnn_mma<<<grid, NTH, SB_END>>>(o, a, W1L, b1L, W2L, b2L, W3L, b3L,
                                   W1V, b1V, W2V, b2V, W3V, outp, B);
}

// round 12
// speedup vs baseline: 2.1758x; 1.0905x over previous
#include <cuda_runtime.h>
#include <cuda_bf16.h>
#include <cstdint>
#include <math.h>

#define NTH 512
#define TB  64

// ---- smem byte offsets ----
#define SB_AH  0
#define SB_AL  17408
#define SB_WH  34816
#define SB_WL  69632
#define SB_W3H 104448
#define SB_W3L 110976
#define SB_W1R 117504
#define SB_XH  129792
#define SB_XL  132864
#define SB_DY  135936
#define SB_GX  142080   // 64 x 48 f32 = 12288
#define SB_XF  154368
#define SB_Q   157440
#define SB_QD  158976
#define SB_AA  160512
#define SB_LR  162048
#define SB_MS  167424
#define SB_B   172800
#define SB_END 175456

#define MMA(acc,a0,a1,a2,a3,b0,b1) \
  asm volatile("mma.sync.aligned.m16n8k16.row.col.f32.bf16.bf16.f32 " \
    "{%0,%1,%2,%3},{%4,%5,%6,%7},{%8,%9},{%0,%1,%2,%3};" \
    : "+f"(acc[0]),"+f"(acc[1]),"+f"(acc[2]),"+f"(acc[3]) \
    : "r"(a0),"r"(a1),"r"(a2),"r"(a3),"r"(b0),"r"(b1))

static __device__ __forceinline__ float softplusf(float z) {
    return fmaxf(z, 0.0f) + __logf(1.0f + __expf(-fabsf(z)));
}
static __device__ __forceinline__ uint32_t pack2(float a, float b) {
    __nv_bfloat162 t = __floats2bfloat162_rn(a, b);
    return *reinterpret_cast<uint32_t*>(&t);
}
static __device__ __forceinline__ void wsplit2(float v, char* hi, char* lo, uint32_t off) {
    __nv_bfloat16 h = __float2bfloat16(v);
    *(__nv_bfloat16*)(hi + off) = h;
    *(__nv_bfloat16*)(lo + off) = __float2bfloat16(v - __bfloat162float(h));
}

extern "C" __global__ void __launch_bounds__(NTH, 1)
lnn_mma(const float* __restrict__ o,    const float* __restrict__ ain,
        const float* __restrict__ gW1L, const float* __restrict__ gb1L,
        const float* __restrict__ gW2L, const float* __restrict__ gb2L,
        const float* __restrict__ gW3L, const float* __restrict__ gb3L,
        const float* __restrict__ gW1V, const float* __restrict__ gb1V,
        const float* __restrict__ gW2V, const float* __restrict__ gb2V,
        const float* __restrict__ gW3V,
        float* __restrict__ outp, int B)
{
    extern __shared__ char smc[];
    uint32_t* AH32  = (uint32_t*)(smc + SB_AH);
    uint32_t* AL32  = (uint32_t*)(smc + SB_AL);
    uint32_t* WH32  = (uint32_t*)(smc + SB_WH);
    uint32_t* WL32  = (uint32_t*)(smc + SB_WL);
    uint32_t* W3H32 = (uint32_t*)(smc + SB_W3H);
    uint32_t* W3L32 = (uint32_t*)(smc + SB_W3L);
    uint32_t* U1H32 = (uint32_t*)(smc + SB_W1R);
    uint32_t* U1L32 = (uint32_t*)(smc + SB_W1R + 6144);
    uint32_t* XH32  = (uint32_t*)(smc + SB_XH);
    uint32_t* XL32  = (uint32_t*)(smc + SB_XL);
    float* W1f  = (float*)(smc + SB_W1R);
    float* sDYf = (float*)(smc + SB_DY);
    float* sGX  = (float*)(smc + SB_GX);
    float* sXF  = (float*)(smc + SB_XF);
    float* sQ   = (float*)(smc + SB_Q);
    float* sQD  = (float*)(smc + SB_QD);
    float* sAA  = (float*)(smc + SB_AA);
    float* sLr  = (float*)(smc + SB_LR);
    float* sMs  = (float*)(smc + SB_MS);
    float* sB   = (float*)(smc + SB_B);

    const int tid = threadIdx.x, w = tid >> 5, lane = tid & 31;
    const int gid = lane >> 2, tig = lane & 3;
    const int mt = w & 3, nq = w >> 2;          // 4 M-tiles x 4 N-quarters
    const int r0 = mt * 16 + gid, r1 = r0 + 8;
    const int base = blockIdx.x * TB;
    const int RO[6] = {0, 1, 3, 6, 10, 15};
    #define MML(i,j) ((i)>=(j) ? Msl[RO[i]+(j)] : Msl[RO[j]+(i)])

    // persistent loads
    for (int i = tid; i < 128; i += NTH) {
        sB[i] = gb1L[i]; sB[128 + i] = gb2L[i];
        sB[256 + i] = gb1V[i]; sB[384 + i] = gb2V[i]; sB[512 + i] = gW3V[i];
    }
    if (tid < 24) sB[640 + tid] = tid < 21 ? gb3L[tid] : 0.f;
    for (int i = tid; i < 3072; i += NTH) {     // W3^T tile (24 x 128)
        int j = i >> 7, k = i & 127;
        float v = (j < 21) ? gW3L[k * 21 + j] : 0.f;
        wsplit2(v, smc + SB_W3H, smc + SB_W3L, (uint32_t)(j * 272 + k * 2));
    }
    for (int i = tid; i < TB * 6; i += NTH) {
        int r = i / 6, c = i - 6 * r;
        int g = base + r; if (g > B - 1) g = B - 1;
        sQ[i] = o[g * 18 + c]; sQD[i] = o[g * 18 + 6 + c]; sAA[i] = ain[g * 6 + c];
    }

    float sg1[4][4], sg2[4][4], k1v[6], k2v[6];

    // ---- helpers ----
    auto storeA = [&](int nt, float v0, float v1, float v2, float v3) {
        int ci = nq * 16 + nt * 4 + tig;
        uint32_t h01 = pack2(v0, v1);
        __nv_bfloat162 hh = *reinterpret_cast<__nv_bfloat162*>(&h01);
        AH32[r0 * 68 + ci] = h01;
        AL32[r0 * 68 + ci] = pack2(v0 - __bfloat162float(hh.x), v1 - __bfloat162float(hh.y));
        uint32_t h23 = pack2(v2, v3);
        __nv_bfloat162 hh2 = *reinterpret_cast<__nv_bfloat162*>(&h23);
        AH32[r1 * 68 + ci] = h23;
        AL32[r1 * 68 + ci] = pack2(v2 - __bfloat162float(hh2.x), v3 - __bfloat162float(hh2.y));
    };
    auto bigGemm = [&](float (&acc)[4][4]) {
        #pragma unroll
        for (int nt = 0; nt < 4; nt++)
            acc[nt][0] = acc[nt][1] = acc[nt][2] = acc[nt][3] = 0.f;
        #pragma unroll
        for (int kt = 0; kt < 8; kt++) {
            int ab = r0 * 68 + kt * 8 + tig;
            uint32_t ah0 = AH32[ab], ah1 = AH32[ab + 544], ah2 = AH32[ab + 4], ah3 = AH32[ab + 548];
            uint32_t al0 = AL32[ab], al1 = AL32[ab + 544], al2 = AL32[ab + 4], al3 = AL32[ab + 548];
            uint32_t bh0[4], bh1[4], bl0[4], bl1[4];
            #pragma unroll
            for (int nt = 0; nt < 4; nt++) {
                int nb = (nq * 32 + nt * 8 + gid) * 68 + kt * 8 + tig;
                bh0[nt] = WH32[nb]; bh1[nt] = WH32[nb + 4];
                bl0[nt] = WL32[nb]; bl1[nt] = WL32[nb + 4];
            }
            #pragma unroll
            for (int nt = 0; nt < 4; nt++) MMA(acc[nt], ah0, ah1, ah2, ah3, bh0[nt], bh1[nt]);
            #pragma unroll
            for (int nt = 0; nt < 4; nt++) MMA(acc[nt], ah0, ah1, ah2, ah3, bl0[nt], bl1[nt]);
            #pragma unroll
            for (int nt = 0; nt < 4; nt++) MMA(acc[nt], al0, al1, al2, al3, bh0[nt], bh1[nt]);
        }
    };
    auto l1Gemm = [&](float (&acc)[4][4]) {
        int ab = r0 * 12 + tig;
        uint32_t ah0 = XH32[ab], ah1 = XH32[ab + 96], ah2 = XH32[ab + 4], ah3 = XH32[ab + 100];
        uint32_t al0 = XL32[ab], al1 = XL32[ab + 96], al2 = XL32[ab + 4], al3 = XL32[ab + 100];
        uint32_t bh0[4], bh1[4], bl0[4], bl1[4];
        #pragma unroll
        for (int nt = 0; nt < 4; nt++) {
            acc[nt][0] = acc[nt][1] = acc[nt][2] = acc[nt][3] = 0.f;
            int nb = (nq * 32 + nt * 8 + gid) * 12 + tig;
            bh0[nt] = U1H32[nb]; bh1[nt] = U1H32[nb + 4];
            bl0[nt] = U1L32[nb]; bl1[nt] = U1L32[nb + 4];
        }
        #pragma unroll
        for (int nt = 0; nt < 4; nt++) MMA(acc[nt], ah0, ah1, ah2, ah3, bh0[nt], bh1[nt]);
        #pragma unroll
        for (int nt = 0; nt < 4; nt++) MMA(acc[nt], ah0, ah1, ah2, ah3, bl0[nt], bl1[nt]);
        #pragma unroll
        for (int nt = 0; nt < 4; nt++) MMA(acc[nt], al0, al1, al2, al3, bh0[nt], bh1[nt]);
    };
    auto miniGemm = [&]() {           // nq==0 warps only; writes sDYf (raw, no bias)
        float acc[3][4];
        #pragma unroll
        for (int nt = 0; nt < 3; nt++)
            acc[nt][0] = acc[nt][1] = acc[nt][2] = acc[nt][3] = 0.f;
        #pragma unroll
        for (int kt = 0; kt < 8; kt++) {
            int ab = r0 * 68 + kt * 8 + tig;
            uint32_t ah0 = AH32[ab], ah1 = AH32[ab + 544], ah2 = AH32[ab + 4], ah3 = AH32[ab + 548];
            uint32_t al0 = AL32[ab], al1 = AL32[ab + 544], al2 = AL32[ab + 4], al3 = AL32[ab + 548];
            uint32_t bh0[3], bh1[3], bl0[3], bl1[3];
            #pragma unroll
            for (int nt = 0; nt < 3; nt++) {
                int nb = (nt * 8 + gid) * 68 + kt * 8 + tig;
                bh0[nt] = W3H32[nb]; bh1[nt] = W3H32[nb + 4];
                bl0[nt] = W3L32[nb]; bl1[nt] = W3L32[nb + 4];
            }
            #pragma unroll
            for (int nt = 0; nt < 3; nt++) MMA(acc[nt], ah0, ah1, ah2, ah3, bh0[nt], bh1[nt]);
            #pragma unroll
            for (int nt = 0; nt < 3; nt++) MMA(acc[nt], ah0, ah1, ah2, ah3, bl0[nt], bl1[nt]);
            #pragma unroll
            for (int nt = 0; nt < 3; nt++) MMA(acc[nt], al0, al1, al2, al3, bh0[nt], bh1[nt]);
        }
        #pragma unroll
        for (int nt = 0; nt < 3; nt++) {
            int c = nt * 8 + tig * 2;
            sDYf[r0 * 24 + c] = acc[nt][0]; sDYf[r0 * 24 + c + 1] = acc[nt][1];
            sDYf[r1 * 24 + c] = acc[nt][2]; sDYf[r1 * 24 + c + 1] = acc[nt][3];
        }
    };
    auto buildU1 = [&](int d) {       // tangent input u1(d) -> A (W1f = W1L fp32)
        float cq0 = sXF[r0 * 12 + 2 * d], sq0 = sXF[r0 * 12 + 2 * d + 1];
        float cq1 = sXF[r1 * 12 + 2 * d], sq1 = sXF[r1 * 12 + 2 * d + 1];
        #pragma unroll
        for (int nt = 0; nt < 4; nt++) {
            int c = nq * 32 + nt * 8 + tig * 2;
            float2 wa = *(const float2*)&W1f[2 * d * 128 + c];
            float2 wb = *(const float2*)&W1f[(2 * d + 1) * 128 + c];
            storeA(nt,
                sg1[nt][0] * (cq0 * wb.x - sq0 * wa.x),
                sg1[nt][1] * (cq0 * wb.y - sq0 * wa.y),
                sg1[nt][2] * (cq1 * wb.x - sq1 * wa.x),
                sg1[nt][3] * (cq1 * wb.y - sq1 * wa.y));
        }
    };
    auto streamW2T = [&](const float* g) {   // Wt[n][k] = g[k*128+n]
        for (int i = tid; i < 16384; i += NTH) {
            int k = i >> 7, n = i & 127;
            wsplit2(g[i], smc + SB_WH, smc + SB_WL, (uint32_t)(n * 272 + k * 2));
        }
    };
    auto streamW2D = [&](const float* g) {   // Wt[t][n] = g[t*128+n]  (VJP)
        for (int i = tid; i < 16384; i += NTH) {
            int t = i >> 7, n = i & 127;
            wsplit2(g[i], smc + SB_WH, smc + SB_WL, (uint32_t)(t * 272 + n * 2));
        }
    };
    auto streamW1S = [&](const float* g) {   // layer1 B: [c][t], t padded to 16
        for (int i = tid; i < 2048; i += NTH) {
            int c = i >> 4, t = i & 15;
            float v = (t < 12) ? g[t * 128 + c] : 0.f;
            wsplit2(v, smc + SB_W1R, smc + SB_W1R + 6144, (uint32_t)(c * 48 + t * 2));
        }
    };
    auto streamW1F = [&](const float* g) {
        for (int i = tid; i < 1536; i += NTH) W1f[i] = g[i];
    };

    __syncthreads();
    const float ADT = (2.0f / 3.0f) * 0.02f;

    for (int stage = 0; stage < 2; ++stage) {
        if (tid < TB) {                  // trig features + X tile
            int r = tid;
            #pragma unroll
            for (int i = 0; i < 6; i++) {
                float sv, cv; __sincosf(sQ[r * 6 + i], &sv, &cv);
                sXF[r * 12 + 2 * i] = cv; sXF[r * 12 + 2 * i + 1] = sv;
            }
            #pragma unroll
            for (int t = 0; t < 12; t++)
                wsplit2(sXF[r * 12 + t], smc + SB_XH, smc + SB_XL, (uint32_t)(r * 48 + t * 2));
            XH32[r * 12 + 6] = 0; XH32[r * 12 + 7] = 0;
            XL32[r * 12 + 6] = 0; XL32[r * 12 + 7] = 0;
        }
        streamW2T(gW2L);
        streamW1S(gW1L);
        __syncthreads();

        // layer1 L -> h1 (A), sigma1 (regs)
        {
            float acc[4][4]; l1Gemm(acc);
            #pragma unroll
            for (int nt = 0; nt < 4; nt++) {
                int c = nq * 32 + nt * 8 + tig * 2;
                float h0 = softplusf(acc[nt][0] + sB[c]);
                float h1 = softplusf(acc[nt][1] + sB[c + 1]);
                float h2 = softplusf(acc[nt][2] + sB[c]);
                float h3 = softplusf(acc[nt][3] + sB[c + 1]);
                sg1[nt][0] = 1.f - __expf(-h0); sg1[nt][1] = 1.f - __expf(-h1);
                sg1[nt][2] = 1.f - __expf(-h2); sg1[nt][3] = 1.f - __expf(-h3);
                storeA(nt, h0, h1, h2, h3);
            }
        }
        __syncthreads();
        streamW1F(gW1L);                 // W1f := W1L fp32 (split tile dead)
        // h2 = softplus(h1 @ W2L^T + b2L)
        {
            float acc[4][4]; bigGemm(acc);
            __syncthreads();
            #pragma unroll
            for (int nt = 0; nt < 4; nt++) {
                int c = nq * 32 + nt * 8 + tig * 2;
                float h0 = softplusf(acc[nt][0] + sB[128 + c]);
                float h1 = softplusf(acc[nt][1] + sB[128 + c + 1]);
                float h2 = softplusf(acc[nt][2] + sB[128 + c]);
                float h3 = softplusf(acc[nt][3] + sB[128 + c + 1]);
                sg2[nt][0] = 1.f - __expf(-h0); sg2[nt][1] = 1.f - __expf(-h1);
                sg2[nt][2] = 1.f - __expf(-h2); sg2[nt][3] = 1.f - __expf(-h3);
                storeA(nt, h0, h1, h2, h3);
            }
        }
        __syncthreads();
        if (nq == 0) miniGemm();         // y -> sDY
        __syncthreads();

        float wv[6], Aacc[6], svec[6], Cacc[6];
        if (tid < TB) {                  // physics init
            int r = tid;
            const float* dy = sDYf + r * 24;
            float Lrl[21], Msl[21];
            #pragma unroll
            for (int t = 0; t < 21; t++) { Lrl[t] = dy[t] + sB[640 + t]; sLr[r * 21 + t] = Lrl[t]; }
            #pragma unroll
            for (int i = 0; i < 6; i++)
                #pragma unroll
                for (int j = 0; j < 6; j++) if (j <= i) {
                    float s2 = 0.f;
                    #pragma unroll
                    for (int k = 0; k < 6; k++) if (k <= j) s2 += Lrl[RO[i] + k] * Lrl[RO[j] + k];
                    if (i == j) s2 += 1e-6f;
                    Msl[RO[i] + j] = s2; sMs[r * 21 + RO[i] + j] = s2;
                }
            #pragma unroll
            for (int i = 0; i < 6; i++) {
                float s2 = 0.f;
                #pragma unroll
                for (int j = 0; j < 6; j++) s2 += MML(i, j) * sQD[r * 6 + j];
                wv[i] = s2; Aacc[i] = 0.f; svec[i] = 0.f;
            }
        }
        buildU1(0);
        __syncthreads();

        // ---- 6 tangent directions ----
        for (int d = 0; d < 6; ++d) {
            {
                float acc[4][4]; bigGemm(acc);   // u1 @ W2L^T
                __syncthreads();
                #pragma unroll
                for (int nt = 0; nt < 4; nt++)   // u2 = sigma2 * acc
                    storeA(nt, acc[nt][0] * sg2[nt][0], acc[nt][1] * sg2[nt][1],
                               acc[nt][2] * sg2[nt][2], acc[nt][3] * sg2[nt][3]);
            }
            __syncthreads();
            if (nq == 0) miniGemm();             // dy(d) -> sDY
            if (d == 5) streamW1S(gW1V);         // W1R := W1V split
            __syncthreads();
            if (tid < TB) {                      // physics(d)
                int r = tid;
                const float* dy = sDYf + r * 24;
                const float* Lp = sLr + r * 21;
                float qdr[6];
                #pragma unroll
                for (int j = 0; j < 6; j++) qdr[j] = sQD[r * 6 + j];
                float D6[6][6];
                #pragma unroll
                for (int i = 0; i < 6; i++)
                    #pragma unroll
                    for (int j = 0; j < 6; j++) if (j <= i) {
                        float s2 = 0.f;
                        #pragma unroll
                        for (int k = 0; k < 6; k++) if (k <= j)
                            s2 += dy[RO[i] + k] * Lp[RO[j] + k] + Lp[RO[i] + k] * dy[RO[j] + k];
                        D6[i][j] = s2; D6[j][i] = s2;
                    }
                float qdd = qdr[d], cdot = 0.f;
                #pragma unroll
                for (int i = 0; i < 6; i++) {
                    float v1 = 0.f, v2 = 0.f;
                    #pragma unroll
                    for (int j = 0; j < 6; j++) { v1 += D6[i][j] * wv[j]; v2 += D6[i][j] * qdr[j]; }
                    Aacc[i] += qdd * v1; svec[i] += qdd * v2; cdot += qdr[i] * v1;
                }
                Cacc[d] = cdot;
            }
            if (d < 5) {
                buildU1(d + 1);
            } else {                             // layer1 V -> h1V (A), sigma1V
                float acc[4][4]; l1Gemm(acc);
                #pragma unroll
                for (int nt = 0; nt < 4; nt++) {
                    int c = nq * 32 + nt * 8 + tig * 2;
                    float h0 = softplusf(acc[nt][0] + sB[256 + c]);
                    float h1 = softplusf(acc[nt][1] + sB[256 + c + 1]);
                    float h2 = softplusf(acc[nt][2] + sB[256 + c]);
                    float h3 = softplusf(acc[nt][3] + sB[256 + c + 1]);
                    sg1[nt][0] = 1.f - __expf(-h0); sg1[nt][1] = 1.f - __expf(-h1);
                    sg1[nt][2] = 1.f - __expf(-h2); sg1[nt][3] = 1.f - __expf(-h3);
                    storeA(nt, h0, h1, h2, h3);
                }
            }
            __syncthreads();
        }

        streamW2T(gW2V);                         // W := W2V^T
        streamW1F(gW1V);                         // W1f := W1V fp32
        __syncthreads();
        // h2V ; u2g = sig(h2V)*W3V
        {
            float acc[4][4]; bigGemm(acc);
            __syncthreads();
            #pragma unroll
            for (int nt = 0; nt < 4; nt++) {
                int c = nq * 32 + nt * 8 + tig * 2;
                float h0 = softplusf(acc[nt][0] + sB[384 + c]);
                float h1 = softplusf(acc[nt][1] + sB[384 + c + 1]);
                float h2 = softplusf(acc[nt][2] + sB[384 + c]);
                float h3 = softplusf(acc[nt][3] + sB[384 + c + 1]);
                storeA(nt, (1.f - __expf(-h0)) * sB[512 + c],
                           (1.f - __expf(-h1)) * sB[512 + c + 1],
                           (1.f - __expf(-h2)) * sB[512 + c],
                           (1.f - __expf(-h3)) * sB[512 + c + 1]);
            }
        }
        __syncthreads();
        streamW2D(gW2V);                         // W := W2V direct (VJP)
        __syncthreads();
        // VJP GEMM + gx projection
        {
            float acc[4][4]; bigGemm(acc);
            float gx0[12], gx1[12];
            #pragma unroll
            for (int t = 0; t < 12; t++) { gx0[t] = 0.f; gx1[t] = 0.f; }
            #pragma unroll
            for (int nt = 0; nt < 4; nt++) {
                int c = nq * 32 + nt * 8 + tig * 2;
                float u0 = acc[nt][0] * sg1[nt][0], u1 = acc[nt][1] * sg1[nt][1];
                float u2 = acc[nt][2] * sg1[nt][2], u3 = acc[nt][3] * sg1[nt][3];
                #pragma unroll
                for (int t = 0; t < 12; t++) {
                    float2 wv2 = *(const float2*)&W1f[t * 128 + c];
                    gx0[t] += u0 * wv2.x + u1 * wv2.y;
                    gx1[t] += u2 * wv2.x + u3 * wv2.y;
                }
            }
            #pragma unroll
            for (int t = 0; t < 12; t++) {
                gx0[t] += __shfl_xor_sync(0xFFFFFFFF, gx0[t], 1);
                gx0[t] += __shfl_xor_sync(0xFFFFFFFF, gx0[t], 2);
                gx1[t] += __shfl_xor_sync(0xFFFFFFFF, gx1[t], 1);
                gx1[t] += __shfl_xor_sync(0xFFFFFFFF, gx1[t], 2);
            }
            if (tig == 0) {
                #pragma unroll
                for (int t = 0; t < 12; t++) {
                    sGX[r0 * 48 + nq * 12 + t] = gx0[t];
                    sGX[r1 * 48 + nq * 12 + t] = gx1[t];
                }
            }
        }
        __syncthreads();
        // final per-row: cvec, rhs, solves, state update
        if (tid < TB) {
            int r = tid;
            float Msl[21];
            #pragma unroll
            for (int t = 0; t < 21; t++) Msl[t] = sMs[r * 21 + t];
            float cv[6];
            #pragma unroll
            for (int i = 0; i < 6; i++) {
                float ms = 0.f;
                #pragma unroll
                for (int j = 0; j < 6; j++) ms += MML(i, j) * svec[j];
                cv[i] = Aacc[i] + ms - Cacc[i];
            }
            float rhs[6];
            #pragma unroll
            for (int i = 0; i < 6; i++) {
                float g0 = sGX[r * 48 + 2 * i]      + sGX[r * 48 + 12 + 2 * i]
                         + sGX[r * 48 + 24 + 2 * i] + sGX[r * 48 + 36 + 2 * i];
                float g1 = sGX[r * 48 + 2 * i + 1]      + sGX[r * 48 + 12 + 2 * i + 1]
                         + sGX[r * 48 + 24 + 2 * i + 1] + sGX[r * 48 + 36 + 2 * i + 1];
                float dv = -sXF[r * 12 + 2 * i + 1] * g0 + sXF[r * 12 + 2 * i] * g1;
                rhs[i] = sAA[r * 6 + i] - cv[i] - dv;
            }
            float yv[6], zv[6];
            #pragma unroll
            for (int i = 0; i < 6; i++) {
                float s2 = rhs[i];
                #pragma unroll
                for (int j = 0; j < 6; j++) if (j < i) s2 -= Msl[RO[i] + j] * yv[j];
                yv[i] = s2 / Msl[RO[i] + i];
            }
            #pragma unroll
            for (int ii = 5; ii >= 0; ii--) {
                float s2 = yv[ii];
                #pragma unroll
                for (int j = 0; j < 6; j++) if (j > ii) s2 -= Msl[RO[j] + ii] * zv[j];
                zv[ii] = s2 / Msl[RO[ii] + ii];
            }
            if (stage == 0) {
                #pragma unroll
                for (int i = 0; i < 6; i++) {
                    k1v[i] = zv[i];
                    float qdi = sQD[r * 6 + i];
                    sQ[r * 6 + i] += ADT * qdi;
                    sQD[r * 6 + i] = qdi + ADT * zv[i];
                }
            } else {
                #pragma unroll
                for (int i = 0; i < 6; i++) k2v[i] = zv[i];
            }
        }
        __syncthreads();
    }

    // ---- output ----
    if (tid < TB && base + tid < B) {
        int g = base + tid, r = tid;
        #pragma unroll
        for (int i = 0; i < 6; i++)
            outp[g * 18 + i] = o[g * 18 + i]
                + 0.02f * (0.25f * o[g * 18 + 6 + i] + 0.75f * sQD[r * 6 + i]);
        #pragma unroll
        for (int i = 0; i < 6; i++)
            outp[g * 18 + 6 + i] = o[g * 18 + 6 + i]
                + 0.02f * (0.25f * k1v[i] + 0.75f * k2v[i]);
        #pragma unroll
        for (int i = 0; i < 6; i++)
            outp[g * 18 + 12 + i] = o[g * 18 + 12 + i];
    }
}

extern "C" void kernel_launch(void* const* d_in, const int* in_sizes, int n_in,
                              void* d_out, int out_size) {
    const float* o   = (const float*)d_in[0];
    const float* a   = (const float*)d_in[1];
    const float* W1L = (const float*)d_in[2];
    const float* b1L = (const float*)d_in[3];
    const float* W2L = (const float*)d_in[4];
    const float* b2L = (const float*)d_in[5];
    const float* W3L = (const float*)d_in[6];
    const float* b3L = (const float*)d_in[7];
    const float* W1V = (const float*)d_in[8];
    const float* b1V = (const float*)d_in[9];
    const float* W2V = (const float*)d_in[10];
    const float* b2V = (const float*)d_in[11];
    const float* W3V = (const float*)d_in[12];
    float* outp = (float*)d_out;

    int B = in_sizes[0] / 18;
    int grid = (B + TB - 1) / TB;
    cudaFuncSetAttribute(lnn_mma,
                         cudaFuncAttributeMaxDynamicSharedMemorySize, SB_END);
    lnn_mma<<<grid, NTH, SB_END>>>(o, a, W1L, b1L, W2L, b2L, W3L, b3L,
                                   W1V, b1V, W2V, b2V, W3V, outp, B);
}

// round 13
// speedup vs baseline: 2.2835x; 1.0495x over previous
#include <cuda_runtime.h>
#include <cuda_bf16.h>
#include <cstdint>
#include <math.h>

#define NTH 512
#define TB  64

// ---- smem byte offsets (all 16B aligned) ----
#define SB_AH  0
#define SB_AL  17408
#define SB_WH  34816
#define SB_WL  69632
#define SB_W3H 104448
#define SB_W3L 110976
#define SB_W1R 117504
#define SB_XH  129792
#define SB_XL  132864
#define SB_DY  135936
#define SB_GX  142080   // 64 x 48 f32
#define SB_XF  154368
#define SB_Q   157440
#define SB_QD  158976
#define SB_AA  160512
#define SB_LR  162048
#define SB_MS  167424
#define SB_B   172800
#define SB_END 175456

#define MMA(acc,a0,a1,a2,a3,b0,b1) \
  asm volatile("mma.sync.aligned.m16n8k16.row.col.f32.bf16.bf16.f32 " \
    "{%0,%1,%2,%3},{%4,%5,%6,%7},{%8,%9},{%0,%1,%2,%3};" \
    : "+f"(acc[0]),"+f"(acc[1]),"+f"(acc[2]),"+f"(acc[3]) \
    : "r"(a0),"r"(a1),"r"(a2),"r"(a3),"r"(b0),"r"(b1))

__device__ __forceinline__ void ldsm4(uint32_t& d0, uint32_t& d1, uint32_t& d2,
                                      uint32_t& d3, uint32_t addr) {
    asm volatile("ldmatrix.sync.aligned.m8n8.x4.shared.b16 {%0,%1,%2,%3},[%4];"
        : "=r"(d0), "=r"(d1), "=r"(d2), "=r"(d3) : "r"(addr));
}
__device__ __forceinline__ void ldsm2(uint32_t& d0, uint32_t& d1, uint32_t addr) {
    asm volatile("ldmatrix.sync.aligned.m8n8.x2.shared.b16 {%0,%1},[%2];"
        : "=r"(d0), "=r"(d1) : "r"(addr));
}

static __device__ __forceinline__ float softplusf(float z) {
    return fmaxf(z, 0.0f) + __logf(1.0f + __expf(-fabsf(z)));
}
static __device__ __forceinline__ uint32_t pack2(float a, float b) {
    __nv_bfloat162 t = __floats2bfloat162_rn(a, b);
    return *reinterpret_cast<uint32_t*>(&t);
}
static __device__ __forceinline__ void wsplit2(float v, char* hi, char* lo, uint32_t off) {
    __nv_bfloat16 h = __float2bfloat16(v);
    *(__nv_bfloat16*)(hi + off) = h;
    *(__nv_bfloat16*)(lo + off) = __float2bfloat16(v - __bfloat162float(h));
}

extern "C" __global__ void __launch_bounds__(NTH, 1)
lnn_mma(const float* __restrict__ o,    const float* __restrict__ ain,
        const float* __restrict__ gW1L, const float* __restrict__ gb1L,
        const float* __restrict__ gW2L, const float* __restrict__ gb2L,
        const float* __restrict__ gW3L, const float* __restrict__ gb3L,
        const float* __restrict__ gW1V, const float* __restrict__ gb1V,
        const float* __restrict__ gW2V, const float* __restrict__ gb2V,
        const float* __restrict__ gW3V,
        float* __restrict__ outp, int B)
{
    extern __shared__ char smc[];
    uint32_t* AH32  = (uint32_t*)(smc + SB_AH);
    uint32_t* AL32  = (uint32_t*)(smc + SB_AL);
    uint32_t* XH32  = (uint32_t*)(smc + SB_XH);
    uint32_t* XL32  = (uint32_t*)(smc + SB_XL);
    float* W1f  = (float*)(smc + SB_W1R);
    float* sDYf = (float*)(smc + SB_DY);
    float* sGX  = (float*)(smc + SB_GX);
    float* sXF  = (float*)(smc + SB_XF);
    float* sQ   = (float*)(smc + SB_Q);
    float* sQD  = (float*)(smc + SB_QD);
    float* sAA  = (float*)(smc + SB_AA);
    float* sLr  = (float*)(smc + SB_LR);
    float* sMs  = (float*)(smc + SB_MS);
    float* sB   = (float*)(smc + SB_B);

    const int tid = threadIdx.x, w = tid >> 5, lane = tid & 31;
    const int gid = lane >> 2, tig = lane & 3;
    const int mt = w & 3, nq = w >> 2;          // 4 M-tiles x 4 N-quarters
    const int r0 = mt * 16 + gid, r1 = r0 + 8;
    const int base = blockIdx.x * TB;
    const int RO[6] = {0, 1, 3, 6, 10, 15};
    #define MML(i,j) ((i)>=(j) ? Msl[RO[i]+(j)] : Msl[RO[j]+(i)])

    const uint32_t sbs = (uint32_t)__cvta_generic_to_shared(smc);
    // ldmatrix per-lane address components
    const int rowA = mt * 16 + (lane & 7) + ((lane >> 3) & 1) * 8;
    const int colA = (lane >> 4) * 16;
    const uint32_t aAddrH = sbs + SB_AH + rowA * 272 + colA;
    const uint32_t aAddrL = sbs + SB_AL + rowA * 272 + colA;
    const int rowBl = (lane & 7) + ((lane >> 4) << 3);   // 0..15 within a 16-row pair
    const int colB  = ((lane >> 3) & 1) * 16;
    const uint32_t bAddrH0 = sbs + SB_WH + (nq * 32 + rowBl) * 272 + colB;
    const uint32_t bAddrH1 = bAddrH0 + 16 * 272;
    const uint32_t bAddrL0 = sbs + SB_WL + (nq * 32 + rowBl) * 272 + colB;
    const uint32_t bAddrL1 = bAddrL0 + 16 * 272;
    const uint32_t mAddrH0 = sbs + SB_W3H + rowBl * 272 + colB;          // W3 rows 0-15
    const uint32_t mAddrL0 = sbs + SB_W3L + rowBl * 272 + colB;
    const uint32_t mAddrH2 = sbs + SB_W3H + (16 + (lane & 7)) * 272 + colB; // rows 16-23 (x2)
    const uint32_t mAddrL2 = sbs + SB_W3L + (16 + (lane & 7)) * 272 + colB;
    const uint32_t xAddrH = sbs + SB_XH + rowA * 48 + colA;
    const uint32_t xAddrL = sbs + SB_XL + rowA * 48 + colA;
    const uint32_t uAddrH0 = sbs + SB_W1R + (nq * 32 + rowBl) * 48 + colB;
    const uint32_t uAddrH1 = uAddrH0 + 16 * 48;
    const uint32_t uAddrL0 = uAddrH0 + 6144;
    const uint32_t uAddrL1 = uAddrH1 + 6144;

    // persistent loads
    for (int i = tid; i < 128; i += NTH) {
        sB[i] = gb1L[i]; sB[128 + i] = gb2L[i];
        sB[256 + i] = gb1V[i]; sB[384 + i] = gb2V[i]; sB[512 + i] = gW3V[i];
    }
    if (tid < 24) sB[640 + tid] = tid < 21 ? gb3L[tid] : 0.f;
    for (int i = tid; i < 3072; i += NTH) {     // W3^T tile (24 x 128)
        int j = i >> 7, k = i & 127;
        float v = (j < 21) ? gW3L[k * 21 + j] : 0.f;
        wsplit2(v, smc + SB_W3H, smc + SB_W3L, (uint32_t)(j * 272 + k * 2));
    }
    for (int i = tid; i < TB * 6; i += NTH) {
        int r = i / 6, c = i - 6 * r;
        int g = base + r; if (g > B - 1) g = B - 1;
        sQ[i] = o[g * 18 + c]; sQD[i] = o[g * 18 + 6 + c]; sAA[i] = ain[g * 6 + c];
    }

    float sg1[4][4], sg2[4][4], k1v[6], k2v[6];

    // ---- helpers ----
    auto storeA = [&](int nt, float v0, float v1, float v2, float v3) {
        int ci = nq * 16 + nt * 4 + tig;
        uint32_t h01 = pack2(v0, v1);
        __nv_bfloat162 hh = *reinterpret_cast<__nv_bfloat162*>(&h01);
        AH32[r0 * 68 + ci] = h01;
        AL32[r0 * 68 + ci] = pack2(v0 - __bfloat162float(hh.x), v1 - __bfloat162float(hh.y));
        uint32_t h23 = pack2(v2, v3);
        __nv_bfloat162 hh2 = *reinterpret_cast<__nv_bfloat162*>(&h23);
        AH32[r1 * 68 + ci] = h23;
        AL32[r1 * 68 + ci] = pack2(v2 - __bfloat162float(hh2.x), v3 - __bfloat162float(hh2.y));
    };
    auto bigGemm = [&](float (&acc)[4][4]) {
        #pragma unroll
        for (int nt = 0; nt < 4; nt++)
            acc[nt][0] = acc[nt][1] = acc[nt][2] = acc[nt][3] = 0.f;
        #pragma unroll
        for (int kt = 0; kt < 8; kt++) {
            uint32_t ko = kt * 32;
            uint32_t ah0, ah1, ah2, ah3, al0, al1, al2, al3;
            ldsm4(ah0, ah1, ah2, ah3, aAddrH + ko);
            ldsm4(al0, al1, al2, al3, aAddrL + ko);
            uint32_t bh[8], bl[8];
            ldsm4(bh[0], bh[1], bh[2], bh[3], bAddrH0 + ko);
            ldsm4(bh[4], bh[5], bh[6], bh[7], bAddrH1 + ko);
            ldsm4(bl[0], bl[1], bl[2], bl[3], bAddrL0 + ko);
            ldsm4(bl[4], bl[5], bl[6], bl[7], bAddrL1 + ko);
            #pragma unroll
            for (int nt = 0; nt < 4; nt++) MMA(acc[nt], ah0, ah1, ah2, ah3, bh[nt*2], bh[nt*2+1]);
            #pragma unroll
            for (int nt = 0; nt < 4; nt++) MMA(acc[nt], ah0, ah1, ah2, ah3, bl[nt*2], bl[nt*2+1]);
            #pragma unroll
            for (int nt = 0; nt < 4; nt++) MMA(acc[nt], al0, al1, al2, al3, bh[nt*2], bh[nt*2+1]);
        }
    };
    auto l1Gemm = [&](float (&acc)[4][4]) {
        uint32_t ah0, ah1, ah2, ah3, al0, al1, al2, al3;
        ldsm4(ah0, ah1, ah2, ah3, xAddrH);
        ldsm4(al0, al1, al2, al3, xAddrL);
        uint32_t bh[8], bl[8];
        ldsm4(bh[0], bh[1], bh[2], bh[3], uAddrH0);
        ldsm4(bh[4], bh[5], bh[6], bh[7], uAddrH1);
        ldsm4(bl[0], bl[1], bl[2], bl[3], uAddrL0);
        ldsm4(bl[4], bl[5], bl[6], bl[7], uAddrL1);
        #pragma unroll
        for (int nt = 0; nt < 4; nt++) {
            acc[nt][0] = acc[nt][1] = acc[nt][2] = acc[nt][3] = 0.f;
        }
        #pragma unroll
        for (int nt = 0; nt < 4; nt++) MMA(acc[nt], ah0, ah1, ah2, ah3, bh[nt*2], bh[nt*2+1]);
        #pragma unroll
        for (int nt = 0; nt < 4; nt++) MMA(acc[nt], ah0, ah1, ah2, ah3, bl[nt*2], bl[nt*2+1]);
        #pragma unroll
        for (int nt = 0; nt < 4; nt++) MMA(acc[nt], al0, al1, al2, al3, bh[nt*2], bh[nt*2+1]);
    };
    auto miniGemm = [&]() {           // nq==0 warps only; writes sDYf (raw, no bias)
        float acc[3][4];
        #pragma unroll
        for (int nt = 0; nt < 3; nt++)
            acc[nt][0] = acc[nt][1] = acc[nt][2] = acc[nt][3] = 0.f;
        #pragma unroll
        for (int kt = 0; kt < 8; kt++) {
            uint32_t ko = kt * 32;
            uint32_t ah0, ah1, ah2, ah3, al0, al1, al2, al3;
            ldsm4(ah0, ah1, ah2, ah3, aAddrH + ko);
            ldsm4(al0, al1, al2, al3, aAddrL + ko);
            uint32_t bh[6], bl[6];
            ldsm4(bh[0], bh[1], bh[2], bh[3], mAddrH0 + ko);
            ldsm2(bh[4], bh[5], mAddrH2 + ko);
            ldsm4(bl[0], bl[1], bl[2], bl[3], mAddrL0 + ko);
            ldsm2(bl[4], bl[5], mAddrL2 + ko);
            #pragma unroll
            for (int nt = 0; nt < 3; nt++) MMA(acc[nt], ah0, ah1, ah2, ah3, bh[nt*2], bh[nt*2+1]);
            #pragma unroll
            for (int nt = 0; nt < 3; nt++) MMA(acc[nt], ah0, ah1, ah2, ah3, bl[nt*2], bl[nt*2+1]);
            #pragma unroll
            for (int nt = 0; nt < 3; nt++) MMA(acc[nt], al0, al1, al2, al3, bh[nt*2], bh[nt*2+1]);
        }
        #pragma unroll
        for (int nt = 0; nt < 3; nt++) {
            int c = nt * 8 + tig * 2;
            sDYf[r0 * 24 + c] = acc[nt][0]; sDYf[r0 * 24 + c + 1] = acc[nt][1];
            sDYf[r1 * 24 + c] = acc[nt][2]; sDYf[r1 * 24 + c + 1] = acc[nt][3];
        }
    };
    auto buildU1 = [&](int d) {       // tangent input u1(d) -> A (W1f = W1L fp32)
        float cq0 = sXF[r0 * 12 + 2 * d], sq0 = sXF[r0 * 12 + 2 * d + 1];
        float cq1 = sXF[r1 * 12 + 2 * d], sq1 = sXF[r1 * 12 + 2 * d + 1];
        #pragma unroll
        for (int nt = 0; nt < 4; nt++) {
            int c = nq * 32 + nt * 8 + tig * 2;
            float2 wa = *(const float2*)&W1f[2 * d * 128 + c];
            float2 wb = *(const float2*)&W1f[(2 * d + 1) * 128 + c];
            storeA(nt,
                sg1[nt][0] * (cq0 * wb.x - sq0 * wa.x),
                sg1[nt][1] * (cq0 * wb.y - sq0 * wa.y),
                sg1[nt][2] * (cq1 * wb.x - sq1 * wa.x),
                sg1[nt][3] * (cq1 * wb.y - sq1 * wa.y));
        }
    };
    auto streamW2T = [&](const float* g) {   // Wt[n][k] = g[k*128+n]
        for (int i = tid; i < 16384; i += NTH) {
            int k = i >> 7, n = i & 127;
            wsplit2(g[i], smc + SB_WH, smc + SB_WL, (uint32_t)(n * 272 + k * 2));
        }
    };
    auto streamW2D = [&](const float* g) {   // Wt[t][n] = g[t*128+n]  (VJP)
        for (int i = tid; i < 16384; i += NTH) {
            int t = i >> 7, n = i & 127;
            wsplit2(g[i], smc + SB_WH, smc + SB_WL, (uint32_t)(t * 272 + n * 2));
        }
    };
    auto streamW1S = [&](const float* g) {   // layer1 B: [c][t], t padded to 16
        for (int i = tid; i < 2048; i += NTH) {
            int c = i >> 4, t = i & 15;
            float v = (t < 12) ? g[t * 128 + c] : 0.f;
            wsplit2(v, smc + SB_W1R, smc + SB_W1R + 6144, (uint32_t)(c * 48 + t * 2));
        }
    };
    auto streamW1F = [&](const float* g) {
        for (int i = tid; i < 1536; i += NTH) W1f[i] = g[i];
    };

    __syncthreads();
    const float ADT = (2.0f / 3.0f) * 0.02f;

    for (int stage = 0; stage < 2; ++stage) {
        if (tid < TB) {                  // trig features + X tile
            int r = tid;
            #pragma unroll
            for (int i = 0; i < 6; i++) {
                float sv, cv; __sincosf(sQ[r * 6 + i], &sv, &cv);
                sXF[r * 12 + 2 * i] = cv; sXF[r * 12 + 2 * i + 1] = sv;
            }
            #pragma unroll
            for (int t = 0; t < 12; t++)
                wsplit2(sXF[r * 12 + t], smc + SB_XH, smc + SB_XL, (uint32_t)(r * 48 + t * 2));
            XH32[r * 12 + 6] = 0; XH32[r * 12 + 7] = 0;
            XL32[r * 12 + 6] = 0; XL32[r * 12 + 7] = 0;
        }
        streamW2T(gW2L);
        streamW1S(gW1L);
        __syncthreads();

        // layer1 L -> h1 (A), sigma1 (regs)
        {
            float acc[4][4]; l1Gemm(acc);
            #pragma unroll
            for (int nt = 0; nt < 4; nt++) {
                int c = nq * 32 + nt * 8 + tig * 2;
                float h0 = softplusf(acc[nt][0] + sB[c]);
                float h1 = softplusf(acc[nt][1] + sB[c + 1]);
                float h2 = softplusf(acc[nt][2] + sB[c]);
                float h3 = softplusf(acc[nt][3] + sB[c + 1]);
                sg1[nt][0] = 1.f - __expf(-h0); sg1[nt][1] = 1.f - __expf(-h1);
                sg1[nt][2] = 1.f - __expf(-h2); sg1[nt][3] = 1.f - __expf(-h3);
                storeA(nt, h0, h1, h2, h3);
            }
        }
        __syncthreads();
        streamW1F(gW1L);                 // W1f := W1L fp32 (split tile dead)
        // h2 = softplus(h1 @ W2L^T + b2L)
        {
            float acc[4][4]; bigGemm(acc);
            __syncthreads();
            #pragma unroll
            for (int nt = 0; nt < 4; nt++) {
                int c = nq * 32 + nt * 8 + tig * 2;
                float h0 = softplusf(acc[nt][0] + sB[128 + c]);
                float h1 = softplusf(acc[nt][1] + sB[128 + c + 1]);
                float h2 = softplusf(acc[nt][2] + sB[128 + c]);
                float h3 = softplusf(acc[nt][3] + sB[128 + c + 1]);
                sg2[nt][0] = 1.f - __expf(-h0); sg2[nt][1] = 1.f - __expf(-h1);
                sg2[nt][2] = 1.f - __expf(-h2); sg2[nt][3] = 1.f - __expf(-h3);
                storeA(nt, h0, h1, h2, h3);
            }
        }
        __syncthreads();
        if (nq == 0) miniGemm();         // y -> sDY
        __syncthreads();

        float wv[6], Aacc[6], svec[6], Cacc[6];
        if (tid < TB) {                  // physics init
            int r = tid;
            const float* dy = sDYf + r * 24;
            float Lrl[21], Msl[21];
            #pragma unroll
            for (int t = 0; t < 21; t++) { Lrl[t] = dy[t] + sB[640 + t]; sLr[r * 21 + t] = Lrl[t]; }
            #pragma unroll
            for (int i = 0; i < 6; i++)
                #pragma unroll
                for (int j = 0; j < 6; j++) if (j <= i) {
                    float s2 = 0.f;
                    #pragma unroll
                    for (int k = 0; k < 6; k++) if (k <= j) s2 += Lrl[RO[i] + k] * Lrl[RO[j] + k];
                    if (i == j) s2 += 1e-6f;
                    Msl[RO[i] + j] = s2; sMs[r * 21 + RO[i] + j] = s2;
                }
            #pragma unroll
            for (int i = 0; i < 6; i++) {
                float s2 = 0.f;
                #pragma unroll
                for (int j = 0; j < 6; j++) s2 += MML(i, j) * sQD[r * 6 + j];
                wv[i] = s2; Aacc[i] = 0.f; svec[i] = 0.f;
            }
        }
        buildU1(0);
        __syncthreads();

        // ---- 6 tangent directions ----
        for (int d = 0; d < 6; ++d) {
            {
                float acc[4][4]; bigGemm(acc);   // u1 @ W2L^T
                __syncthreads();
                #pragma unroll
                for (int nt = 0; nt < 4; nt++)   // u2 = sigma2 * acc
                    storeA(nt, acc[nt][0] * sg2[nt][0], acc[nt][1] * sg2[nt][1],
                               acc[nt][2] * sg2[nt][2], acc[nt][3] * sg2[nt][3]);
            }
            __syncthreads();
            if (nq == 0) miniGemm();             // dy(d) -> sDY
            if (d == 5) streamW1S(gW1V);         // W1R := W1V split
            __syncthreads();
            if (tid < TB) {                      // physics(d)
                int r = tid;
                const float* dy = sDYf + r * 24;
                const float* Lp = sLr + r * 21;
                float qdr[6];
                #pragma unroll
                for (int j = 0; j < 6; j++) qdr[j] = sQD[r * 6 + j];
                float D6[6][6];
                #pragma unroll
                for (int i = 0; i < 6; i++)
                    #pragma unroll
                    for (int j = 0; j < 6; j++) if (j <= i) {
                        float s2 = 0.f;
                        #pragma unroll
                        for (int k = 0; k < 6; k++) if (k <= j)
                            s2 += dy[RO[i] + k] * Lp[RO[j] + k] + Lp[RO[i] + k] * dy[RO[j] + k];
                        D6[i][j] = s2; D6[j][i] = s2;
                    }
                float qdd = qdr[d], cdot = 0.f;
                #pragma unroll
                for (int i = 0; i < 6; i++) {
                    float v1 = 0.f, v2 = 0.f;
                    #pragma unroll
                    for (int j = 0; j < 6; j++) { v1 += D6[i][j] * wv[j]; v2 += D6[i][j] * qdr[j]; }
                    Aacc[i] += qdd * v1; svec[i] += qdd * v2; cdot += qdr[i] * v1;
                }
                Cacc[d] = cdot;
            }
            if (d < 5) {
                buildU1(d + 1);
            } else {                             // layer1 V -> h1V (A), sigma1V
                float acc[4][4]; l1Gemm(acc);
                #pragma unroll
                for (int nt = 0; nt < 4; nt++) {
                    int c = nq * 32 + nt * 8 + tig * 2;
                    float h0 = softplusf(acc[nt][0] + sB[256 + c]);
                    float h1 = softplusf(acc[nt][1] + sB[256 + c + 1]);
                    float h2 = softplusf(acc[nt][2] + sB[256 + c]);
                    float h3 = softplusf(acc[nt][3] + sB[256 + c + 1]);
                    sg1[nt][0] = 1.f - __expf(-h0); sg1[nt][1] = 1.f - __expf(-h1);
                    sg1[nt][2] = 1.f - __expf(-h2); sg1[nt][3] = 1.f - __expf(-h3);
                    storeA(nt, h0, h1, h2, h3);
                }
            }
            __syncthreads();
        }

        streamW2T(gW2V);                         // W := W2V^T
        streamW1F(gW1V);                         // W1f := W1V fp32
        __syncthreads();
        // h2V ; u2g = sig(h2V)*W3V
        {
            float acc[4][4]; bigGemm(acc);
            __syncthreads();
            #pragma unroll
            for (int nt = 0; nt < 4; nt++) {
                int c = nq * 32 + nt * 8 + tig * 2;
                float h0 = softplusf(acc[nt][0] + sB[384 + c]);
                float h1 = softplusf(acc[nt][1] + sB[384 + c + 1]);
                float h2 = softplusf(acc[nt][2] + sB[384 + c]);
                float h3 = softplusf(acc[nt][3] + sB[384 + c + 1]);
                storeA(nt, (1.f - __expf(-h0)) * sB[512 + c],
                           (1.f - __expf(-h1)) * sB[512 + c + 1],
                           (1.f - __expf(-h2)) * sB[512 + c],
                           (1.f - __expf(-h3)) * sB[512 + c + 1]);
            }
        }
        __syncthreads();
        streamW2D(gW2V);                         // W := W2V direct (VJP)
        __syncthreads();
        // VJP GEMM + gx projection
        {
            float acc[4][4]; bigGemm(acc);
            float gx0[12], gx1[12];
            #pragma unroll
            for (int t = 0; t < 12; t++) { gx0[t] = 0.f; gx1[t] = 0.f; }
            #pragma unroll
            for (int nt = 0; nt < 4; nt++) {
                int c = nq * 32 + nt * 8 + tig * 2;
                float u0 = acc[nt][0] * sg1[nt][0], u1 = acc[nt][1] * sg1[nt][1];
                float u2 = acc[nt][2] * sg1[nt][2], u3 = acc[nt][3] * sg1[nt][3];
                #pragma unroll
                for (int t = 0; t < 12; t++) {
                    float2 wv2 = *(const float2*)&W1f[t * 128 + c];
                    gx0[t] += u0 * wv2.x + u1 * wv2.y;
                    gx1[t] += u2 * wv2.x + u3 * wv2.y;
                }
            }
            #pragma unroll
            for (int t = 0; t < 12; t++) {
                gx0[t] += __shfl_xor_sync(0xFFFFFFFF, gx0[t], 1);
                gx0[t] += __shfl_xor_sync(0xFFFFFFFF, gx0[t], 2);
                gx1[t] += __shfl_xor_sync(0xFFFFFFFF, gx1[t], 1);
                gx1[t] += __shfl_xor_sync(0xFFFFFFFF, gx1[t], 2);
            }
            if (tig == 0) {
                #pragma unroll
                for (int t = 0; t < 12; t++) {
                    sGX[r0 * 48 + nq * 12 + t] = gx0[t];
                    sGX[r1 * 48 + nq * 12 + t] = gx1[t];
                }
            }
        }
        __syncthreads();
        // final per-row: cvec, rhs, solves, state update
        if (tid < TB) {
            int r = tid;
            float Msl[21];
            #pragma unroll
            for (int t = 0; t < 21; t++) Msl[t] = sMs[r * 21 + t];
            float cv[6];
            #pragma unroll
            for (int i = 0; i < 6; i++) {
                float ms = 0.f;
                #pragma unroll
                for (int j = 0; j < 6; j++) ms += MML(i, j) * svec[j];
                cv[i] = Aacc[i] + ms - Cacc[i];
            }
            float rhs[6];
            #pragma unroll
            for (int i = 0; i < 6; i++) {
                float g0 = sGX[r * 48 + 2 * i]      + sGX[r * 48 + 12 + 2 * i]
                         + sGX[r * 48 + 24 + 2 * i] + sGX[r * 48 + 36 + 2 * i];
                float g1 = sGX[r * 48 + 2 * i + 1]      + sGX[r * 48 + 12 + 2 * i + 1]
                         + sGX[r * 48 + 24 + 2 * i + 1] + sGX[r * 48 + 36 + 2 * i + 1];
                float dv = -sXF[r * 12 + 2 * i + 1] * g0 + sXF[r * 12 + 2 * i] * g1;
                rhs[i] = sAA[r * 6 + i] - cv[i] - dv;
            }
            float yv[6], zv[6];
            #pragma unroll
            for (int i = 0; i < 6; i++) {
                float s2 = rhs[i];
                #pragma unroll
                for (int j = 0; j < 6; j++) if (j < i) s2 -= Msl[RO[i] + j] * yv[j];
                yv[i] = s2 / Msl[RO[i] + i];
            }
            #pragma unroll
            for (int ii = 5; ii >= 0; ii--) {
                float s2 = yv[ii];
                #pragma unroll
                for (int j = 0; j < 6; j++) if (j > ii) s2 -= Msl[RO[j] + ii] * zv[j];
                zv[ii] = s2 / Msl[RO[ii] + ii];
            }
            if (stage == 0) {
                #pragma unroll
                for (int i = 0; i < 6; i++) {
                    k1v[i] = zv[i];
                    float qdi = sQD[r * 6 + i];
                    sQ[r * 6 + i] += ADT * qdi;
                    sQD[r * 6 + i] = qdi + ADT * zv[i];
                }
            } else {
                #pragma unroll
                for (int i = 0; i < 6; i++) k2v[i] = zv[i];
            }
        }
        __syncthreads();
    }

    // ---- output ----
    if (tid < TB && base + tid < B) {
        int g = base + tid, r = tid;
        #pragma unroll
        for (int i = 0; i < 6; i++)
            outp[g * 18 + i] = o[g * 18 + i]
                + 0.02f * (0.25f * o[g * 18 + 6 + i] + 0.75f * sQD[r * 6 + i]);
        #pragma unroll
        for (int i = 0; i < 6; i++)
            outp[g * 18 + 6 + i] = o[g * 18 + 6 + i]
                + 0.02f * (0.25f * k1v[i] + 0.75f * k2v[i]);
        #pragma unroll
        for (int i = 0; i < 6; i++)
            outp[g * 18 + 12 + i] = o[g * 18 + 12 + i];
    }
}

extern "C" void kernel_launch(void* const* d_in, const int* in_sizes, int n_in,
                              void* d_out, int out_size) {
    const float* o   = (const float*)d_in[0];
    const float* a   = (const float*)d_in[1];
    const float* W1L = (const float*)d_in[2];
    const float* b1L = (const float*)d_in[3];
    const float* W2L = (const float*)d_in[4];
    const float* b2L = (const float*)d_in[5];
    const float* W3L = (const float*)d_in[6];
    const float* b3L = (const float*)d_in[7];
    const float* W1V = (const float*)d_in[8];
    const float* b1V = (const float*)d_in[9];
    const float* W2V = (const float*)d_in[10];
    const float* b2V = (const float*)d_in[11];
    const float* W3V = (const float*)d_in[12];
    float* outp = (float*)d_out;

    int B = in_sizes[0] / 18;
    int grid = (B + TB - 1) / TB;
    cudaFuncSetAttribute(lnn_mma,
                         cudaFuncAttributeMaxDynamicSharedMemorySize, SB_END);
    lnn_mma<<<grid, NTH, SB_END>>>(o, a, W1L, b1L, W2L, b2L, W3L, b3L,
                                   W1V, b1V, W2V, b2V, W3V, outp, B);
}

// round 14
// speedup vs baseline: 2.5800x; 1.1298x over previous
#include <cuda_runtime.h>
#include <cuda_bf16.h>
#include <cstdint>
#include <math.h>

#define NTH 512
#define TB  64

// ---- smem byte offsets (all 16B aligned) ----
#define SB_AH  0
#define SB_AL  17408
#define SB_WH  34816
#define SB_WL  69632
#define SB_W3H 104448
#define SB_W3L 110976
#define SB_W1R 117504
#define SB_XH  129792
#define SB_XL  132864
#define SB_DY  135936
#define SB_GX  142080   // 64 x 48 f32
#define SB_XF  154368
#define SB_Q   157440
#define SB_QD  158976
#define SB_AA  160512
#define SB_LR  162048
#define SB_MS  167424
#define SB_B   172800
#define SB_END 175456

#define MMA(acc,a0,a1,a2,a3,b0,b1) \
  asm volatile("mma.sync.aligned.m16n8k16.row.col.f32.bf16.bf16.f32 " \
    "{%0,%1,%2,%3},{%4,%5,%6,%7},{%8,%9},{%0,%1,%2,%3};" \
    : "+f"(acc[0]),"+f"(acc[1]),"+f"(acc[2]),"+f"(acc[3]) \
    : "r"(a0),"r"(a1),"r"(a2),"r"(a3),"r"(b0),"r"(b1))

__device__ __forceinline__ void ldsm4(uint32_t& d0, uint32_t& d1, uint32_t& d2,
                                      uint32_t& d3, uint32_t addr) {
    asm volatile("ldmatrix.sync.aligned.m8n8.x4.shared.b16 {%0,%1,%2,%3},[%4];"
        : "=r"(d0), "=r"(d1), "=r"(d2), "=r"(d3) : "r"(addr));
}
__device__ __forceinline__ void ldsm4t(uint32_t& d0, uint32_t& d1, uint32_t& d2,
                                       uint32_t& d3, uint32_t addr) {
    asm volatile("ldmatrix.sync.aligned.m8n8.x4.trans.shared.b16 {%0,%1,%2,%3},[%4];"
        : "=r"(d0), "=r"(d1), "=r"(d2), "=r"(d3) : "r"(addr));
}
__device__ __forceinline__ void ldsm2t(uint32_t& d0, uint32_t& d1, uint32_t addr) {
    asm volatile("ldmatrix.sync.aligned.m8n8.x2.trans.shared.b16 {%0,%1},[%2];"
        : "=r"(d0), "=r"(d1) : "r"(addr));
}

static __device__ __forceinline__ float softplusf(float z) {
    return fmaxf(z, 0.0f) + __logf(1.0f + __expf(-fabsf(z)));
}
static __device__ __forceinline__ uint32_t pack2(float a, float b) {
    __nv_bfloat162 t = __floats2bfloat162_rn(a, b);
    return *reinterpret_cast<uint32_t*>(&t);
}
static __device__ __forceinline__ void wsplit2(float v, char* hi, char* lo, uint32_t off) {
    __nv_bfloat16 h = __float2bfloat16(v);
    *(__nv_bfloat16*)(hi + off) = h;
    *(__nv_bfloat16*)(lo + off) = __float2bfloat16(v - __bfloat162float(h));
}

extern "C" __global__ void __launch_bounds__(NTH, 1)
lnn_mma(const float* __restrict__ o,    const float* __restrict__ ain,
        const float* __restrict__ gW1L, const float* __restrict__ gb1L,
        const float* __restrict__ gW2L, const float* __restrict__ gb2L,
        const float* __restrict__ gW3L, const float* __restrict__ gb3L,
        const float* __restrict__ gW1V, const float* __restrict__ gb1V,
        const float* __restrict__ gW2V, const float* __restrict__ gb2V,
        const float* __restrict__ gW3V,
        float* __restrict__ outp, int B)
{
    extern __shared__ char smc[];
    uint32_t* AH32  = (uint32_t*)(smc + SB_AH);
    uint32_t* AL32  = (uint32_t*)(smc + SB_AL);
    uint32_t* XH32  = (uint32_t*)(smc + SB_XH);
    uint32_t* XL32  = (uint32_t*)(smc + SB_XL);
    float* W1f  = (float*)(smc + SB_W1R);
    float* sDYf = (float*)(smc + SB_DY);
    float* sGX  = (float*)(smc + SB_GX);
    float* sXF  = (float*)(smc + SB_XF);
    float* sQ   = (float*)(smc + SB_Q);
    float* sQD  = (float*)(smc + SB_QD);
    float* sAA  = (float*)(smc + SB_AA);
    float* sLr  = (float*)(smc + SB_LR);
    float* sMs  = (float*)(smc + SB_MS);
    float* sB   = (float*)(smc + SB_B);

    const int tid = threadIdx.x, w = tid >> 5, lane = tid & 31;
    const int gid = lane >> 2, tig = lane & 3;
    const int mt = w & 3, nq = w >> 2;          // 4 M-tiles x 4 N-quarters
    const int r0 = mt * 16 + gid, r1 = r0 + 8;
    const int base = blockIdx.x * TB;
    const int RO[6] = {0, 1, 3, 6, 10, 15};
    #define MML(i,j) ((i)>=(j) ? Msl[RO[i]+(j)] : Msl[RO[j]+(i)])

    const uint32_t sbs = (uint32_t)__cvta_generic_to_shared(smc);
    // A fragments (non-trans, rows = batch)
    const int rowA = mt * 16 + (lane & 7) + ((lane >> 3) & 1) * 8;
    const int colA = (lane >> 4) * 16;
    const uint32_t aAddrH = sbs + SB_AH + rowA * 272 + colA;
    const uint32_t aAddrL = sbs + SB_AL + rowA * 272 + colA;
    // forward B fragments (TRANS, W stored raw row-major [k][n])
    const int rowK = (lane & 7) + ((lane >> 3) & 1) * 8;
    const int colT = (lane >> 4) * 16;
    const uint32_t bTH = sbs + SB_WH + rowK * 272 + nq * 64 + colT;
    const uint32_t bTL = sbs + SB_WL + rowK * 272 + nq * 64 + colT;
    // VJP B fragments (non-trans, same raw W tile, rows = t)
    const int rowBl = (lane & 7) + ((lane >> 4) << 3);
    const int colB  = ((lane >> 3) & 1) * 16;
    const uint32_t bVH0 = sbs + SB_WH + (nq * 32 + rowBl) * 272 + colB;
    const uint32_t bVH1 = bVH0 + 16 * 272;
    const uint32_t bVL0 = sbs + SB_WL + (nq * 32 + rowBl) * 272 + colB;
    const uint32_t bVL1 = bVL0 + 16 * 272;
    // mini (W3 stored raw [c][t], TRANS), stride 48B
    const uint32_t mTH = sbs + SB_W3H + rowK * 48 + colT;
    const uint32_t mTL = sbs + SB_W3L + rowK * 48 + colT;
    const uint32_t mTH2 = sbs + SB_W3H + rowK * 48 + 32;
    const uint32_t mTL2 = sbs + SB_W3L + rowK * 48 + 32;
    // layer1 (non-trans, u1 tile [c][t16])
    const uint32_t xAddrH = sbs + SB_XH + rowA * 48 + colA;
    const uint32_t xAddrL = sbs + SB_XL + rowA * 48 + colA;
    const uint32_t uAddrH0 = sbs + SB_W1R + (nq * 32 + rowBl) * 48 + colB;
    const uint32_t uAddrH1 = uAddrH0 + 16 * 48;
    const uint32_t uAddrL0 = uAddrH0 + 6144;
    const uint32_t uAddrL1 = uAddrH1 + 6144;

    // persistent loads
    for (int i = tid; i < 128; i += NTH) {
        sB[i] = gb1L[i]; sB[128 + i] = gb2L[i];
        sB[256 + i] = gb1V[i]; sB[384 + i] = gb2V[i]; sB[512 + i] = gW3V[i];
    }
    if (tid < 24) sB[640 + tid] = tid < 21 ? gb3L[tid] : 0.f;
    for (int i = tid; i < 3072; i += NTH) {     // W3 raw tile [c][t] (128 x 24)
        int c = i / 24, t = i - c * 24;
        float v = (t < 21) ? gW3L[c * 21 + t] : 0.f;
        wsplit2(v, smc + SB_W3H, smc + SB_W3L, (uint32_t)(c * 48 + t * 2));
    }
    for (int i = tid; i < TB * 6; i += NTH) {
        int r = i / 6, c = i - 6 * r;
        int g = base + r; if (g > B - 1) g = B - 1;
        sQ[i] = o[g * 18 + c]; sQD[i] = o[g * 18 + 6 + c]; sAA[i] = ain[g * 6 + c];
    }

    float sg1[4][4], sg2[4][4], k1v[6], k2v[6];

    // ---- helpers ----
    auto storeA = [&](int nt, float v0, float v1, float v2, float v3) {
        int ci = nq * 16 + nt * 4 + tig;
        uint32_t h01 = pack2(v0, v1);
        __nv_bfloat162 hh = *reinterpret_cast<__nv_bfloat162*>(&h01);
        AH32[r0 * 68 + ci] = h01;
        AL32[r0 * 68 + ci] = pack2(v0 - __bfloat162float(hh.x), v1 - __bfloat162float(hh.y));
        uint32_t h23 = pack2(v2, v3);
        __nv_bfloat162 hh2 = *reinterpret_cast<__nv_bfloat162*>(&h23);
        AH32[r1 * 68 + ci] = h23;
        AL32[r1 * 68 + ci] = pack2(v2 - __bfloat162float(hh2.x), v3 - __bfloat162float(hh2.y));
    };
    auto bigGemm = [&](float (&acc)[4][4], bool fwd) {
        #pragma unroll
        for (int nt = 0; nt < 4; nt++)
            acc[nt][0] = acc[nt][1] = acc[nt][2] = acc[nt][3] = 0.f;
        #pragma unroll
        for (int kt = 0; kt < 8; kt++) {
            uint32_t ah0, ah1, ah2, ah3, al0, al1, al2, al3;
            ldsm4(ah0, ah1, ah2, ah3, aAddrH + kt * 32);
            ldsm4(al0, al1, al2, al3, aAddrL + kt * 32);
            uint32_t bh[8], bl[8];
            if (fwd) {
                ldsm4t(bh[0], bh[1], bh[2], bh[3], bTH + kt * 4352);
                ldsm4t(bh[4], bh[5], bh[6], bh[7], bTH + kt * 4352 + 32);
                ldsm4t(bl[0], bl[1], bl[2], bl[3], bTL + kt * 4352);
                ldsm4t(bl[4], bl[5], bl[6], bl[7], bTL + kt * 4352 + 32);
            } else {
                ldsm4(bh[0], bh[1], bh[2], bh[3], bVH0 + kt * 32);
                ldsm4(bh[4], bh[5], bh[6], bh[7], bVH1 + kt * 32);
                ldsm4(bl[0], bl[1], bl[2], bl[3], bVL0 + kt * 32);
                ldsm4(bl[4], bl[5], bl[6], bl[7], bVL1 + kt * 32);
            }
            #pragma unroll
            for (int nt = 0; nt < 4; nt++) MMA(acc[nt], ah0, ah1, ah2, ah3, bh[nt*2], bh[nt*2+1]);
            #pragma unroll
            for (int nt = 0; nt < 4; nt++) MMA(acc[nt], ah0, ah1, ah2, ah3, bl[nt*2], bl[nt*2+1]);
            #pragma unroll
            for (int nt = 0; nt < 4; nt++) MMA(acc[nt], al0, al1, al2, al3, bh[nt*2], bh[nt*2+1]);
        }
    };
    auto l1Gemm = [&](float (&acc)[4][4]) {
        uint32_t ah0, ah1, ah2, ah3, al0, al1, al2, al3;
        ldsm4(ah0, ah1, ah2, ah3, xAddrH);
        ldsm4(al0, al1, al2, al3, xAddrL);
        uint32_t bh[8], bl[8];
        ldsm4(bh[0], bh[1], bh[2], bh[3], uAddrH0);
        ldsm4(bh[4], bh[5], bh[6], bh[7], uAddrH1);
        ldsm4(bl[0], bl[1], bl[2], bl[3], uAddrL0);
        ldsm4(bl[4], bl[5], bl[6], bl[7], uAddrL1);
        #pragma unroll
        for (int nt = 0; nt < 4; nt++)
            acc[nt][0] = acc[nt][1] = acc[nt][2] = acc[nt][3] = 0.f;
        #pragma unroll
        for (int nt = 0; nt < 4; nt++) MMA(acc[nt], ah0, ah1, ah2, ah3, bh[nt*2], bh[nt*2+1]);
        #pragma unroll
        for (int nt = 0; nt < 4; nt++) MMA(acc[nt], ah0, ah1, ah2, ah3, bl[nt*2], bl[nt*2+1]);
        #pragma unroll
        for (int nt = 0; nt < 4; nt++) MMA(acc[nt], al0, al1, al2, al3, bh[nt*2], bh[nt*2+1]);
    };
    auto miniGemm = [&]() {           // nq==0 warps only; writes sDYf (raw)
        float acc[3][4];
        #pragma unroll
        for (int nt = 0; nt < 3; nt++)
            acc[nt][0] = acc[nt][1] = acc[nt][2] = acc[nt][3] = 0.f;
        #pragma unroll
        for (int kt = 0; kt < 8; kt++) {
            uint32_t ah0, ah1, ah2, ah3, al0, al1, al2, al3;
            ldsm4(ah0, ah1, ah2, ah3, aAddrH + kt * 32);
            ldsm4(al0, al1, al2, al3, aAddrL + kt * 32);
            uint32_t bh[6], bl[6];
            ldsm4t(bh[0], bh[1], bh[2], bh[3], mTH + kt * 768);
            ldsm2t(bh[4], bh[5], mTH2 + kt * 768);
            ldsm4t(bl[0], bl[1], bl[2], bl[3], mTL + kt * 768);
            ldsm2t(bl[4], bl[5], mTL2 + kt * 768);
            #pragma unroll
            for (int nt = 0; nt < 3; nt++) MMA(acc[nt], ah0, ah1, ah2, ah3, bh[nt*2], bh[nt*2+1]);
            #pragma unroll
            for (int nt = 0; nt < 3; nt++) MMA(acc[nt], ah0, ah1, ah2, ah3, bl[nt*2], bl[nt*2+1]);
            #pragma unroll
            for (int nt = 0; nt < 3; nt++) MMA(acc[nt], al0, al1, al2, al3, bh[nt*2], bh[nt*2+1]);
        }
        #pragma unroll
        for (int nt = 0; nt < 3; nt++) {
            int c = nt * 8 + tig * 2;
            sDYf[r0 * 24 + c] = acc[nt][0]; sDYf[r0 * 24 + c + 1] = acc[nt][1];
            sDYf[r1 * 24 + c] = acc[nt][2]; sDYf[r1 * 24 + c + 1] = acc[nt][3];
        }
    };
    auto buildU1 = [&](int d) {       // tangent input u1(d) -> A (W1f = W1L fp32)
        float cq0 = sXF[r0 * 12 + 2 * d], sq0 = sXF[r0 * 12 + 2 * d + 1];
        float cq1 = sXF[r1 * 12 + 2 * d], sq1 = sXF[r1 * 12 + 2 * d + 1];
        #pragma unroll
        for (int nt = 0; nt < 4; nt++) {
            int c = nq * 32 + nt * 8 + tig * 2;
            float2 wa = *(const float2*)&W1f[2 * d * 128 + c];
            float2 wb = *(const float2*)&W1f[(2 * d + 1) * 128 + c];
            storeA(nt,
                sg1[nt][0] * (cq0 * wb.x - sq0 * wa.x),
                sg1[nt][1] * (cq0 * wb.y - sq0 * wa.y),
                sg1[nt][2] * (cq1 * wb.x - sq1 * wa.x),
                sg1[nt][3] * (cq1 * wb.y - sq1 * wa.y));
        }
    };
    auto streamW2 = [&](const float* g) {    // raw row-major 128x128 -> W tiles
        for (int i = tid * 4; i < 16384; i += NTH * 4) {
            float4 v = *(const float4*)&g[i];
            int r = i >> 7, c = i & 127;
            uint32_t h01 = pack2(v.x, v.y), h23 = pack2(v.z, v.w);
            __nv_bfloat162 a01 = *reinterpret_cast<__nv_bfloat162*>(&h01);
            __nv_bfloat162 a23 = *reinterpret_cast<__nv_bfloat162*>(&h23);
            uint32_t l01 = pack2(v.x - __bfloat162float(a01.x), v.y - __bfloat162float(a01.y));
            uint32_t l23 = pack2(v.z - __bfloat162float(a23.x), v.w - __bfloat162float(a23.y));
            *(uint2*)(smc + SB_WH + r * 272 + c * 2) = make_uint2(h01, h23);
            *(uint2*)(smc + SB_WL + r * 272 + c * 2) = make_uint2(l01, l23);
        }
    };
    auto streamW1S = [&](const float* g) {   // layer1 B: [c][t], t padded to 16
        for (int i = tid; i < 2048; i += NTH) {
            int c = i >> 4, t = i & 15;
            float v = (t < 12) ? g[t * 128 + c] : 0.f;
            wsplit2(v, smc + SB_W1R, smc + SB_W1R + 6144, (uint32_t)(c * 48 + t * 2));
        }
    };
    auto streamW1F = [&](const float* g) {
        for (int i = tid; i < 1536; i += NTH) W1f[i] = g[i];
    };

    __syncthreads();
    const float ADT = (2.0f / 3.0f) * 0.02f;

    for (int stage = 0; stage < 2; ++stage) {
        if (tid < TB) {                  // trig features + X tile
            int r = tid;
            #pragma unroll
            for (int i = 0; i < 6; i++) {
                float sv, cv; __sincosf(sQ[r * 6 + i], &sv, &cv);
                sXF[r * 12 + 2 * i] = cv; sXF[r * 12 + 2 * i + 1] = sv;
            }
            #pragma unroll
            for (int t = 0; t < 12; t++)
                wsplit2(sXF[r * 12 + t], smc + SB_XH, smc + SB_XL, (uint32_t)(r * 48 + t * 2));
            XH32[r * 12 + 6] = 0; XH32[r * 12 + 7] = 0;
            XL32[r * 12 + 6] = 0; XL32[r * 12 + 7] = 0;
        }
        streamW2(gW2L);
        streamW1S(gW1L);
        __syncthreads();

        // layer1 L -> h1 (A), sigma1 (regs)
        {
            float acc[4][4]; l1Gemm(acc);
            #pragma unroll
            for (int nt = 0; nt < 4; nt++) {
                int c = nq * 32 + nt * 8 + tig * 2;
                float h0 = softplusf(acc[nt][0] + sB[c]);
                float h1 = softplusf(acc[nt][1] + sB[c + 1]);
                float h2 = softplusf(acc[nt][2] + sB[c]);
                float h3 = softplusf(acc[nt][3] + sB[c + 1]);
                sg1[nt][0] = 1.f - __expf(-h0); sg1[nt][1] = 1.f - __expf(-h1);
                sg1[nt][2] = 1.f - __expf(-h2); sg1[nt][3] = 1.f - __expf(-h3);
                storeA(nt, h0, h1, h2, h3);
            }
        }
        __syncthreads();
        streamW1F(gW1L);                 // W1f := W1L fp32 (split tile dead)
        // h2 = softplus(h1 @ W2L^T + b2L)
        {
            float acc[4][4]; bigGemm(acc, true);
            __syncthreads();
            #pragma unroll
            for (int nt = 0; nt < 4; nt++) {
                int c = nq * 32 + nt * 8 + tig * 2;
                float h0 = softplusf(acc[nt][0] + sB[128 + c]);
                float h1 = softplusf(acc[nt][1] + sB[128 + c + 1]);
                float h2 = softplusf(acc[nt][2] + sB[128 + c]);
                float h3 = softplusf(acc[nt][3] + sB[128 + c + 1]);
                sg2[nt][0] = 1.f - __expf(-h0); sg2[nt][1] = 1.f - __expf(-h1);
                sg2[nt][2] = 1.f - __expf(-h2); sg2[nt][3] = 1.f - __expf(-h3);
                storeA(nt, h0, h1, h2, h3);
            }
        }
        __syncthreads();
        if (nq == 0) miniGemm();         // y -> sDY
        __syncthreads();

        float wv[6], Aacc[6], svec[6], Cacc[6];
        if (tid < TB) {                  // physics init
            int r = tid;
            const float* dy = sDYf + r * 24;
            float Lrl[21], Msl[21];
            #pragma unroll
            for (int t = 0; t < 21; t++) { Lrl[t] = dy[t] + sB[640 + t]; sLr[r * 21 + t] = Lrl[t]; }
            #pragma unroll
            for (int i = 0; i < 6; i++)
                #pragma unroll
                for (int j = 0; j < 6; j++) if (j <= i) {
                    float s2 = 0.f;
                    #pragma unroll
                    for (int k = 0; k < 6; k++) if (k <= j) s2 += Lrl[RO[i] + k] * Lrl[RO[j] + k];
                    if (i == j) s2 += 1e-6f;
                    Msl[RO[i] + j] = s2; sMs[r * 21 + RO[i] + j] = s2;
                }
            #pragma unroll
            for (int i = 0; i < 6; i++) {
                float s2 = 0.f;
                #pragma unroll
                for (int j = 0; j < 6; j++) s2 += MML(i, j) * sQD[r * 6 + j];
                wv[i] = s2; Aacc[i] = 0.f; svec[i] = 0.f;
            }
        }
        buildU1(0);
        __syncthreads();

        // ---- 6 tangent directions ----
        for (int d = 0; d < 6; ++d) {
            {
                float acc[4][4]; bigGemm(acc, true);   // u1 @ W2L^T
                __syncthreads();
                #pragma unroll
                for (int nt = 0; nt < 4; nt++)   // u2 = sigma2 * acc
                    storeA(nt, acc[nt][0] * sg2[nt][0], acc[nt][1] * sg2[nt][1],
                               acc[nt][2] * sg2[nt][2], acc[nt][3] * sg2[nt][3]);
            }
            __syncthreads();
            if (nq == 0) miniGemm();             // dy(d) -> sDY
            if (d == 5) streamW1S(gW1V);         // W1R := W1V split
            __syncthreads();
            if (tid < TB) {                      // physics(d)
                int r = tid;
                const float* dy = sDYf + r * 24;
                const float* Lp = sLr + r * 21;
                float qdr[6];
                #pragma unroll
                for (int j = 0; j < 6; j++) qdr[j] = sQD[r * 6 + j];
                float D6[6][6];
                #pragma unroll
                for (int i = 0; i < 6; i++)
                    #pragma unroll
                    for (int j = 0; j < 6; j++) if (j <= i) {
                        float s2 = 0.f;
                        #pragma unroll
                        for (int k = 0; k < 6; k++) if (k <= j)
                            s2 += dy[RO[i] + k] * Lp[RO[j] + k] + Lp[RO[i] + k] * dy[RO[j] + k];
                        D6[i][j] = s2; D6[j][i] = s2;
                    }
                float qdd = qdr[d], cdot = 0.f;
                #pragma unroll
                for (int i = 0; i < 6; i++) {
                    float v1 = 0.f, v2 = 0.f;
                    #pragma unroll
                    for (int j = 0; j < 6; j++) { v1 += D6[i][j] * wv[j]; v2 += D6[i][j] * qdr[j]; }
                    Aacc[i] += qdd * v1; svec[i] += qdd * v2; cdot += qdr[i] * v1;
                }
                Cacc[d] = cdot;
            }
            if (d < 5) {
                buildU1(d + 1);
            } else {                             // layer1 V -> h1V (A), sigma1V
                float acc[4][4]; l1Gemm(acc);
                #pragma unroll
                for (int nt = 0; nt < 4; nt++) {
                    int c = nq * 32 + nt * 8 + tig * 2;
                    float h0 = softplusf(acc[nt][0] + sB[256 + c]);
                    float h1 = softplusf(acc[nt][1] + sB[256 + c + 1]);
                    float h2 = softplusf(acc[nt][2] + sB[256 + c]);
                    float h3 = softplusf(acc[nt][3] + sB[256 + c + 1]);
                    sg1[nt][0] = 1.f - __expf(-h0); sg1[nt][1] = 1.f - __expf(-h1);
                    sg1[nt][2] = 1.f - __expf(-h2); sg1[nt][3] = 1.f - __expf(-h3);
                    storeA(nt, h0, h1, h2, h3);
                }
            }
            __syncthreads();
        }

        streamW2(gW2V);                          // W := W2V raw (fwd + VJP reuse!)
        streamW1F(gW1V);                         // W1f := W1V fp32
        __syncthreads();
        // h2V ; u2g = sig(h2V)*W3V
        {
            float acc[4][4]; bigGemm(acc, true);
            __syncthreads();
            #pragma unroll
            for (int nt = 0; nt < 4; nt++) {
                int c = nq * 32 + nt * 8 + tig * 2;
                float h0 = softplusf(acc[nt][0] + sB[384 + c]);
                float h1 = softplusf(acc[nt][1] + sB[384 + c + 1]);
                float h2 = softplusf(acc[nt][2] + sB[384 + c]);
                float h3 = softplusf(acc[nt][3] + sB[384 + c + 1]);
                storeA(nt, (1.f - __expf(-h0)) * sB[512 + c],
                           (1.f - __expf(-h1)) * sB[512 + c + 1],
                           (1.f - __expf(-h2)) * sB[512 + c],
                           (1.f - __expf(-h3)) * sB[512 + c + 1]);
            }
        }
        __syncthreads();
        // VJP GEMM (same W tile, non-trans) + gx projection
        {
            float acc[4][4]; bigGemm(acc, false);
            float gx0[12], gx1[12];
            #pragma unroll
            for (int t = 0; t < 12; t++) { gx0[t] = 0.f; gx1[t] = 0.f; }
            #pragma unroll
            for (int nt = 0; nt < 4; nt++) {
                int c = nq * 32 + nt * 8 + tig * 2;
                float u0 = acc[nt][0] * sg1[nt][0], u1 = acc[nt][1] * sg1[nt][1];
                float u2 = acc[nt][2] * sg1[nt][2], u3 = acc[nt][3] * sg1[nt][3];
                #pragma unroll
                for (int t = 0; t < 12; t++) {
                    float2 wv2 = *(const float2*)&W1f[t * 128 + c];
                    gx0[t] += u0 * wv2.x + u1 * wv2.y;
                    gx1[t] += u2 * wv2.x + u3 * wv2.y;
                }
            }
            #pragma unroll
            for (int t = 0; t < 12; t++) {
                gx0[t] += __shfl_xor_sync(0xFFFFFFFF, gx0[t], 1);
                gx0[t] += __shfl_xor_sync(0xFFFFFFFF, gx0[t], 2);
                gx1[t] += __shfl_xor_sync(0xFFFFFFFF, gx1[t], 1);
                gx1[t] += __shfl_xor_sync(0xFFFFFFFF, gx1[t], 2);
            }
            if (tig == 0) {
                #pragma unroll
                for (int t = 0; t < 12; t++) {
                    sGX[r0 * 48 + nq * 12 + t] = gx0[t];
                    sGX[r1 * 48 + nq * 12 + t] = gx1[t];
                }
            }
        }
        __syncthreads();
        // final per-row: cvec, rhs, solves, state update
        if (tid < TB) {
            int r = tid;
            float Msl[21];
            #pragma unroll
            for (int t = 0; t < 21; t++) Msl[t] = sMs[r * 21 + t];
            float cv[6];
            #pragma unroll
            for (int i = 0; i < 6; i++) {
                float ms = 0.f;
                #pragma unroll
                for (int j = 0; j < 6; j++) ms += MML(i, j) * svec[j];
                cv[i] = Aacc[i] + ms - Cacc[i];
            }
            float rhs[6];
            #pragma unroll
            for (int i = 0; i < 6; i++) {
                float g0 = sGX[r * 48 + 2 * i]      + sGX[r * 48 + 12 + 2 * i]
                         + sGX[r * 48 + 24 + 2 * i] + sGX[r * 48 + 36 + 2 * i];
                float g1 = sGX[r * 48 + 2 * i + 1]      + sGX[r * 48 + 12 + 2 * i + 1]
                         + sGX[r * 48 + 24 + 2 * i + 1] + sGX[r * 48 + 36 + 2 * i + 1];
                float dv = -sXF[r * 12 + 2 * i + 1] * g0 + sXF[r * 12 + 2 * i] * g1;
                rhs[i] = sAA[r * 6 + i] - cv[i] - dv;
            }
            float yv[6], zv[6];
            #pragma unroll
            for (int i = 0; i < 6; i++) {
                float s2 = rhs[i];
                #pragma unroll
                for (int j = 0; j < 6; j++) if (j < i) s2 -= Msl[RO[i] + j] * yv[j];
                yv[i] = s2 / Msl[RO[i] + i];
            }
            #pragma unroll
            for (int ii = 5; ii >= 0; ii--) {
                float s2 = yv[ii];
                #pragma unroll
                for (int j = 0; j < 6; j++) if (j > ii) s2 -= Msl[RO[j] + ii] * zv[j];
                zv[ii] = s2 / Msl[RO[ii] + ii];
            }
            if (stage == 0) {
                #pragma unroll
                for (int i = 0; i < 6; i++) {
                    k1v[i] = zv[i];
                    float qdi = sQD[r * 6 + i];
                    sQ[r * 6 + i] += ADT * qdi;
                    sQD[r * 6 + i] = qdi + ADT * zv[i];
                }
            } else {
                #pragma unroll
                for (int i = 0; i < 6; i++) k2v[i] = zv[i];
            }
        }
        __syncthreads();
    }

    // ---- output ----
    if (tid < TB && base + tid < B) {
        int g = base + tid, r = tid;
        #pragma unroll
        for (int i = 0; i < 6; i++)
            outp[g * 18 + i] = o[g * 18 + i]
                + 0.02f * (0.25f * o[g * 18 + 6 + i] + 0.75f * sQD[r * 6 + i]);
        #pragma unroll
        for (int i = 0; i < 6; i++)
            outp[g * 18 + 6 + i] = o[g * 18 + 6 + i]
                + 0.02f * (0.25f * k1v[i] + 0.75f * k2v[i]);
        #pragma unroll
        for (int i = 0; i < 6; i++)
            outp[g * 18 + 12 + i] = o[g * 18 + 12 + i];
    }
}

extern "C" void kernel_launch(void* const* d_in, const int* in_sizes, int n_in,
                              void* d_out, int out_size) {
    const float* o   = (const float*)d_in[0];
    const float* a   = (const float*)d_in[1];
    const float* W1L = (const float*)d_in[2];
    const float* b1L = (const float*)d_in[3];
    const float* W2L = (const float*)d_in[4];
    const float* b2L = (const float*)d_in[5];
    const float* W3L = (const float*)d_in[6];
    const float* b3L = (const float*)d_in[7];
    const float* W1V = (const float*)d_in[8];
    const float* b1V = (const float*)d_in[9];
    const float* W2V = (const float*)d_in[10];
    const float* b2V = (const float*)d_in[11];
    const float* W3V = (const float*)d_in[12];
    float* outp = (float*)d_out;

    int B = in_sizes[0] / 18;
    int grid = (B + TB - 1) / TB;
    cudaFuncSetAttribute(lnn_mma,
                         cudaFuncAttributeMaxDynamicSharedMemorySize, SB_END);
    lnn_mma<<<grid, NTH, SB_END>>>(o, a, W1L, b1L, W2L, b2L, W3L, b3L,
                                   W1V, b1V, W2V, b2V, W3V, outp, B);
}

// round 15
// speedup vs baseline: 2.6705x; 1.0351x over previous
#include <cuda_runtime.h>
#include <cuda_bf16.h>
#include <cstdint>
#include <math.h>

#define NTH 512
#define TB  64

// ---- smem byte offsets ----
#define SB_XAH 0        // X activation buffer hi (64 x 272B)
#define SB_XAL 17408
#define SB_YAH 34816    // Y activation buffer hi
#define SB_YAL 52224
#define SB_WH  69632
#define SB_WL  104448
#define SB_W3H 139264
#define SB_W3L 145408
#define SB_W1R 151552
#define SB_XH  163840
#define SB_XL  166912
#define SB_DY  169984
#define SB_GX  176128
#define SB_XF  188416
#define SB_Q   191488
#define SB_QD  193024
#define SB_AA  194560
#define SB_LR  196096
#define SB_MS  201472
#define SB_B   206848
#define SB_END 209504

#define MMA(acc,a0,a1,a2,a3,b0,b1) \
  asm volatile("mma.sync.aligned.m16n8k16.row.col.f32.bf16.bf16.f32 " \
    "{%0,%1,%2,%3},{%4,%5,%6,%7},{%8,%9},{%0,%1,%2,%3};" \
    : "+f"(acc[0]),"+f"(acc[1]),"+f"(acc[2]),"+f"(acc[3]) \
    : "r"(a0),"r"(a1),"r"(a2),"r"(a3),"r"(b0),"r"(b1))

__device__ __forceinline__ void ldsm4(uint32_t& d0, uint32_t& d1, uint32_t& d2,
                                      uint32_t& d3, uint32_t addr) {
    asm volatile("ldmatrix.sync.aligned.m8n8.x4.shared.b16 {%0,%1,%2,%3},[%4];"
        : "=r"(d0), "=r"(d1), "=r"(d2), "=r"(d3) : "r"(addr));
}
__device__ __forceinline__ void ldsm4t(uint32_t& d0, uint32_t& d1, uint32_t& d2,
                                       uint32_t& d3, uint32_t addr) {
    asm volatile("ldmatrix.sync.aligned.m8n8.x4.trans.shared.b16 {%0,%1,%2,%3},[%4];"
        : "=r"(d0), "=r"(d1), "=r"(d2), "=r"(d3) : "r"(addr));
}
__device__ __forceinline__ void ldsm2t(uint32_t& d0, uint32_t& d1, uint32_t addr) {
    asm volatile("ldmatrix.sync.aligned.m8n8.x2.trans.shared.b16 {%0,%1},[%2];"
        : "=r"(d0), "=r"(d1) : "r"(addr));
}

static __device__ __forceinline__ float softplusf(float z) {
    return fmaxf(z, 0.0f) + __logf(1.0f + __expf(-fabsf(z)));
}
static __device__ __forceinline__ uint32_t pack2(float a, float b) {
    __nv_bfloat162 t = __floats2bfloat162_rn(a, b);
    return *reinterpret_cast<uint32_t*>(&t);
}
static __device__ __forceinline__ void wsplit2(float v, char* hi, char* lo, uint32_t off) {
    __nv_bfloat16 h = __float2bfloat16(v);
    *(__nv_bfloat16*)(hi + off) = h;
    *(__nv_bfloat16*)(lo + off) = __float2bfloat16(v - __bfloat162float(h));
}

extern "C" __global__ void __launch_bounds__(NTH, 1)
lnn_mma(const float* __restrict__ o,    const float* __restrict__ ain,
        const float* __restrict__ gW1L, const float* __restrict__ gb1L,
        const float* __restrict__ gW2L, const float* __restrict__ gb2L,
        const float* __restrict__ gW3L, const float* __restrict__ gb3L,
        const float* __restrict__ gW1V, const float* __restrict__ gb1V,
        const float* __restrict__ gW2V, const float* __restrict__ gb2V,
        const float* __restrict__ gW3V,
        float* __restrict__ outp, int B)
{
    extern __shared__ char smc[];
    uint32_t* XH32 = (uint32_t*)(smc + SB_XH);
    uint32_t* XL32 = (uint32_t*)(smc + SB_XL);
    float* W1f  = (float*)(smc + SB_W1R);
    float* sDYf = (float*)(smc + SB_DY);
    float* sGX  = (float*)(smc + SB_GX);
    float* sXF  = (float*)(smc + SB_XF);
    float* sQ   = (float*)(smc + SB_Q);
    float* sQD  = (float*)(smc + SB_QD);
    float* sAA  = (float*)(smc + SB_AA);
    float* sLr  = (float*)(smc + SB_LR);
    float* sMs  = (float*)(smc + SB_MS);
    float* sB   = (float*)(smc + SB_B);

    const int tid = threadIdx.x, w = tid >> 5, lane = tid & 31;
    const int gid = lane >> 2, tig = lane & 3;
    const int mt = w & 3, nq = w >> 2;
    const int r0 = mt * 16 + gid, r1 = r0 + 8;
    const int base = blockIdx.x * TB;
    const int RO[6] = {0, 1, 3, 6, 10, 15};
    #define MML(i,j) ((i)>=(j) ? Msl[RO[i]+(j)] : Msl[RO[j]+(i)])

    const uint32_t sbs = (uint32_t)__cvta_generic_to_shared(smc);
    // A fragment base (add buffer offset SB_XAH/SB_YAH)
    const int rowA = mt * 16 + (lane & 7) + ((lane >> 3) & 1) * 8;
    const int colA = (lane >> 4) * 16;
    const uint32_t aFrag = sbs + rowA * 272 + colA;
    // forward B fragments (TRANS, raw [k][n])
    const int rowK = (lane & 7) + ((lane >> 3) & 1) * 8;
    const int colT = (lane >> 4) * 16;
    const uint32_t bTH = sbs + SB_WH + rowK * 272 + nq * 64 + colT;
    const uint32_t bTL = sbs + SB_WL + rowK * 272 + nq * 64 + colT;
    // VJP B fragments (non-trans, same raw tile)
    const int rowBl = (lane & 7) + ((lane >> 4) << 3);
    const int colB  = ((lane >> 3) & 1) * 16;
    const uint32_t bVH0 = sbs + SB_WH + (nq * 32 + rowBl) * 272 + colB;
    const uint32_t bVH1 = bVH0 + 16 * 272;
    const uint32_t bVL0 = sbs + SB_WL + (nq * 32 + rowBl) * 272 + colB;
    const uint32_t bVL1 = bVL0 + 16 * 272;
    // mini W3 (raw [c][t], TRANS)
    const uint32_t mTH = sbs + SB_W3H + rowK * 48 + colT;
    const uint32_t mTL = sbs + SB_W3L + rowK * 48 + colT;
    const uint32_t mTH2 = sbs + SB_W3H + rowK * 48 + 32;
    const uint32_t mTL2 = sbs + SB_W3L + rowK * 48 + 32;
    // layer1
    const uint32_t xAddrH = sbs + SB_XH + rowA * 48 + colA;
    const uint32_t xAddrL = sbs + SB_XL + rowA * 48 + colA;
    const uint32_t uAddrH0 = sbs + SB_W1R + (nq * 32 + rowBl) * 48 + colB;
    const uint32_t uAddrH1 = uAddrH0 + 16 * 48;
    const uint32_t uAddrL0 = uAddrH0 + 6144;
    const uint32_t uAddrL1 = uAddrH1 + 6144;

    // persistent loads
    for (int i = tid; i < 128; i += NTH) {
        sB[i] = gb1L[i]; sB[128 + i] = gb2L[i];
        sB[256 + i] = gb1V[i]; sB[384 + i] = gb2V[i]; sB[512 + i] = gW3V[i];
    }
    if (tid < 24) sB[640 + tid] = tid < 21 ? gb3L[tid] : 0.f;
    for (int i = tid; i < 3072; i += NTH) {     // W3 raw tile [c][t]
        int c = i / 24, t = i - c * 24;
        float v = (t < 21) ? gW3L[c * 21 + t] : 0.f;
        wsplit2(v, smc + SB_W3H, smc + SB_W3L, (uint32_t)(c * 48 + t * 2));
    }
    for (int i = tid; i < TB * 6; i += NTH) {
        int r = i / 6, c = i - 6 * r;
        int g = base + r; if (g > B - 1) g = B - 1;
        sQ[i] = o[g * 18 + c]; sQD[i] = o[g * 18 + 6 + c]; sAA[i] = ain[g * 6 + c];
    }

    float sg1[4][4], sg2[4][4], k1v[6], k2v[6];
    float wv[6], Aacc[6], svec[6], Cacc[6];

    // ---- helpers ----
    auto storeA = [&](uint32_t bufOff, int nt, float v0, float v1, float v2, float v3) {
        uint32_t* H = (uint32_t*)(smc + bufOff);
        uint32_t* L = (uint32_t*)(smc + bufOff + 17408);
        int ci = nq * 16 + nt * 4 + tig;
        uint32_t h01 = pack2(v0, v1);
        __nv_bfloat162 hh = *reinterpret_cast<__nv_bfloat162*>(&h01);
        H[r0 * 68 + ci] = h01;
        L[r0 * 68 + ci] = pack2(v0 - __bfloat162float(hh.x), v1 - __bfloat162float(hh.y));
        uint32_t h23 = pack2(v2, v3);
        __nv_bfloat162 hh2 = *reinterpret_cast<__nv_bfloat162*>(&h23);
        H[r1 * 68 + ci] = h23;
        L[r1 * 68 + ci] = pack2(v2 - __bfloat162float(hh2.x), v3 - __bfloat162float(hh2.y));
    };
    auto bigGemm = [&](float (&acc)[4][4], bool fwd, uint32_t aOff) {
        const uint32_t aH = aFrag + aOff, aL = aFrag + aOff + 17408;
        #pragma unroll
        for (int nt = 0; nt < 4; nt++)
            acc[nt][0] = acc[nt][1] = acc[nt][2] = acc[nt][3] = 0.f;
        #pragma unroll
        for (int kt = 0; kt < 8; kt++) {
            uint32_t ah0, ah1, ah2, ah3, al0, al1, al2, al3;
            ldsm4(ah0, ah1, ah2, ah3, aH + kt * 32);
            ldsm4(al0, al1, al2, al3, aL + kt * 32);
            uint32_t bh[8], bl[8];
            if (fwd) {
                ldsm4t(bh[0], bh[1], bh[2], bh[3], bTH + kt * 4352);
                ldsm4t(bh[4], bh[5], bh[6], bh[7], bTH + kt * 4352 + 32);
                ldsm4t(bl[0], bl[1], bl[2], bl[3], bTL + kt * 4352);
                ldsm4t(bl[4], bl[5], bl[6], bl[7], bTL + kt * 4352 + 32);
            } else {
                ldsm4(bh[0], bh[1], bh[2], bh[3], bVH0 + kt * 32);
                ldsm4(bh[4], bh[5], bh[6], bh[7], bVH1 + kt * 32);
                ldsm4(bl[0], bl[1], bl[2], bl[3], bVL0 + kt * 32);
                ldsm4(bl[4], bl[5], bl[6], bl[7], bVL1 + kt * 32);
            }
            #pragma unroll
            for (int nt = 0; nt < 4; nt++) MMA(acc[nt], ah0, ah1, ah2, ah3, bh[nt*2], bh[nt*2+1]);
            #pragma unroll
            for (int nt = 0; nt < 4; nt++) MMA(acc[nt], ah0, ah1, ah2, ah3, bl[nt*2], bl[nt*2+1]);
            #pragma unroll
            for (int nt = 0; nt < 4; nt++) MMA(acc[nt], al0, al1, al2, al3, bh[nt*2], bh[nt*2+1]);
        }
    };
    auto l1Gemm = [&](float (&acc)[4][4]) {
        uint32_t ah0, ah1, ah2, ah3, al0, al1, al2, al3;
        ldsm4(ah0, ah1, ah2, ah3, xAddrH);
        ldsm4(al0, al1, al2, al3, xAddrL);
        uint32_t bh[8], bl[8];
        ldsm4(bh[0], bh[1], bh[2], bh[3], uAddrH0);
        ldsm4(bh[4], bh[5], bh[6], bh[7], uAddrH1);
        ldsm4(bl[0], bl[1], bl[2], bl[3], uAddrL0);
        ldsm4(bl[4], bl[5], bl[6], bl[7], uAddrL1);
        #pragma unroll
        for (int nt = 0; nt < 4; nt++)
            acc[nt][0] = acc[nt][1] = acc[nt][2] = acc[nt][3] = 0.f;
        #pragma unroll
        for (int nt = 0; nt < 4; nt++) MMA(acc[nt], ah0, ah1, ah2, ah3, bh[nt*2], bh[nt*2+1]);
        #pragma unroll
        for (int nt = 0; nt < 4; nt++) MMA(acc[nt], ah0, ah1, ah2, ah3, bl[nt*2], bl[nt*2+1]);
        #pragma unroll
        for (int nt = 0; nt < 4; nt++) MMA(acc[nt], al0, al1, al2, al3, bh[nt*2], bh[nt*2+1]);
    };
    auto miniGemm = [&]() {           // nq==0 warps; A from Y buffer
        const uint32_t aH = aFrag + SB_YAH, aL = aFrag + SB_YAH + 17408;
        float acc[3][4];
        #pragma unroll
        for (int nt = 0; nt < 3; nt++)
            acc[nt][0] = acc[nt][1] = acc[nt][2] = acc[nt][3] = 0.f;
        #pragma unroll
        for (int kt = 0; kt < 8; kt++) {
            uint32_t ah0, ah1, ah2, ah3, al0, al1, al2, al3;
            ldsm4(ah0, ah1, ah2, ah3, aH + kt * 32);
            ldsm4(al0, al1, al2, al3, aL + kt * 32);
            uint32_t bh[6], bl[6];
            ldsm4t(bh[0], bh[1], bh[2], bh[3], mTH + kt * 768);
            ldsm2t(bh[4], bh[5], mTH2 + kt * 768);
            ldsm4t(bl[0], bl[1], bl[2], bl[3], mTL + kt * 768);
            ldsm2t(bl[4], bl[5], mTL2 + kt * 768);
            #pragma unroll
            for (int nt = 0; nt < 3; nt++) MMA(acc[nt], ah0, ah1, ah2, ah3, bh[nt*2], bh[nt*2+1]);
            #pragma unroll
            for (int nt = 0; nt < 3; nt++) MMA(acc[nt], ah0, ah1, ah2, ah3, bl[nt*2], bl[nt*2+1]);
            #pragma unroll
            for (int nt = 0; nt < 3; nt++) MMA(acc[nt], al0, al1, al2, al3, bh[nt*2], bh[nt*2+1]);
        }
        #pragma unroll
        for (int nt = 0; nt < 3; nt++) {
            int c = nt * 8 + tig * 2;
            sDYf[r0 * 24 + c] = acc[nt][0]; sDYf[r0 * 24 + c + 1] = acc[nt][1];
            sDYf[r1 * 24 + c] = acc[nt][2]; sDYf[r1 * 24 + c + 1] = acc[nt][3];
        }
    };
    auto buildU1 = [&](int d) {       // u1(d) -> X buffer
        float cq0 = sXF[r0 * 12 + 2 * d], sq0 = sXF[r0 * 12 + 2 * d + 1];
        float cq1 = sXF[r1 * 12 + 2 * d], sq1 = sXF[r1 * 12 + 2 * d + 1];
        #pragma unroll
        for (int nt = 0; nt < 4; nt++) {
            int c = nq * 32 + nt * 8 + tig * 2;
            float2 wa = *(const float2*)&W1f[2 * d * 128 + c];
            float2 wb = *(const float2*)&W1f[(2 * d + 1) * 128 + c];
            storeA(SB_XAH, nt,
                sg1[nt][0] * (cq0 * wb.x - sq0 * wa.x),
                sg1[nt][1] * (cq0 * wb.y - sq0 * wa.y),
                sg1[nt][2] * (cq1 * wb.x - sq1 * wa.x),
                sg1[nt][3] * (cq1 * wb.y - sq1 * wa.y));
        }
    };
    auto physicsStep = [&](int d) {   // tid < 64 only
        int r = tid;
        const float* dy = sDYf + r * 24;
        const float* Lp = sLr + r * 21;
        float qdr[6];
        #pragma unroll
        for (int j = 0; j < 6; j++) qdr[j] = sQD[r * 6 + j];
        float D6[6][6];
        #pragma unroll
        for (int i = 0; i < 6; i++)
            #pragma unroll
            for (int j = 0; j < 6; j++) if (j <= i) {
                float s2 = 0.f;
                #pragma unroll
                for (int k = 0; k < 6; k++) if (k <= j)
                    s2 += dy[RO[i] + k] * Lp[RO[j] + k] + Lp[RO[i] + k] * dy[RO[j] + k];
                D6[i][j] = s2; D6[j][i] = s2;
            }
        float qdd = qdr[d], cdot = 0.f;
        #pragma unroll
        for (int i = 0; i < 6; i++) {
            float v1 = 0.f, v2 = 0.f;
            #pragma unroll
            for (int j = 0; j < 6; j++) { v1 += D6[i][j] * wv[j]; v2 += D6[i][j] * qdr[j]; }
            Aacc[i] += qdd * v1; svec[i] += qdd * v2; cdot += qdr[i] * v1;
        }
        Cacc[d] = cdot;
    };
    auto streamW2body = [&](const float* g, int t, int nt) {
        for (int i = t * 4; i < 16384; i += nt * 4) {
            float4 v = *(const float4*)&g[i];
            int r = i >> 7, c = i & 127;
            uint32_t h01 = pack2(v.x, v.y), h23 = pack2(v.z, v.w);
            __nv_bfloat162 a01 = *reinterpret_cast<__nv_bfloat162*>(&h01);
            __nv_bfloat162 a23 = *reinterpret_cast<__nv_bfloat162*>(&h23);
            uint32_t l01 = pack2(v.x - __bfloat162float(a01.x), v.y - __bfloat162float(a01.y));
            uint32_t l23 = pack2(v.z - __bfloat162float(a23.x), v.w - __bfloat162float(a23.y));
            *(uint2*)(smc + SB_WH + r * 272 + c * 2) = make_uint2(h01, h23);
            *(uint2*)(smc + SB_WL + r * 272 + c * 2) = make_uint2(l01, l23);
        }
    };
    auto streamW1Sbody = [&](const float* g, int t, int nt) {
        for (int i = t; i < 2048; i += nt) {
            int c = i >> 4, tt = i & 15;
            float v = (tt < 12) ? g[tt * 128 + c] : 0.f;
            wsplit2(v, smc + SB_W1R, smc + SB_W1R + 6144, (uint32_t)(c * 48 + tt * 2));
        }
    };
    auto streamW1F = [&](const float* g) {
        for (int i = tid; i < 1536; i += NTH) W1f[i] = g[i];
    };

    __syncthreads();
    const float ADT = (2.0f / 3.0f) * 0.02f;

    for (int stage = 0; stage < 2; ++stage) {
        // head: trig + streams
        if (tid < TB) {
            int r = tid;
            #pragma unroll
            for (int i = 0; i < 6; i++) {
                float sv, cv; __sincosf(sQ[r * 6 + i], &sv, &cv);
                sXF[r * 12 + 2 * i] = cv; sXF[r * 12 + 2 * i + 1] = sv;
            }
            #pragma unroll
            for (int t = 0; t < 12; t++)
                wsplit2(sXF[r * 12 + t], smc + SB_XH, smc + SB_XL, (uint32_t)(r * 48 + t * 2));
            XH32[r * 12 + 6] = 0; XH32[r * 12 + 7] = 0;
            XL32[r * 12 + 6] = 0; XL32[r * 12 + 7] = 0;
        }
        streamW2body(gW2L, tid, NTH);
        streamW1Sbody(gW1L, tid, NTH);
        __syncthreads();

        // layer1 L -> h1 (X), sigma1 (regs)
        {
            float acc[4][4]; l1Gemm(acc);
            #pragma unroll
            for (int nt = 0; nt < 4; nt++) {
                int c = nq * 32 + nt * 8 + tig * 2;
                float h0 = softplusf(acc[nt][0] + sB[c]);
                float h1 = softplusf(acc[nt][1] + sB[c + 1]);
                float h2 = softplusf(acc[nt][2] + sB[c]);
                float h3 = softplusf(acc[nt][3] + sB[c + 1]);
                sg1[nt][0] = 1.f - __expf(-h0); sg1[nt][1] = 1.f - __expf(-h1);
                sg1[nt][2] = 1.f - __expf(-h2); sg1[nt][3] = 1.f - __expf(-h3);
                storeA(SB_XAH, nt, h0, h1, h2, h3);
            }
        }
        __syncthreads();
        streamW1F(gW1L);                          // W1f := W1L fp32
        // h2 = softplus(h1 @ W2L^T + b2L) -> Y, sigma2 regs
        {
            float acc[4][4]; bigGemm(acc, true, SB_XAH);
            #pragma unroll
            for (int nt = 0; nt < 4; nt++) {
                int c = nq * 32 + nt * 8 + tig * 2;
                float h0 = softplusf(acc[nt][0] + sB[128 + c]);
                float h1 = softplusf(acc[nt][1] + sB[128 + c + 1]);
                float h2 = softplusf(acc[nt][2] + sB[128 + c]);
                float h3 = softplusf(acc[nt][3] + sB[128 + c + 1]);
                sg2[nt][0] = 1.f - __expf(-h0); sg2[nt][1] = 1.f - __expf(-h1);
                sg2[nt][2] = 1.f - __expf(-h2); sg2[nt][3] = 1.f - __expf(-h3);
                storeA(SB_YAH, nt, h0, h1, h2, h3);
            }
        }
        __syncthreads();
        if (nq == 0) miniGemm();                  // y -> sDY (reads Y)
        buildU1(0);                               // u1(0) -> X
        __syncthreads();

        // ---- 6 tangent directions ----
        for (int d = 0; d < 6; ++d) {
            if (tid < TB) {
                if (d == 0) {                     // physics init (reads y)
                    int r = tid;
                    const float* dy = sDYf + r * 24;
                    float Lrl[21], Msl[21];
                    #pragma unroll
                    for (int t = 0; t < 21; t++) { Lrl[t] = dy[t] + sB[640 + t]; sLr[r * 21 + t] = Lrl[t]; }
                    #pragma unroll
                    for (int i = 0; i < 6; i++)
                        #pragma unroll
                        for (int j = 0; j < 6; j++) if (j <= i) {
                            float s2 = 0.f;
                            #pragma unroll
                            for (int k = 0; k < 6; k++) if (k <= j) s2 += Lrl[RO[i] + k] * Lrl[RO[j] + k];
                            if (i == j) s2 += 1e-6f;
                            Msl[RO[i] + j] = s2; sMs[r * 21 + RO[i] + j] = s2;
                        }
                    #pragma unroll
                    for (int i = 0; i < 6; i++) {
                        float s2 = 0.f;
                        #pragma unroll
                        for (int j = 0; j < 6; j++) s2 += MML(i, j) * sQD[r * 6 + j];
                        wv[i] = s2; Aacc[i] = 0.f; svec[i] = 0.f;
                    }
                } else {
                    physicsStep(d - 1);
                }
            }
            {
                float acc[4][4]; bigGemm(acc, true, SB_XAH);  // u1 @ W2L^T
                #pragma unroll
                for (int nt = 0; nt < 4; nt++)                // u2 -> Y (no sync needed)
                    storeA(SB_YAH, nt, acc[nt][0] * sg2[nt][0], acc[nt][1] * sg2[nt][1],
                           acc[nt][2] * sg2[nt][2], acc[nt][3] * sg2[nt][3]);
            }
            __syncthreads();
            if (nq == 0) miniGemm();                          // dy(d) (reads Y)
            if (d < 5) {
                buildU1(d + 1);                               // -> X
            } else if (nq != 0) {                             // stream V weights
                streamW2body(gW2V, tid - 128, NTH - 128);
                streamW1Sbody(gW1V, tid - 128, NTH - 128);
            }
            __syncthreads();
        }

        // tail: physics(5), layer1 V
        if (tid < TB) physicsStep(5);
        {
            float acc[4][4]; l1Gemm(acc);                     // W1R = W1V split
            #pragma unroll
            for (int nt = 0; nt < 4; nt++) {
                int c = nq * 32 + nt * 8 + tig * 2;
                float h0 = softplusf(acc[nt][0] + sB[256 + c]);
                float h1 = softplusf(acc[nt][1] + sB[256 + c + 1]);
                float h2 = softplusf(acc[nt][2] + sB[256 + c]);
                float h3 = softplusf(acc[nt][3] + sB[256 + c + 1]);
                sg1[nt][0] = 1.f - __expf(-h0); sg1[nt][1] = 1.f - __expf(-h1);
                sg1[nt][2] = 1.f - __expf(-h2); sg1[nt][3] = 1.f - __expf(-h3);
                storeA(SB_XAH, nt, h0, h1, h2, h3);           // h1V -> X
            }
        }
        __syncthreads();
        streamW1F(gW1V);                                      // W1f := W1V fp32
        // h2V -> u2g (Y)
        {
            float acc[4][4]; bigGemm(acc, true, SB_XAH);
            #pragma unroll
            for (int nt = 0; nt < 4; nt++) {
                int c = nq * 32 + nt * 8 + tig * 2;
                float h0 = softplusf(acc[nt][0] + sB[384 + c]);
                float h1 = softplusf(acc[nt][1] + sB[384 + c + 1]);
                float h2 = softplusf(acc[nt][2] + sB[384 + c]);
                float h3 = softplusf(acc[nt][3] + sB[384 + c + 1]);
                storeA(SB_YAH, nt, (1.f - __expf(-h0)) * sB[512 + c],
                       (1.f - __expf(-h1)) * sB[512 + c + 1],
                       (1.f - __expf(-h2)) * sB[512 + c],
                       (1.f - __expf(-h3)) * sB[512 + c + 1]);
            }
        }
        __syncthreads();
        // VJP GEMM (A from Y, non-trans B) + gx projection
        {
            float acc[4][4]; bigGemm(acc, false, SB_YAH);
            float gx0[12], gx1[12];
            #pragma unroll
            for (int t = 0; t < 12; t++) { gx0[t] = 0.f; gx1[t] = 0.f; }
            #pragma unroll
            for (int nt = 0; nt < 4; nt++) {
                int c = nq * 32 + nt * 8 + tig * 2;
                float u0 = acc[nt][0] * sg1[nt][0], u1 = acc[nt][1] * sg1[nt][1];
                float u2 = acc[nt][2] * sg1[nt][2], u3 = acc[nt][3] * sg1[nt][3];
                #pragma unroll
                for (int t = 0; t < 12; t++) {
                    float2 wv2 = *(const float2*)&W1f[t * 128 + c];
                    gx0[t] += u0 * wv2.x + u1 * wv2.y;
                    gx1[t] += u2 * wv2.x + u3 * wv2.y;
                }
            }
            #pragma unroll
            for (int t = 0; t < 12; t++) {
                gx0[t] += __shfl_xor_sync(0xFFFFFFFF, gx0[t], 1);
                gx0[t] += __shfl_xor_sync(0xFFFFFFFF, gx0[t], 2);
                gx1[t] += __shfl_xor_sync(0xFFFFFFFF, gx1[t], 1);
                gx1[t] += __shfl_xor_sync(0xFFFFFFFF, gx1[t], 2);
            }
            if (tig == 0) {
                #pragma unroll
                for (int t = 0; t < 12; t++) {
                    sGX[r0 * 48 + nq * 12 + t] = gx0[t];
                    sGX[r1 * 48 + nq * 12 + t] = gx1[t];
                }
            }
        }
        __syncthreads();
        // final per-row: cvec, rhs, solves, state update
        if (tid < TB) {
            int r = tid;
            float Msl[21];
            #pragma unroll
            for (int t = 0; t < 21; t++) Msl[t] = sMs[r * 21 + t];
            float cv[6];
            #pragma unroll
            for (int i = 0; i < 6; i++) {
                float ms = 0.f;
                #pragma unroll
                for (int j = 0; j < 6; j++) ms += MML(i, j) * svec[j];
                cv[i] = Aacc[i] + ms - Cacc[i];
            }
            float rhs[6];
            #pragma unroll
            for (int i = 0; i < 6; i++) {
                float g0 = sGX[r * 48 + 2 * i]      + sGX[r * 48 + 12 + 2 * i]
                         + sGX[r * 48 + 24 + 2 * i] + sGX[r * 48 + 36 + 2 * i];
                float g1 = sGX[r * 48 + 2 * i + 1]      + sGX[r * 48 + 12 + 2 * i + 1]
                         + sGX[r * 48 + 24 + 2 * i + 1] + sGX[r * 48 + 36 + 2 * i + 1];
                float dv = -sXF[r * 12 + 2 * i + 1] * g0 + sXF[r * 12 + 2 * i] * g1;
                rhs[i] = sAA[r * 6 + i] - cv[i] - dv;
            }
            float yv[6], zv[6];
            #pragma unroll
            for (int i = 0; i < 6; i++) {
                float s2 = rhs[i];
                #pragma unroll
                for (int j = 0; j < 6; j++) if (j < i) s2 -= Msl[RO[i] + j] * yv[j];
                yv[i] = s2 / Msl[RO[i] + i];
            }
            #pragma unroll
            for (int ii = 5; ii >= 0; ii--) {
                float s2 = yv[ii];
                #pragma unroll
                for (int j = 0; j < 6; j++) if (j > ii) s2 -= Msl[RO[j] + ii] * zv[j];
                zv[ii] = s2 / Msl[RO[ii] + ii];
            }
            if (stage == 0) {
                #pragma unroll
                for (int i = 0; i < 6; i++) {
                    k1v[i] = zv[i];
                    float qdi = sQD[r * 6 + i];
                    sQ[r * 6 + i] += ADT * qdi;
                    sQD[r * 6 + i] = qdi + ADT * zv[i];
                }
            } else {
                #pragma unroll
                for (int i = 0; i < 6; i++) k2v[i] = zv[i];
            }
        }
        __syncthreads();
    }

    // ---- output ----
    if (tid < TB && base + tid < B) {
        int g = base + tid, r = tid;
        #pragma unroll
        for (int i = 0; i < 6; i++)
            outp[g * 18 + i] = o[g * 18 + i]
                + 0.02f * (0.25f * o[g * 18 + 6 + i] + 0.75f * sQD[r * 6 + i]);
        #pragma unroll
        for (int i = 0; i < 6; i++)
            outp[g * 18 + 6 + i] = o[g * 18 + 6 + i]
                + 0.02f * (0.25f * k1v[i] + 0.75f * k2v[i]);
        #pragma unroll
        for (int i = 0; i < 6; i++)
            outp[g * 18 + 12 + i] = o[g * 18 + 12 + i];
    }
}

extern "C" void kernel_launch(void* const* d_in, const int* in_sizes, int n_in,
                              void* d_out, int out_size) {
    const float* o   = (const float*)d_in[0];
    const float* a   = (const float*)d_in[1];
    const float* W1L = (const float*)d_in[2];
    const float* b1L = (const float*)d_in[3];
    const float* W2L = (const float*)d_in[4];
    const float* b2L = (const float*)d_in[5];
    const float* W3L = (const float*)d_in[6];
    const float* b3L = (const float*)d_in[7];
    const float* W1V = (const float*)d_in[8];
    const float* b1V = (const float*)d_in[9];
    const float* W2V = (const float*)d_in[10];
    const float* b2V = (const float*)d_in[11];
    const float* W3V = (const float*)d_in[12];
    float* outp = (float*)d_out;

    int B = in_sizes[0] / 18;
    int grid = (B + TB - 1) / TB;
    cudaFuncSetAttribute(lnn_mma,
                         cudaFuncAttributeMaxDynamicSharedMemorySize, SB_END);
    lnn_mma<<<grid, NTH, SB_END>>>(o, a, W1L, b1L, W2L, b2L, W3L, b3L,
                                   W1V, b1V, W2V, b2V, W3V, outp, B);
}

// round 16
// speedup vs baseline: 2.6852x; 1.0055x over previous
#include <cuda_runtime.h>
#include <cuda_bf16.h>
#include <cstdint>
#include <math.h>

#define NTH 512
#define TB  64

// ---- smem byte offsets ----
#define SB_XAH 0        // X activation buffer hi (64 x 272B)
#define SB_XAL 17408
#define SB_YAH 34816    // Y activation buffer hi
#define SB_YAL 52224
#define SB_WH  69632
#define SB_WL  104448
#define SB_W3H 139264
#define SB_W3L 145408
#define SB_W1R 151552
#define SB_XH  163840
#define SB_XL  166912
#define SB_DY  169984   // 64 x 25 f32 (padded, conflict-free)
#define SB_GX  176384   // 64 x 49 f32
#define SB_XF  188928   // 64 x 13 f32
#define SB_Q   192256   // 64 x 7 f32
#define SB_QD  194048
#define SB_AA  195840
#define SB_LR  197632   // 64 x 21 f32
#define SB_MS  203008
#define SB_B   208384
#define SB_END 211040

#define MMA(acc,a0,a1,a2,a3,b0,b1) \
  asm volatile("mma.sync.aligned.m16n8k16.row.col.f32.bf16.bf16.f32 " \
    "{%0,%1,%2,%3},{%4,%5,%6,%7},{%8,%9},{%0,%1,%2,%3};" \
    : "+f"(acc[0]),"+f"(acc[1]),"+f"(acc[2]),"+f"(acc[3]) \
    : "r"(a0),"r"(a1),"r"(a2),"r"(a3),"r"(b0),"r"(b1))

__device__ __forceinline__ void ldsm4(uint32_t& d0, uint32_t& d1, uint32_t& d2,
                                      uint32_t& d3, uint32_t addr) {
    asm volatile("ldmatrix.sync.aligned.m8n8.x4.shared.b16 {%0,%1,%2,%3},[%4];"
        : "=r"(d0), "=r"(d1), "=r"(d2), "=r"(d3) : "r"(addr));
}
__device__ __forceinline__ void ldsm4t(uint32_t& d0, uint32_t& d1, uint32_t& d2,
                                       uint32_t& d3, uint32_t addr) {
    asm volatile("ldmatrix.sync.aligned.m8n8.x4.trans.shared.b16 {%0,%1,%2,%3},[%4];"
        : "=r"(d0), "=r"(d1), "=r"(d2), "=r"(d3) : "r"(addr));
}
__device__ __forceinline__ void ldsm2t(uint32_t& d0, uint32_t& d1, uint32_t addr) {
    asm volatile("ldmatrix.sync.aligned.m8n8.x2.trans.shared.b16 {%0,%1},[%2];"
        : "=r"(d0), "=r"(d1) : "r"(addr));
}

static __device__ __forceinline__ float softplusf(float z) {
    return fmaxf(z, 0.0f) + __logf(1.0f + __expf(-fabsf(z)));
}
static __device__ __forceinline__ uint32_t pack2(float a, float b) {
    __nv_bfloat162 t = __floats2bfloat162_rn(a, b);
    return *reinterpret_cast<uint32_t*>(&t);
}
static __device__ __forceinline__ void wsplit2(float v, char* hi, char* lo, uint32_t off) {
    __nv_bfloat16 h = __float2bfloat16(v);
    *(__nv_bfloat16*)(hi + off) = h;
    *(__nv_bfloat16*)(lo + off) = __float2bfloat16(v - __bfloat162float(h));
}

extern "C" __global__ void __launch_bounds__(NTH, 1)
lnn_mma(const float* __restrict__ o,    const float* __restrict__ ain,
        const float* __restrict__ gW1L, const float* __restrict__ gb1L,
        const float* __restrict__ gW2L, const float* __restrict__ gb2L,
        const float* __restrict__ gW3L, const float* __restrict__ gb3L,
        const float* __restrict__ gW1V, const float* __restrict__ gb1V,
        const float* __restrict__ gW2V, const float* __restrict__ gb2V,
        const float* __restrict__ gW3V,
        float* __restrict__ outp, int B)
{
    extern __shared__ char smc[];
    uint32_t* XH32 = (uint32_t*)(smc + SB_XH);
    uint32_t* XL32 = (uint32_t*)(smc + SB_XL);
    float* W1f  = (float*)(smc + SB_W1R);
    float* sDYf = (float*)(smc + SB_DY);
    float* sGX  = (float*)(smc + SB_GX);
    float* sXF  = (float*)(smc + SB_XF);
    float* sQ   = (float*)(smc + SB_Q);
    float* sQD  = (float*)(smc + SB_QD);
    float* sAA  = (float*)(smc + SB_AA);
    float* sLr  = (float*)(smc + SB_LR);
    float* sMs  = (float*)(smc + SB_MS);
    float* sB   = (float*)(smc + SB_B);

    const int tid = threadIdx.x, w = tid >> 5, lane = tid & 31;
    const int gid = lane >> 2, tig = lane & 3;
    const int mt = w & 3, nq = w >> 2;
    const int r0 = mt * 16 + gid, r1 = r0 + 8;
    const int base = blockIdx.x * TB;
    const int RO[6] = {0, 1, 3, 6, 10, 15};
    #define MML(i,j) ((i)>=(j) ? Msl[RO[i]+(j)] : Msl[RO[j]+(i)])

    const uint32_t sbs = (uint32_t)__cvta_generic_to_shared(smc);
    const int rowA = mt * 16 + (lane & 7) + ((lane >> 3) & 1) * 8;
    const int colA = (lane >> 4) * 16;
    const uint32_t aFrag = sbs + rowA * 272 + colA;
    const int rowK = (lane & 7) + ((lane >> 3) & 1) * 8;
    const int colT = (lane >> 4) * 16;
    const uint32_t bTH = sbs + SB_WH + rowK * 272 + nq * 64 + colT;
    const uint32_t bTL = sbs + SB_WL + rowK * 272 + nq * 64 + colT;
    const int rowBl = (lane & 7) + ((lane >> 4) << 3);
    const int colB  = ((lane >> 3) & 1) * 16;
    const uint32_t bVH0 = sbs + SB_WH + (nq * 32 + rowBl) * 272 + colB;
    const uint32_t bVH1 = bVH0 + 16 * 272;
    const uint32_t bVL0 = sbs + SB_WL + (nq * 32 + rowBl) * 272 + colB;
    const uint32_t bVL1 = bVL0 + 16 * 272;
    const uint32_t mTH = sbs + SB_W3H + rowK * 48 + colT;
    const uint32_t mTL = sbs + SB_W3L + rowK * 48 + colT;
    const uint32_t mTH2 = sbs + SB_W3H + rowK * 48 + 32;
    const uint32_t mTL2 = sbs + SB_W3L + rowK * 48 + 32;
    const uint32_t xAddrH = sbs + SB_XH + rowA * 48 + colA;
    const uint32_t xAddrL = sbs + SB_XL + rowA * 48 + colA;
    const uint32_t uAddrH0 = sbs + SB_W1R + (nq * 32 + rowBl) * 48 + colB;
    const uint32_t uAddrH1 = uAddrH0 + 16 * 48;
    const uint32_t uAddrL0 = uAddrH0 + 6144;
    const uint32_t uAddrL1 = uAddrH1 + 6144;

    // persistent loads
    for (int i = tid; i < 128; i += NTH) {
        sB[i] = gb1L[i]; sB[128 + i] = gb2L[i];
        sB[256 + i] = gb1V[i]; sB[384 + i] = gb2V[i]; sB[512 + i] = gW3V[i];
    }
    if (tid < 24) sB[640 + tid] = tid < 21 ? gb3L[tid] : 0.f;
    for (int i = tid; i < 3072; i += NTH) {     // W3 raw tile [c][t]
        int c = i / 24, t = i - c * 24;
        float v = (t < 21) ? gW3L[c * 21 + t] : 0.f;
        wsplit2(v, smc + SB_W3H, smc + SB_W3L, (uint32_t)(c * 48 + t * 2));
    }
    for (int i = tid; i < TB * 6; i += NTH) {
        int r = i / 6, c = i - 6 * r;
        int g = base + r; if (g > B - 1) g = B - 1;
        sQ[r * 7 + c] = o[g * 18 + c];
        sQD[r * 7 + c] = o[g * 18 + 6 + c];
        sAA[r * 7 + c] = ain[g * 6 + c];
    }

    float sg1[4][4], sg2[4][4], k1v[6], k2v[6];
    float wv[6], Aacc[6], svec[6], Cacc[6];

    // ---- helpers ----
    auto storeA = [&](uint32_t bufOff, int nt, float v0, float v1, float v2, float v3) {
        uint32_t* H = (uint32_t*)(smc + bufOff);
        uint32_t* L = (uint32_t*)(smc + bufOff + 17408);
        int ci = nq * 16 + nt * 4 + tig;
        uint32_t h01 = pack2(v0, v1);
        __nv_bfloat162 hh = *reinterpret_cast<__nv_bfloat162*>(&h01);
        H[r0 * 68 + ci] = h01;
        L[r0 * 68 + ci] = pack2(v0 - __bfloat162float(hh.x), v1 - __bfloat162float(hh.y));
        uint32_t h23 = pack2(v2, v3);
        __nv_bfloat162 hh2 = *reinterpret_cast<__nv_bfloat162*>(&h23);
        H[r1 * 68 + ci] = h23;
        L[r1 * 68 + ci] = pack2(v2 - __bfloat162float(hh2.x), v3 - __bfloat162float(hh2.y));
    };
    auto bigGemm = [&](float (&acc)[4][4], bool fwd, uint32_t aOff) {
        const uint32_t aH = aFrag + aOff, aL = aFrag + aOff + 17408;
        #pragma unroll
        for (int nt = 0; nt < 4; nt++)
            acc[nt][0] = acc[nt][1] = acc[nt][2] = acc[nt][3] = 0.f;
        #pragma unroll
        for (int kt = 0; kt < 8; kt++) {
            uint32_t ah0, ah1, ah2, ah3, al0, al1, al2, al3;
            ldsm4(ah0, ah1, ah2, ah3, aH + kt * 32);
            ldsm4(al0, al1, al2, al3, aL + kt * 32);
            uint32_t bh[8], bl[8];
            if (fwd) {
                ldsm4t(bh[0], bh[1], bh[2], bh[3], bTH + kt * 4352);
                ldsm4t(bh[4], bh[5], bh[6], bh[7], bTH + kt * 4352 + 32);
                ldsm4t(bl[0], bl[1], bl[2], bl[3], bTL + kt * 4352);
                ldsm4t(bl[4], bl[5], bl[6], bl[7], bTL + kt * 4352 + 32);
            } else {
                ldsm4(bh[0], bh[1], bh[2], bh[3], bVH0 + kt * 32);
                ldsm4(bh[4], bh[5], bh[6], bh[7], bVH1 + kt * 32);
                ldsm4(bl[0], bl[1], bl[2], bl[3], bVL0 + kt * 32);
                ldsm4(bl[4], bl[5], bl[6], bl[7], bVL1 + kt * 32);
            }
            #pragma unroll
            for (int nt = 0; nt < 4; nt++) MMA(acc[nt], ah0, ah1, ah2, ah3, bh[nt*2], bh[nt*2+1]);
            #pragma unroll
            for (int nt = 0; nt < 4; nt++) MMA(acc[nt], ah0, ah1, ah2, ah3, bl[nt*2], bl[nt*2+1]);
            #pragma unroll
            for (int nt = 0; nt < 4; nt++) MMA(acc[nt], al0, al1, al2, al3, bh[nt*2], bh[nt*2+1]);
        }
    };
    auto l1Gemm = [&](float (&acc)[4][4]) {
        uint32_t ah0, ah1, ah2, ah3, al0, al1, al2, al3;
        ldsm4(ah0, ah1, ah2, ah3, xAddrH);
        ldsm4(al0, al1, al2, al3, xAddrL);
        uint32_t bh[8], bl[8];
        ldsm4(bh[0], bh[1], bh[2], bh[3], uAddrH0);
        ldsm4(bh[4], bh[5], bh[6], bh[7], uAddrH1);
        ldsm4(bl[0], bl[1], bl[2], bl[3], uAddrL0);
        ldsm4(bl[4], bl[5], bl[6], bl[7], uAddrL1);
        #pragma unroll
        for (int nt = 0; nt < 4; nt++)
            acc[nt][0] = acc[nt][1] = acc[nt][2] = acc[nt][3] = 0.f;
        #pragma unroll
        for (int nt = 0; nt < 4; nt++) MMA(acc[nt], ah0, ah1, ah2, ah3, bh[nt*2], bh[nt*2+1]);
        #pragma unroll
        for (int nt = 0; nt < 4; nt++) MMA(acc[nt], ah0, ah1, ah2, ah3, bl[nt*2], bl[nt*2+1]);
        #pragma unroll
        for (int nt = 0; nt < 4; nt++) MMA(acc[nt], al0, al1, al2, al3, bh[nt*2], bh[nt*2+1]);
    };
    auto miniGemm = [&]() {           // nq==0 warps; A from Y buffer
        const uint32_t aH = aFrag + SB_YAH, aL = aFrag + SB_YAH + 17408;
        float acc[3][4];
        #pragma unroll
        for (int nt = 0; nt < 3; nt++)
            acc[nt][0] = acc[nt][1] = acc[nt][2] = acc[nt][3] = 0.f;
        #pragma unroll
        for (int kt = 0; kt < 8; kt++) {
            uint32_t ah0, ah1, ah2, ah3, al0, al1, al2, al3;
            ldsm4(ah0, ah1, ah2, ah3, aH + kt * 32);
            ldsm4(al0, al1, al2, al3, aL + kt * 32);
            uint32_t bh[6], bl[6];
            ldsm4t(bh[0], bh[1], bh[2], bh[3], mTH + kt * 768);
            ldsm2t(bh[4], bh[5], mTH2 + kt * 768);
            ldsm4t(bl[0], bl[1], bl[2], bl[3], mTL + kt * 768);
            ldsm2t(bl[4], bl[5], mTL2 + kt * 768);
            #pragma unroll
            for (int nt = 0; nt < 3; nt++) MMA(acc[nt], ah0, ah1, ah2, ah3, bh[nt*2], bh[nt*2+1]);
            #pragma unroll
            for (int nt = 0; nt < 3; nt++) MMA(acc[nt], ah0, ah1, ah2, ah3, bl[nt*2], bl[nt*2+1]);
            #pragma unroll
            for (int nt = 0; nt < 3; nt++) MMA(acc[nt], al0, al1, al2, al3, bh[nt*2], bh[nt*2+1]);
        }
        #pragma unroll
        for (int nt = 0; nt < 3; nt++) {
            int c = nt * 8 + tig * 2;
            sDYf[r0 * 25 + c] = acc[nt][0]; sDYf[r0 * 25 + c + 1] = acc[nt][1];
            sDYf[r1 * 25 + c] = acc[nt][2]; sDYf[r1 * 25 + c + 1] = acc[nt][3];
        }
    };
    auto buildU1 = [&](int d) {       // u1(d) -> X buffer
        float cq0 = sXF[r0 * 13 + 2 * d], sq0 = sXF[r0 * 13 + 2 * d + 1];
        float cq1 = sXF[r1 * 13 + 2 * d], sq1 = sXF[r1 * 13 + 2 * d + 1];
        #pragma unroll
        for (int nt = 0; nt < 4; nt++) {
            int c = nq * 32 + nt * 8 + tig * 2;
            float2 wa = *(const float2*)&W1f[2 * d * 128 + c];
            float2 wb = *(const float2*)&W1f[(2 * d + 1) * 128 + c];
            storeA(SB_XAH, nt,
                sg1[nt][0] * (cq0 * wb.x - sq0 * wa.x),
                sg1[nt][1] * (cq0 * wb.y - sq0 * wa.y),
                sg1[nt][2] * (cq1 * wb.x - sq1 * wa.x),
                sg1[nt][3] * (cq1 * wb.y - sq1 * wa.y));
        }
    };
    auto physicsStep = [&](int d) {   // tid < 64 only
        int r = tid;
        const float* dy = sDYf + r * 25;
        const float* Lp = sLr + r * 21;
        float qdr[6];
        #pragma unroll
        for (int j = 0; j < 6; j++) qdr[j] = sQD[r * 7 + j];
        float D6[6][6];
        #pragma unroll
        for (int i = 0; i < 6; i++)
            #pragma unroll
            for (int j = 0; j < 6; j++) if (j <= i) {
                float s2 = 0.f;
                #pragma unroll
                for (int k = 0; k < 6; k++) if (k <= j)
                    s2 += dy[RO[i] + k] * Lp[RO[j] + k] + Lp[RO[i] + k] * dy[RO[j] + k];
                D6[i][j] = s2; D6[j][i] = s2;
            }
        float qdd = qdr[d], cdot = 0.f;
        #pragma unroll
        for (int i = 0; i < 6; i++) {
            float v1 = 0.f, v2 = 0.f;
            #pragma unroll
            for (int j = 0; j < 6; j++) { v1 += D6[i][j] * wv[j]; v2 += D6[i][j] * qdr[j]; }
            Aacc[i] += qdd * v1; svec[i] += qdd * v2; cdot += qdr[i] * v1;
        }
        Cacc[d] = cdot;
    };
    auto streamW2body = [&](const float* g, int t, int nt) {
        for (int i = t * 4; i < 16384; i += nt * 4) {
            float4 v = *(const float4*)&g[i];
            int r = i >> 7, c = i & 127;
            uint32_t h01 = pack2(v.x, v.y), h23 = pack2(v.z, v.w);
            __nv_bfloat162 a01 = *reinterpret_cast<__nv_bfloat162*>(&h01);
            __nv_bfloat162 a23 = *reinterpret_cast<__nv_bfloat162*>(&h23);
            uint32_t l01 = pack2(v.x - __bfloat162float(a01.x), v.y - __bfloat162float(a01.y));
            uint32_t l23 = pack2(v.z - __bfloat162float(a23.x), v.w - __bfloat162float(a23.y));
            *(uint2*)(smc + SB_WH + r * 272 + c * 2) = make_uint2(h01, h23);
            *(uint2*)(smc + SB_WL + r * 272 + c * 2) = make_uint2(l01, l23);
        }
    };
    auto streamW1Sbody = [&](const float* g, int t, int nt) {
        for (int i = t; i < 2048; i += nt) {
            int c = i >> 4, tt = i & 15;
            float v = (tt < 12) ? g[tt * 128 + c] : 0.f;
            wsplit2(v, smc + SB_W1R, smc + SB_W1R + 6144, (uint32_t)(c * 48 + tt * 2));
        }
    };
    auto streamW1F = [&](const float* g) {
        for (int i = tid; i < 1536; i += NTH) W1f[i] = g[i];
    };

    __syncthreads();
    const float ADT = (2.0f / 3.0f) * 0.02f;

    for (int stage = 0; stage < 2; ++stage) {
        // head: trig + streams
        if (tid < TB) {
            int r = tid;
            #pragma unroll
            for (int i = 0; i < 6; i++) {
                float sv, cv; __sincosf(sQ[r * 7 + i], &sv, &cv);
                sXF[r * 13 + 2 * i] = cv; sXF[r * 13 + 2 * i + 1] = sv;
            }
            #pragma unroll
            for (int t = 0; t < 12; t++)
                wsplit2(sXF[r * 13 + t], smc + SB_XH, smc + SB_XL, (uint32_t)(r * 48 + t * 2));
            XH32[r * 12 + 6] = 0; XH32[r * 12 + 7] = 0;
            XL32[r * 12 + 6] = 0; XL32[r * 12 + 7] = 0;
        }
        streamW2body(gW2L, tid, NTH);
        streamW1Sbody(gW1L, tid, NTH);
        __syncthreads();

        // layer1 L -> h1 (X), sigma1 (regs)
        {
            float acc[4][4]; l1Gemm(acc);
            #pragma unroll
            for (int nt = 0; nt < 4; nt++) {
                int c = nq * 32 + nt * 8 + tig * 2;
                float h0 = softplusf(acc[nt][0] + sB[c]);
                float h1 = softplusf(acc[nt][1] + sB[c + 1]);
                float h2 = softplusf(acc[nt][2] + sB[c]);
                float h3 = softplusf(acc[nt][3] + sB[c + 1]);
                sg1[nt][0] = 1.f - __expf(-h0); sg1[nt][1] = 1.f - __expf(-h1);
                sg1[nt][2] = 1.f - __expf(-h2); sg1[nt][3] = 1.f - __expf(-h3);
                storeA(SB_XAH, nt, h0, h1, h2, h3);
            }
        }
        __syncthreads();
        streamW1F(gW1L);                          // W1f := W1L fp32
        // h2 = softplus(h1 @ W2L^T + b2L) -> Y, sigma2 regs
        {
            float acc[4][4]; bigGemm(acc, true, SB_XAH);
            #pragma unroll
            for (int nt = 0; nt < 4; nt++) {
                int c = nq * 32 + nt * 8 + tig * 2;
                float h0 = softplusf(acc[nt][0] + sB[128 + c]);
                float h1 = softplusf(acc[nt][1] + sB[128 + c + 1]);
                float h2 = softplusf(acc[nt][2] + sB[128 + c]);
                float h3 = softplusf(acc[nt][3] + sB[128 + c + 1]);
                sg2[nt][0] = 1.f - __expf(-h0); sg2[nt][1] = 1.f - __expf(-h1);
                sg2[nt][2] = 1.f - __expf(-h2); sg2[nt][3] = 1.f - __expf(-h3);
                storeA(SB_YAH, nt, h0, h1, h2, h3);
            }
        }
        __syncthreads();
        if (nq == 0) miniGemm();                  // y -> sDY (reads Y)
        buildU1(0);                               // u1(0) -> X
        __syncthreads();

        // ---- 6 tangent directions ----
        for (int d = 0; d < 6; ++d) {
            if (tid < TB) {
                if (d == 0) {                     // physics init (reads y)
                    int r = tid;
                    const float* dy = sDYf + r * 25;
                    float Lrl[21], Msl[21];
                    #pragma unroll
                    for (int t = 0; t < 21; t++) { Lrl[t] = dy[t] + sB[640 + t]; sLr[r * 21 + t] = Lrl[t]; }
                    #pragma unroll
                    for (int i = 0; i < 6; i++)
                        #pragma unroll
                        for (int j = 0; j < 6; j++) if (j <= i) {
                            float s2 = 0.f;
                            #pragma unroll
                            for (int k = 0; k < 6; k++) if (k <= j) s2 += Lrl[RO[i] + k] * Lrl[RO[j] + k];
                            if (i == j) s2 += 1e-6f;
                            Msl[RO[i] + j] = s2; sMs[r * 21 + RO[i] + j] = s2;
                        }
                    #pragma unroll
                    for (int i = 0; i < 6; i++) {
                        float s2 = 0.f;
                        #pragma unroll
                        for (int j = 0; j < 6; j++) s2 += MML(i, j) * sQD[r * 7 + j];
                        wv[i] = s2; Aacc[i] = 0.f; svec[i] = 0.f;
                    }
                } else {
                    physicsStep(d - 1);
                }
            }
            {
                float acc[4][4]; bigGemm(acc, true, SB_XAH);  // u1 @ W2L^T
                #pragma unroll
                for (int nt = 0; nt < 4; nt++)                // u2 -> Y
                    storeA(SB_YAH, nt, acc[nt][0] * sg2[nt][0], acc[nt][1] * sg2[nt][1],
                           acc[nt][2] * sg2[nt][2], acc[nt][3] * sg2[nt][3]);
            }
            __syncthreads();
            if (nq == 0) miniGemm();                          // dy(d) (reads Y)
            if (d < 5) {
                buildU1(d + 1);                               // -> X
            } else if (nq != 0) {                             // stream V weights
                streamW2body(gW2V, tid - 128, NTH - 128);
                streamW1Sbody(gW1V, tid - 128, NTH - 128);
            }
            __syncthreads();
        }

        // tail: physics(5), layer1 V
        if (tid < TB) physicsStep(5);
        {
            float acc[4][4]; l1Gemm(acc);                     // W1R = W1V split
            #pragma unroll
            for (int nt = 0; nt < 4; nt++) {
                int c = nq * 32 + nt * 8 + tig * 2;
                float h0 = softplusf(acc[nt][0] + sB[256 + c]);
                float h1 = softplusf(acc[nt][1] + sB[256 + c + 1]);
                float h2 = softplusf(acc[nt][2] + sB[256 + c]);
                float h3 = softplusf(acc[nt][3] + sB[256 + c + 1]);
                sg1[nt][0] = 1.f - __expf(-h0); sg1[nt][1] = 1.f - __expf(-h1);
                sg1[nt][2] = 1.f - __expf(-h2); sg1[nt][3] = 1.f - __expf(-h3);
                storeA(SB_XAH, nt, h0, h1, h2, h3);           // h1V -> X
            }
        }
        __syncthreads();
        streamW1F(gW1V);                                      // W1f := W1V fp32
        // h2V -> u2g (Y)
        {
            float acc[4][4]; bigGemm(acc, true, SB_XAH);
            #pragma unroll
            for (int nt = 0; nt < 4; nt++) {
                int c = nq * 32 + nt * 8 + tig * 2;
                float h0 = softplusf(acc[nt][0] + sB[384 + c]);
                float h1 = softplusf(acc[nt][1] + sB[384 + c + 1]);
                float h2 = softplusf(acc[nt][2] + sB[384 + c]);
                float h3 = softplusf(acc[nt][3] + sB[384 + c + 1]);
                storeA(SB_YAH, nt, (1.f - __expf(-h0)) * sB[512 + c],
                       (1.f - __expf(-h1)) * sB[512 + c + 1],
                       (1.f - __expf(-h2)) * sB[512 + c],
                       (1.f - __expf(-h3)) * sB[512 + c + 1]);
            }
        }
        __syncthreads();
        // VJP GEMM (A from Y, non-trans B) + gx projection
        {
            float acc[4][4]; bigGemm(acc, false, SB_YAH);
            float gx0[12], gx1[12];
            #pragma unroll
            for (int t = 0; t < 12; t++) { gx0[t] = 0.f; gx1[t] = 0.f; }
            #pragma unroll
            for (int nt = 0; nt < 4; nt++) {
                int c = nq * 32 + nt * 8 + tig * 2;
                float u0 = acc[nt][0] * sg1[nt][0], u1 = acc[nt][1] * sg1[nt][1];
                float u2 = acc[nt][2] * sg1[nt][2], u3 = acc[nt][3] * sg1[nt][3];
                #pragma unroll
                for (int t = 0; t < 12; t++) {
                    float2 wv2 = *(const float2*)&W1f[t * 128 + c];
                    gx0[t] += u0 * wv2.x + u1 * wv2.y;
                    gx1[t] += u2 * wv2.x + u3 * wv2.y;
                }
            }
            #pragma unroll
            for (int t = 0; t < 12; t++) {
                gx0[t] += __shfl_xor_sync(0xFFFFFFFF, gx0[t], 1);
                gx0[t] += __shfl_xor_sync(0xFFFFFFFF, gx0[t], 2);
                gx1[t] += __shfl_xor_sync(0xFFFFFFFF, gx1[t], 1);
                gx1[t] += __shfl_xor_sync(0xFFFFFFFF, gx1[t], 2);
            }
            if (tig == 0) {
                #pragma unroll
                for (int t = 0; t < 12; t++) {
                    sGX[r0 * 49 + nq * 12 + t] = gx0[t];
                    sGX[r1 * 49 + nq * 12 + t] = gx1[t];
                }
            }
        }
        __syncthreads();
        // final per-row: cvec, rhs, solves, state update
        if (tid < TB) {
            int r = tid;
            float Msl[21];
            #pragma unroll
            for (int t = 0; t < 21; t++) Msl[t] = sMs[r * 21 + t];
            float cv[6];
            #pragma unroll
            for (int i = 0; i < 6; i++) {
                float ms = 0.f;
                #pragma unroll
                for (int j = 0; j < 6; j++) ms += MML(i, j) * svec[j];
                cv[i] = Aacc[i] + ms - Cacc[i];
            }
            float rhs[6];
            #pragma unroll
            for (int i = 0; i < 6; i++) {
                float g0 = sGX[r * 49 + 2 * i]      + sGX[r * 49 + 12 + 2 * i]
                         + sGX[r * 49 + 24 + 2 * i] + sGX[r * 49 + 36 + 2 * i];
                float g1 = sGX[r * 49 + 2 * i + 1]      + sGX[r * 49 + 12 + 2 * i + 1]
                         + sGX[r * 49 + 24 + 2 * i + 1] + sGX[r * 49 + 36 + 2 * i + 1];
                float dv = -sXF[r * 13 + 2 * i + 1] * g0 + sXF[r * 13 + 2 * i] * g1;
                rhs[i] = sAA[r * 7 + i] - cv[i] - dv;
            }
            float yv[6], zv[6];
            #pragma unroll
            for (int i = 0; i < 6; i++) {
                float s2 = rhs[i];
                #pragma unroll
                for (int j = 0; j < 6; j++) if (j < i) s2 -= Msl[RO[i] + j] * yv[j];
                yv[i] = s2 / Msl[RO[i] + i];
            }
            #pragma unroll
            for (int ii = 5; ii >= 0; ii--) {
                float s2 = yv[ii];
                #pragma unroll
                for (int j = 0; j < 6; j++) if (j > ii) s2 -= Msl[RO[j] + ii] * zv[j];
                zv[ii] = s2 / Msl[RO[ii] + ii];
            }
            if (stage == 0) {
                #pragma unroll
                for (int i = 0; i < 6; i++) {
                    k1v[i] = zv[i];
                    float qdi = sQD[r * 7 + i];
                    sQ[r * 7 + i] += ADT * qdi;
                    sQD[r * 7 + i] = qdi + ADT * zv[i];
                }
            } else {
                #pragma unroll
                for (int i = 0; i < 6; i++) k2v[i] = zv[i];
            }
        }
        __syncthreads();
    }

    // ---- output ----
    if (tid < TB && base + tid < B) {
        int g = base + tid, r = tid;
        #pragma unroll
        for (int i = 0; i < 6; i++)
            outp[g * 18 + i] = o[g * 18 + i]
                + 0.02f * (0.25f * o[g * 18 + 6 + i] + 0.75f * sQD[r * 7 + i]);
        #pragma unroll
        for (int i = 0; i < 6; i++)
            outp[g * 18 + 6 + i] = o[g * 18 + 6 + i]
                + 0.02f * (0.25f * k1v[i] + 0.75f * k2v[i]);
        #pragma unroll
        for (int i = 0; i < 6; i++)
            outp[g * 18 + 12 + i] = o[g * 18 + 12 + i];
    }
}

extern "C" void kernel_launch(void* const* d_in, const int* in_sizes, int n_in,
                              void* d_out, int out_size) {
    const float* o   = (const float*)d_in[0];
    const float* a   = (const float*)d_in[1];
    const float* W1L = (const float*)d_in[2];
    const float* b1L = (const float*)d_in[3];
    const float* W2L = (const float*)d_in[4];
    const float* b2L = (const float*)d_in[5];
    const float* W3L = (const float*)d_in[6];
    const float* b3L = (const float*)d_in[7];
    const float* W1V = (const float*)d_in[8];
    const float* b1V = (const float*)d_in[9];
    const float* W2V = (const float*)d_in[10];
    const float* b2V = (const float*)d_in[11];
    const float* W3V = (const float*)d_in[12];
    float* outp = (float*)d_out;

    int B = in_sizes[0] / 18;
    int grid = (B + TB - 1) / TB;
    cudaFuncSetAttribute(lnn_mma,
                         cudaFuncAttributeMaxDynamicSharedMemorySize, SB_END);
    lnn_mma<<<grid, NTH, SB_END>>>(o, a, W1L, b1L, W2L, b2L, W3L, b3L,
                                   W1V, b1V, W2V, b2V, W3V, outp, B);
}